// round 1
// baseline (speedup 1.0000x reference)
#include <cuda_runtime.h>
#include <cstdint>

// Problem constants
#define M_NODES 50000
#define N_EDGES 600000
#define IN_DIM  256
#define H_DIM   128

// ---------------------------------------------------------------------------
// Device scratch (static globals — allocation-free per harness rules)
// ---------------------------------------------------------------------------
__device__ float g_h1[(size_t)M_NODES * H_DIM];          // MLP layer-1 output
__device__ float g_T[3 * (size_t)M_NODES * H_DIM];       // T0,T1,T2 poly feats
__device__ float g_agg[(size_t)M_NODES * H_DIM];         // scatter accumulator
__device__ float g_acc[(size_t)M_NODES * H_DIM];         // output accumulator
__device__ float g_dinv[M_NODES];                        // deg^-1/2 (per relation)
__device__ float g_W3eff[3 * H_DIM * H_DIM];             // THETAS folded into W3

__device__ __forceinline__ float leaky(float v) {
    return v > 0.0f ? v : 0.01f * v;
}

// ---------------------------------------------------------------------------
// W3eff[k] = sum_j THETAS[j][k] * W3[j*H:(j+1)*H]
// THETAS (Bernstein, d=2) = [[3,-3,0.75],[0,3,-1.5],[0,0,0.75]]
// ---------------------------------------------------------------------------
__global__ void w3eff_kernel(const float* __restrict__ W3) {
    int i = blockIdx.x * blockDim.x + threadIdx.x;   // over H*H
    if (i >= H_DIM * H_DIM) return;
    int row = i / H_DIM, col = i % H_DIM;
    float w0 = W3[(0 * H_DIM + row) * H_DIM + col];
    float w1 = W3[(1 * H_DIM + row) * H_DIM + col];
    float w2 = W3[(2 * H_DIM + row) * H_DIM + col];
    g_W3eff[0 * H_DIM * H_DIM + i] = 3.0f * w0;
    g_W3eff[1 * H_DIM * H_DIM + i] = -3.0f * w0 + 3.0f * w1;
    g_W3eff[2 * H_DIM * H_DIM + i] = 0.75f * w0 - 1.5f * w1 + 0.75f * w2;
}

// ---------------------------------------------------------------------------
// Zero kernels
// ---------------------------------------------------------------------------
__global__ void zero_agg_kernel() {
    int i = blockIdx.x * blockDim.x + threadIdx.x;   // over M*H/4
    if (i >= M_NODES * H_DIM / 4) return;
    ((float4*)g_agg)[i] = make_float4(0.f, 0.f, 0.f, 0.f);
}
__global__ void zero_dinv_kernel() {
    int i = blockIdx.x * blockDim.x + threadIdx.x;
    if (i < M_NODES) g_dinv[i] = 0.0f;
}

// ---------------------------------------------------------------------------
// Degree + dinv
// ---------------------------------------------------------------------------
__global__ void deg_kernel(const int* __restrict__ dst) {
    int e = blockIdx.x * blockDim.x + threadIdx.x;
    if (e >= N_EDGES) return;
    atomicAdd(&g_dinv[dst[e]], 1.0f);
}
__global__ void dinv_kernel() {
    int i = blockIdx.x * blockDim.x + threadIdx.x;
    if (i >= M_NODES) return;
    g_dinv[i] = rsqrtf(fmaxf(g_dinv[i], 1.0f));
}

// ---------------------------------------------------------------------------
// Scatter: agg[dst] += f[src] * dinv[src]   (one warp per edge, float4 lanes)
// Vector global reduction (sm_90+): one RED.128 per lane.
// ---------------------------------------------------------------------------
__global__ void scatter_kernel(const int* __restrict__ src, const int* __restrict__ dst,
                               int f_idx) {
    int t = blockIdx.x * blockDim.x + threadIdx.x;
    int e = t >> 5;
    if (e >= N_EDGES) return;
    int lane = t & 31;
    int s = __ldg(src + e);
    int d = __ldg(dst + e);
    float ds = __ldg(&g_dinv[s]);
    const float* f = g_T + (size_t)f_idx * M_NODES * H_DIM;
    float4 v = *(const float4*)(f + (size_t)s * H_DIM + lane * 4);
    float* out = g_agg + (size_t)d * H_DIM + lane * 4;
    asm volatile("red.global.add.v4.f32 [%0], {%1,%2,%3,%4};"
                 :: "l"(out), "f"(v.x * ds), "f"(v.y * ds), "f"(v.z * ds), "f"(v.w * ds)
                 : "memory");
}

// ---------------------------------------------------------------------------
// Combine: T[out] = T[in] - agg * dinv[node]
// ---------------------------------------------------------------------------
__global__ void combine_kernel(int in_idx, int out_idx) {
    int i = blockIdx.x * blockDim.x + threadIdx.x;   // over M*32 (float4 units)
    if (i >= M_NODES * (H_DIM / 4)) return;
    int n = i >> 5;
    float dn = g_dinv[n];
    const float* fin = g_T + (size_t)in_idx * M_NODES * H_DIM;
    float* fout = g_T + (size_t)out_idx * M_NODES * H_DIM;
    float4 a = ((const float4*)g_agg)[i];
    float4 v = ((const float4*)fin)[i];
    v.x -= a.x * dn; v.y -= a.y * dn; v.z -= a.z * dn; v.w -= a.w * dn;
    ((float4*)fout)[i] = v;
}

// ---------------------------------------------------------------------------
// Tiled SGEMM for MLP layers.
// KDIM==256: C(g_h1) = leaky(A(x ext) @ B + bias)
// KDIM==128: C(g_T0) = leaky(A(g_h1) @ B + bias)
// Tile: BM=64, BN=128, BK=16; 256 threads; 8x4 microtile.
// ---------------------------------------------------------------------------
template <int KDIM>
__global__ void gemm12_kernel(const float* __restrict__ Aext,
                              const float* __restrict__ B,
                              const float* __restrict__ bias) {
    constexpr int BM = 64, BN = 128, BK = 16;
    __shared__ float As[BK][BM + 4];
    __shared__ float Bs[BK][BN];

    const float* A = (KDIM == 256) ? Aext : g_h1;
    float* C = (KDIM == 256) ? g_h1 : g_T;   // g_T offset 0 == T0

    int t = threadIdx.x;
    int tx = t & 31;          // col group: cols tx*4 .. tx*4+3
    int ty = t >> 5;          // row group: rows ty*8 .. ty*8+7
    int row0 = blockIdx.x * BM;

    int lr = t >> 2;          // A tile row 0..63
    int lk = (t & 3) * 4;     // A tile k-offset {0,4,8,12}
    int br = t >> 5;          // B tile row 0..7 (+8)
    int bc = (t & 31) * 4;    // B tile col

    float acc[8][4] = {};

    for (int k0 = 0; k0 < KDIM; k0 += BK) {
        float4 av = make_float4(0.f, 0.f, 0.f, 0.f);
        int ar = row0 + lr;
        if (ar < M_NODES) av = *(const float4*)(A + (size_t)ar * KDIM + k0 + lk);
        As[lk + 0][lr] = av.x; As[lk + 1][lr] = av.y;
        As[lk + 2][lr] = av.z; As[lk + 3][lr] = av.w;
        *(float4*)&Bs[br][bc]     = *(const float4*)(B + (size_t)(k0 + br) * BN + bc);
        *(float4*)&Bs[br + 8][bc] = *(const float4*)(B + (size_t)(k0 + br + 8) * BN + bc);
        __syncthreads();
#pragma unroll
        for (int kk = 0; kk < BK; kk++) {
            float4 a0 = *(const float4*)&As[kk][ty * 8];
            float4 a1 = *(const float4*)&As[kk][ty * 8 + 4];
            float4 b  = *(const float4*)&Bs[kk][tx * 4];
            float a[8] = {a0.x, a0.y, a0.z, a0.w, a1.x, a1.y, a1.z, a1.w};
            float bb[4] = {b.x, b.y, b.z, b.w};
#pragma unroll
            for (int i = 0; i < 8; i++)
#pragma unroll
                for (int j = 0; j < 4; j++) acc[i][j] += a[i] * bb[j];
        }
        __syncthreads();
    }

#pragma unroll
    for (int i = 0; i < 8; i++) {
        int r = row0 + ty * 8 + i;
        if (r >= M_NODES) break;
        float* cp = C + (size_t)r * H_DIM + tx * 4;
        float4 v;
        v.x = leaky(acc[i][0] + bias[tx * 4 + 0]);
        v.y = leaky(acc[i][1] + bias[tx * 4 + 1]);
        v.z = leaky(acc[i][2] + bias[tx * 4 + 2]);
        v.w = leaky(acc[i][3] + bias[tx * 4 + 3]);
        *(float4*)cp = v;
    }
}

// ---------------------------------------------------------------------------
// GEMM3: g_acc (+)= sum_k T_k @ W3eff_k + b3      (K = 3*128 in 3 chunks)
// ---------------------------------------------------------------------------
template <bool ACCUM>
__global__ void gemm3_kernel(const float* __restrict__ b3) {
    constexpr int BM = 64, BN = 128, BK = 16;
    __shared__ float As[BK][BM + 4];
    __shared__ float Bs[BK][BN];

    int t = threadIdx.x;
    int tx = t & 31;
    int ty = t >> 5;
    int row0 = blockIdx.x * BM;

    int lr = t >> 2;
    int lk = (t & 3) * 4;
    int br = t >> 5;
    int bc = (t & 31) * 4;

    float acc[8][4] = {};

    for (int k0 = 0; k0 < 3 * H_DIM; k0 += BK) {
        int kb = k0 >> 7;            // which T / W3eff chunk
        int ko = k0 & 127;           // offset within chunk
        const float* A = g_T + (size_t)kb * M_NODES * H_DIM;
        const float* B = g_W3eff + kb * H_DIM * H_DIM;

        float4 av = make_float4(0.f, 0.f, 0.f, 0.f);
        int ar = row0 + lr;
        if (ar < M_NODES) av = *(const float4*)(A + (size_t)ar * H_DIM + ko + lk);
        As[lk + 0][lr] = av.x; As[lk + 1][lr] = av.y;
        As[lk + 2][lr] = av.z; As[lk + 3][lr] = av.w;
        *(float4*)&Bs[br][bc]     = *(const float4*)(B + (size_t)(ko + br) * BN + bc);
        *(float4*)&Bs[br + 8][bc] = *(const float4*)(B + (size_t)(ko + br + 8) * BN + bc);
        __syncthreads();
#pragma unroll
        for (int kk = 0; kk < BK; kk++) {
            float4 a0 = *(const float4*)&As[kk][ty * 8];
            float4 a1 = *(const float4*)&As[kk][ty * 8 + 4];
            float4 b  = *(const float4*)&Bs[kk][tx * 4];
            float a[8] = {a0.x, a0.y, a0.z, a0.w, a1.x, a1.y, a1.z, a1.w};
            float bb[4] = {b.x, b.y, b.z, b.w};
#pragma unroll
            for (int i = 0; i < 8; i++)
#pragma unroll
                for (int j = 0; j < 4; j++) acc[i][j] += a[i] * bb[j];
        }
        __syncthreads();
    }

#pragma unroll
    for (int i = 0; i < 8; i++) {
        int r = row0 + ty * 8 + i;
        if (r >= M_NODES) break;
        float* cp = g_acc + (size_t)r * H_DIM + tx * 4;
        float4 v;
        v.x = acc[i][0] + b3[tx * 4 + 0];
        v.y = acc[i][1] + b3[tx * 4 + 1];
        v.z = acc[i][2] + b3[tx * 4 + 2];
        v.w = acc[i][3] + b3[tx * 4 + 3];
        if (ACCUM) {
            float4 c = *(const float4*)cp;
            v.x += c.x; v.y += c.y; v.z += c.z; v.w += c.w;
        }
        *(float4*)cp = v;
    }
}

// ---------------------------------------------------------------------------
// Final activation: out = leaky(acc)
// ---------------------------------------------------------------------------
__global__ void final_kernel(float* __restrict__ out) {
    int i = blockIdx.x * blockDim.x + threadIdx.x;   // float4 units
    if (i >= M_NODES * (H_DIM / 4)) return;
    float4 v = ((const float4*)g_acc)[i];
    v.x = leaky(v.x); v.y = leaky(v.y); v.z = leaky(v.z); v.w = leaky(v.w);
    ((float4*)out)[i] = v;
}

// ---------------------------------------------------------------------------
// Launch
// ---------------------------------------------------------------------------
extern "C" void kernel_launch(void* const* d_in, const int* in_sizes, int n_in,
                              void* d_out, int out_size) {
    const float* x = (const float*)d_in[0];
    const int *src[3], *dst[3];
    const float *W1[3], *b1[3], *W2[3], *b2[3];
    const float *W3, *b3;

    if (in_sizes[3] == N_EDGES) {
        // Order A (reference signature): x, src0,dst0,src1,dst1,src2,dst2,
        //   W1_0,b1_0,W2_0,b2_0, W1_1,..., W1_2,..., W3, b3
        for (int r = 0; r < 3; r++) {
            src[r] = (const int*)d_in[1 + 2 * r];
            dst[r] = (const int*)d_in[2 + 2 * r];
        }
        for (int r = 0; r < 3; r++) {
            W1[r] = (const float*)d_in[7 + 4 * r];
            b1[r] = (const float*)d_in[8 + 4 * r];
            W2[r] = (const float*)d_in[9 + 4 * r];
            b2[r] = (const float*)d_in[10 + 4 * r];
        }
        W3 = (const float*)d_in[19];
        b3 = (const float*)d_in[20];
    } else {
        // Order B (setup_inputs dict order): x, then per-r: src,dst,W1,b1,W2,b2, then W3,b3
        for (int r = 0; r < 3; r++) {
            src[r] = (const int*)d_in[1 + 6 * r];
            dst[r] = (const int*)d_in[2 + 6 * r];
            W1[r]  = (const float*)d_in[3 + 6 * r];
            b1[r]  = (const float*)d_in[4 + 6 * r];
            W2[r]  = (const float*)d_in[5 + 6 * r];
            b2[r]  = (const float*)d_in[6 + 6 * r];
        }
        W3 = (const float*)d_in[19];
        b3 = (const float*)d_in[20];
    }

    const int GEMM_BLOCKS = (M_NODES + 63) / 64;                 // 782
    const int EW_BLOCKS   = (M_NODES * (H_DIM / 4) + 255) / 256; // 6250
    const int SC_BLOCKS   = (N_EDGES * 32 + 255) / 256;          // 75000
    const int DEG_BLOCKS  = (N_EDGES + 255) / 256;
    const int NV_BLOCKS   = (M_NODES + 255) / 256;

    w3eff_kernel<<<(H_DIM * H_DIM + 255) / 256, 256>>>(W3);

    for (int r = 0; r < 3; r++) {
        // MLP: h = leaky(leaky(x@W1+b1)@W2+b2) -> T0
        gemm12_kernel<256><<<GEMM_BLOCKS, 256>>>(x, W1[r], b1[r]);
        gemm12_kernel<128><<<GEMM_BLOCKS, 256>>>(nullptr, W2[r], b2[r]);

        // dinv for this relation
        zero_dinv_kernel<<<NV_BLOCKS, 256>>>();
        deg_kernel<<<DEG_BLOCKS, 256>>>(dst[r]);
        dinv_kernel<<<NV_BLOCKS, 256>>>();

        // T1 = T0 - A(T0),  T2 = T1 - A(T1)
        zero_agg_kernel<<<EW_BLOCKS, 256>>>();
        scatter_kernel<<<SC_BLOCKS, 256>>>(src[r], dst[r], 0);
        combine_kernel<<<EW_BLOCKS, 256>>>(0, 1);

        zero_agg_kernel<<<EW_BLOCKS, 256>>>();
        scatter_kernel<<<SC_BLOCKS, 256>>>(src[r], dst[r], 1);
        combine_kernel<<<EW_BLOCKS, 256>>>(1, 2);

        // acc (+)= sum_k T_k @ W3eff_k + b3
        if (r == 0) gemm3_kernel<false><<<GEMM_BLOCKS, 256>>>(b3);
        else        gemm3_kernel<true><<<GEMM_BLOCKS, 256>>>(b3);
    }

    final_kernel<<<EW_BLOCKS, 256>>>((float*)d_out);
}

// round 3
// speedup vs baseline: 1.7662x; 1.7662x over previous
#include <cuda_runtime.h>
#include <cuda_bf16.h>
#include <cstdint>

#define M_NODES 50000
#define N_EDGES 600000
#define IN_DIM  256
#define H_DIM   128
#define MH ((size_t)M_NODES * H_DIM)

// ---------------------------------------------------------------------------
// Device scratch
// ---------------------------------------------------------------------------
__device__ __align__(256) float g_T[3 * MH];
__device__ __align__(256) float g_agg[MH];
__device__ __align__(256) float g_acc[MH];
__device__ __align__(256) float g_dinv[M_NODES];
__device__ __align__(256) float g_W3eff[3 * H_DIM * H_DIM];

__device__ __align__(256) __nv_bfloat16 g_xh[(size_t)M_NODES * IN_DIM];
__device__ __align__(256) __nv_bfloat16 g_xl[(size_t)M_NODES * IN_DIM];
__device__ __align__(256) __nv_bfloat16 g_h1h[MH];
__device__ __align__(256) __nv_bfloat16 g_h1l[MH];
__device__ __align__(256) __nv_bfloat16 g_Th[3 * MH];
__device__ __align__(256) __nv_bfloat16 g_Tl[3 * MH];
__device__ __align__(256) __nv_bfloat16 g_Bth[128 * 256];
__device__ __align__(256) __nv_bfloat16 g_Btl[128 * 256];
__device__ __align__(256) __nv_bfloat16 g_Bt3h[128 * 384];
__device__ __align__(256) __nv_bfloat16 g_Bt3l[128 * 384];

__device__ __forceinline__ float leaky(float v) { return v > 0.0f ? v : 0.01f * v; }

__device__ __forceinline__ uint32_t s2u(const void* p) {
    uint32_t a;
    asm("{ .reg .u64 t; cvta.to.shared.u64 t, %1; cvt.u32.u64 %0, t; }" : "=r"(a) : "l"(p));
    return a;
}

__device__ __forceinline__ void ldm_x4(uint32_t* r, uint32_t addr) {
    asm volatile("ldmatrix.sync.aligned.m8n8.x4.shared.b16 {%0,%1,%2,%3}, [%4];"
                 : "=r"(r[0]), "=r"(r[1]), "=r"(r[2]), "=r"(r[3]) : "r"(addr));
}

__device__ __forceinline__ void mma16816(float* c, const uint32_t* a, const uint32_t* b) {
    asm volatile(
        "mma.sync.aligned.m16n8k16.row.col.f32.bf16.bf16.f32 "
        "{%0,%1,%2,%3}, {%4,%5,%6,%7}, {%8,%9}, {%0,%1,%2,%3};"
        : "+f"(c[0]), "+f"(c[1]), "+f"(c[2]), "+f"(c[3])
        : "r"(a[0]), "r"(a[1]), "r"(a[2]), "r"(a[3]), "r"(b[0]), "r"(b[1]));
}

// ---------------------------------------------------------------------------
// Warp-MMA GEMM:  C[128 x 128] = (Ah+Al) @ (Bh+Bl)^T  (3-pass bf16, fp32 acc)
//   KDIM=256 EPI=0: A=x,  B=W1t -> leaky -> g_h1h/l
//   KDIM=128 EPI=1: A=h1, B=W2t -> leaky -> g_T[0] fp32 + g_Th/l[0]
//   KDIM=384 EPI=2: A=T,  B=W3t -> g_acc (+)= v + bias
// 8 warps: warp_m = wid&1 (64 rows), warp_n = wid>>1 (32 cols); 4x4 frags.
// ---------------------------------------------------------------------------
#define SPAD 40   // smem row stride in halves (80B: 16B-aligned, conflict-free)

template <int KDIM, int EPI>
__global__ void __launch_bounds__(256, 1) mma_gemm(const float* __restrict__ bias, int accum) {
    __shared__ __nv_bfloat16 sAh[128][SPAD], sAl[128][SPAD];
    __shared__ __nv_bfloat16 sBh[128][SPAD], sBl[128][SPAD];

    const int tid = threadIdx.x;
    const int wid = tid >> 5;
    const int lane = tid & 31;
    const int row0 = blockIdx.x * 128;
    const int wm0 = (wid & 1) * 64;
    const int wn0 = (wid >> 1) * 32;

    const __nv_bfloat16 *Ah, *Al, *Bh, *Bl;
    if (KDIM == 256)      { Ah = g_xh;  Al = g_xl;  Bh = g_Bth;  Bl = g_Btl;  }
    else if (KDIM == 128) { Ah = g_h1h; Al = g_h1l; Bh = g_Bth;  Bl = g_Btl;  }
    else                  { Ah = g_Th;  Al = g_Tl;  Bh = g_Bt3h; Bl = g_Bt3l; }

    const uint32_t uAh = s2u(sAh), uAl = s2u(sAl), uBh = s2u(sBh), uBl = s2u(sBl);

    float acc[4][4][4] = {};

    // ldmatrix lane address components
    const int a_row = (lane & 7) + ((lane >> 3) & 1) * 8;     // within 16-row frag
    const int a_kof = ((lane >> 4) & 1) * 8;                  // k half
    const int b_nof = ((lane >> 4) & 1) * 8;                  // n half (matrix 2,3)
    const int b_kof = ((lane >> 3) & 1) * 8;                  // k half (matrix 1,3)
    const int b_row = lane & 7;

    for (int k0 = 0; k0 < KDIM; k0 += 32) {
        const __nv_bfloat16 *pAh, *pAl;
        int ars, ako;
        if (KDIM == 384) {
            int blk = k0 >> 7;
            pAh = Ah + (size_t)blk * MH;
            pAl = Al + (size_t)blk * MH;
            ars = H_DIM; ako = k0 & 127;
        } else { pAh = Ah; pAl = Al; ars = KDIM; ako = k0; }

        __syncthreads();
#pragma unroll
        for (int it = 0; it < 2; it++) {
            int i = it * 256 + tid;        // over 128 rows x 4 uint4
            int r = i >> 2, q = (i & 3) * 8;
            uint4 z = make_uint4(0, 0, 0, 0);
            uint4 vh = z, vl = z;
            int gr = row0 + r;
            if (gr < M_NODES) {
                vh = *(const uint4*)(pAh + (size_t)gr * ars + ako + q);
                vl = *(const uint4*)(pAl + (size_t)gr * ars + ako + q);
            }
            *(uint4*)&sAh[r][q] = vh;
            *(uint4*)&sAl[r][q] = vl;
            *(uint4*)&sBh[r][q] = *(const uint4*)(Bh + (size_t)r * KDIM + k0 + q);
            *(uint4*)&sBl[r][q] = *(const uint4*)(Bl + (size_t)r * KDIM + k0 + q);
        }
        __syncthreads();

#pragma unroll
        for (int ks = 0; ks < 32; ks += 16) {
            uint32_t ah[4][4], al[4][4], bh[4][2], bl[4][2];
#pragma unroll
            for (int mf = 0; mf < 4; mf++) {
                uint32_t off = ((wm0 + mf * 16 + a_row) * SPAD + ks + a_kof) * 2;
                ldm_x4(ah[mf], uAh + off);
                ldm_x4(al[mf], uAl + off);
            }
#pragma unroll
            for (int nb = 0; nb < 2; nb++) {
                uint32_t off = ((wn0 + nb * 16 + b_nof + b_row) * SPAD + ks + b_kof) * 2;
                uint32_t t[4];
                ldm_x4(t, uBh + off);
                bh[2 * nb][0] = t[0]; bh[2 * nb][1] = t[1];
                bh[2 * nb + 1][0] = t[2]; bh[2 * nb + 1][1] = t[3];
                ldm_x4(t, uBl + off);
                bl[2 * nb][0] = t[0]; bl[2 * nb][1] = t[1];
                bl[2 * nb + 1][0] = t[2]; bl[2 * nb + 1][1] = t[3];
            }
#pragma unroll
            for (int mf = 0; mf < 4; mf++)
#pragma unroll
                for (int nf = 0; nf < 4; nf++) {
                    mma16816(acc[mf][nf], ah[mf], bh[nf]);   // Ah*Bh
                    mma16816(acc[mf][nf], ah[mf], bl[nf]);   // Ah*Bl
                    mma16816(acc[mf][nf], al[mf], bh[nf]);   // Al*Bh
                }
        }
    }

    // Epilogue. C frag layout: lane: rows (wm0+mf*16 + lr, +8), cols wn0+nf*8 + lc,+1
    const int lr = lane >> 2;
    const int lc = (lane & 3) * 2;
#pragma unroll
    for (int mf = 0; mf < 4; mf++) {
#pragma unroll
        for (int half = 0; half < 2; half++) {
            int row = row0 + wm0 + mf * 16 + lr + half * 8;
            if (row >= M_NODES) continue;
#pragma unroll
            for (int nf = 0; nf < 4; nf++) {
                int col = wn0 + nf * 8 + lc;
                float v0 = acc[mf][nf][2 * half]     + __ldg(bias + col);
                float v1 = acc[mf][nf][2 * half + 1] + __ldg(bias + col + 1);
                size_t base = (size_t)row * H_DIM + col;
                if (EPI == 2) {
                    float2 nv = make_float2(v0, v1);
                    if (accum) {
                        float2 c = *(const float2*)(g_acc + base);
                        nv.x += c.x; nv.y += c.y;
                    }
                    *(float2*)(g_acc + base) = nv;
                } else {
                    v0 = leaky(v0); v1 = leaky(v1);
                    if (EPI == 1) *(float2*)(g_T + base) = make_float2(v0, v1);
                    __nv_bfloat16* Ch = (EPI == 0) ? g_h1h : g_Th;
                    __nv_bfloat16* Cl = (EPI == 0) ? g_h1l : g_Tl;
                    __nv_bfloat16 h0 = __float2bfloat16(v0);
                    __nv_bfloat16 h1 = __float2bfloat16(v1);
                    __nv_bfloat162 hh; hh.x = h0; hh.y = h1;
                    __nv_bfloat162 ll;
                    ll.x = __float2bfloat16(v0 - __bfloat162float(h0));
                    ll.y = __float2bfloat16(v1 - __bfloat162float(h1));
                    *(__nv_bfloat162*)(Ch + base) = hh;
                    *(__nv_bfloat162*)(Cl + base) = ll;
                }
            }
        }
    }
}

// ---------------------------------------------------------------------------
// Small kernels
// ---------------------------------------------------------------------------
__global__ void w3eff_kernel(const float* __restrict__ W3) {
    int i = blockIdx.x * blockDim.x + threadIdx.x;
    if (i >= H_DIM * H_DIM) return;
    int row = i / H_DIM, col = i % H_DIM;
    float w0 = W3[(0 * H_DIM + row) * H_DIM + col];
    float w1 = W3[(1 * H_DIM + row) * H_DIM + col];
    float w2 = W3[(2 * H_DIM + row) * H_DIM + col];
    g_W3eff[0 * H_DIM * H_DIM + i] = 3.0f * w0;
    g_W3eff[1 * H_DIM * H_DIM + i] = -3.0f * w0 + 3.0f * w1;
    g_W3eff[2 * H_DIM * H_DIM + i] = 0.75f * w0 - 1.5f * w1 + 0.75f * w2;
}

template <int K>
__global__ void convW_kernel(const float* __restrict__ W) {
    int i = blockIdx.x * blockDim.x + threadIdx.x;
    if (i >= 128 * K) return;
    int n = i / K, k = i % K;
    float v = (K == 384) ? g_W3eff[k * H_DIM + n] : W[k * H_DIM + n];
    __nv_bfloat16 h = __float2bfloat16(v);
    float lo = v - __bfloat162float(h);
    if (K == 384) { g_Bt3h[i] = h; g_Bt3l[i] = __float2bfloat16(lo); }
    else          { g_Bth[i]  = h; g_Btl[i]  = __float2bfloat16(lo); }
}

__global__ void convx_kernel(const float* __restrict__ x) {
    int i = blockIdx.x * blockDim.x + threadIdx.x;
    if (i >= M_NODES * IN_DIM / 2) return;
    float2 v = ((const float2*)x)[i];
    __nv_bfloat16 h0 = __float2bfloat16(v.x), h1 = __float2bfloat16(v.y);
    __nv_bfloat162 hh; hh.x = h0; hh.y = h1;
    __nv_bfloat162 ll;
    ll.x = __float2bfloat16(v.x - __bfloat162float(h0));
    ll.y = __float2bfloat16(v.y - __bfloat162float(h1));
    ((__nv_bfloat162*)g_xh)[i] = hh;
    ((__nv_bfloat162*)g_xl)[i] = ll;
}

__global__ void zero_agg_kernel() {
    int i = blockIdx.x * blockDim.x + threadIdx.x;
    if (i >= (int)(MH / 4)) return;
    ((float4*)g_agg)[i] = make_float4(0.f, 0.f, 0.f, 0.f);
}
__global__ void zero_dinv_kernel() {
    int i = blockIdx.x * blockDim.x + threadIdx.x;
    if (i < M_NODES) g_dinv[i] = 0.0f;
}
__global__ void deg_kernel(const int* __restrict__ dst) {
    int e = blockIdx.x * blockDim.x + threadIdx.x;
    if (e >= N_EDGES) return;
    atomicAdd(&g_dinv[dst[e]], 1.0f);
}
__global__ void dinv_kernel() {
    int i = blockIdx.x * blockDim.x + threadIdx.x;
    if (i >= M_NODES) return;
    g_dinv[i] = rsqrtf(fmaxf(g_dinv[i], 1.0f));
}

__global__ void scatter_kernel(const int* __restrict__ src, const int* __restrict__ dst,
                               int f_idx) {
    int t = blockIdx.x * blockDim.x + threadIdx.x;
    int e = t >> 5;
    if (e >= N_EDGES) return;
    int lane = t & 31;
    int s = __ldg(src + e);
    int d = __ldg(dst + e);
    float ds = __ldg(&g_dinv[s]);
    const float* f = g_T + (size_t)f_idx * MH;
    float4 v = *(const float4*)(f + (size_t)s * H_DIM + lane * 4);
    float* out = g_agg + (size_t)d * H_DIM + lane * 4;
    asm volatile("red.global.add.v4.f32 [%0], {%1,%2,%3,%4};"
                 :: "l"(out), "f"(v.x * ds), "f"(v.y * ds), "f"(v.z * ds), "f"(v.w * ds)
                 : "memory");
}

__global__ void combine_kernel(int in_idx, int out_idx) {
    int i = blockIdx.x * blockDim.x + threadIdx.x;
    if (i >= (int)(MH / 4)) return;
    int n = i >> 5;
    float dn = g_dinv[n];
    const float* fin = g_T + (size_t)in_idx * MH;
    float* fout = g_T + (size_t)out_idx * MH;
    float4 a = ((const float4*)g_agg)[i];
    float4 v = ((const float4*)fin)[i];
    v.x -= a.x * dn; v.y -= a.y * dn; v.z -= a.z * dn; v.w -= a.w * dn;
    ((float4*)fout)[i] = v;
    size_t base = (size_t)out_idx * MH + (size_t)i * 4;
    __nv_bfloat16 h0 = __float2bfloat16(v.x), h1 = __float2bfloat16(v.y);
    __nv_bfloat16 h2 = __float2bfloat16(v.z), h3 = __float2bfloat16(v.w);
    __nv_bfloat162 p0; p0.x = h0; p0.y = h1;
    __nv_bfloat162 p1; p1.x = h2; p1.y = h3;
    *(__nv_bfloat162*)(g_Th + base)     = p0;
    *(__nv_bfloat162*)(g_Th + base + 2) = p1;
    __nv_bfloat162 q0, q1;
    q0.x = __float2bfloat16(v.x - __bfloat162float(h0));
    q0.y = __float2bfloat16(v.y - __bfloat162float(h1));
    q1.x = __float2bfloat16(v.z - __bfloat162float(h2));
    q1.y = __float2bfloat16(v.w - __bfloat162float(h3));
    *(__nv_bfloat162*)(g_Tl + base)     = q0;
    *(__nv_bfloat162*)(g_Tl + base + 2) = q1;
}

__global__ void final_kernel(float* __restrict__ out) {
    int i = blockIdx.x * blockDim.x + threadIdx.x;
    if (i >= (int)(MH / 4)) return;
    float4 v = ((const float4*)g_acc)[i];
    v.x = leaky(v.x); v.y = leaky(v.y); v.z = leaky(v.z); v.w = leaky(v.w);
    ((float4*)out)[i] = v;
}

// ---------------------------------------------------------------------------
// Launch
// ---------------------------------------------------------------------------
extern "C" void kernel_launch(void* const* d_in, const int* in_sizes, int n_in,
                              void* d_out, int out_size) {
    const float* x = (const float*)d_in[0];
    const int *src[3], *dst[3];
    const float *W1[3], *b1[3], *W2[3], *b2[3];
    const float *W3, *b3;

    if (in_sizes[3] == N_EDGES) {
        for (int r = 0; r < 3; r++) {
            src[r] = (const int*)d_in[1 + 2 * r];
            dst[r] = (const int*)d_in[2 + 2 * r];
        }
        for (int r = 0; r < 3; r++) {
            W1[r] = (const float*)d_in[7 + 4 * r];
            b1[r] = (const float*)d_in[8 + 4 * r];
            W2[r] = (const float*)d_in[9 + 4 * r];
            b2[r] = (const float*)d_in[10 + 4 * r];
        }
        W3 = (const float*)d_in[19];
        b3 = (const float*)d_in[20];
    } else {
        for (int r = 0; r < 3; r++) {
            src[r] = (const int*)d_in[1 + 6 * r];
            dst[r] = (const int*)d_in[2 + 6 * r];
            W1[r]  = (const float*)d_in[3 + 6 * r];
            b1[r]  = (const float*)d_in[4 + 6 * r];
            W2[r]  = (const float*)d_in[5 + 6 * r];
            b2[r]  = (const float*)d_in[6 + 6 * r];
        }
        W3 = (const float*)d_in[19];
        b3 = (const float*)d_in[20];
    }

    const int GEMM_GRID = (M_NODES + 127) / 128;                 // 391
    const int EW_BLOCKS = (int)((MH / 4 + 255) / 256);
    const int SC_BLOCKS = (N_EDGES * 32 + 255) / 256;
    const int DEG_BLOCKS = (N_EDGES + 255) / 256;
    const int NV_BLOCKS = (M_NODES + 255) / 256;

    w3eff_kernel<<<(H_DIM * H_DIM + 255) / 256, 256>>>(W3);
    convW_kernel<384><<<(128 * 384 + 255) / 256, 256>>>(W3);
    convx_kernel<<<(M_NODES * IN_DIM / 2 + 255) / 256, 256>>>(x);

    for (int r = 0; r < 3; r++) {
        convW_kernel<256><<<(128 * 256 + 255) / 256, 256>>>(W1[r]);
        mma_gemm<256, 0><<<GEMM_GRID, 256>>>(b1[r], 0);
        convW_kernel<128><<<(128 * 128 + 255) / 256, 256>>>(W2[r]);
        mma_gemm<128, 1><<<GEMM_GRID, 256>>>(b2[r], 0);

        zero_dinv_kernel<<<NV_BLOCKS, 256>>>();
        deg_kernel<<<DEG_BLOCKS, 256>>>(dst[r]);
        dinv_kernel<<<NV_BLOCKS, 256>>>();

        zero_agg_kernel<<<EW_BLOCKS, 256>>>();
        scatter_kernel<<<SC_BLOCKS, 256>>>(src[r], dst[r], 0);
        combine_kernel<<<EW_BLOCKS, 256>>>(0, 1);

        zero_agg_kernel<<<EW_BLOCKS, 256>>>();
        scatter_kernel<<<SC_BLOCKS, 256>>>(src[r], dst[r], 1);
        combine_kernel<<<EW_BLOCKS, 256>>>(1, 2);

        mma_gemm<384, 2><<<GEMM_GRID, 256>>>(b3, r > 0 ? 1 : 0);
    }

    final_kernel<<<EW_BLOCKS, 256>>>((float*)d_out);
}

// round 4
// speedup vs baseline: 1.8996x; 1.0755x over previous
#include <cuda_runtime.h>
#include <cuda_bf16.h>
#include <cstdint>

#define M_NODES 50000
#define N_EDGES 600000
#define IN_DIM  256
#define H_DIM   128
#define MH ((size_t)M_NODES * H_DIM)

// ---------------------------------------------------------------------------
// Device scratch. Layouts:
//  g_T   fp32 [3 rel][2 stages(0,1)][MH]   (stage2 fp32 never needed)
//  g_Th/l bf16 [3 rel][3 stages][MH]
// ---------------------------------------------------------------------------
__device__ __align__(256) float g_T[6 * MH];
__device__ __align__(256) float g_agg3[3 * MH];
__device__ __align__(256) float g_dinv3[3 * M_NODES];
__device__ __align__(256) float g_W3eff[3 * H_DIM * H_DIM];

__device__ __align__(256) __nv_bfloat16 g_xh[(size_t)M_NODES * IN_DIM];
__device__ __align__(256) __nv_bfloat16 g_xl[(size_t)M_NODES * IN_DIM];
__device__ __align__(256) __nv_bfloat16 g_h1h[3 * MH];
__device__ __align__(256) __nv_bfloat16 g_h1l[3 * MH];
__device__ __align__(256) __nv_bfloat16 g_Th[9 * MH];
__device__ __align__(256) __nv_bfloat16 g_Tl[9 * MH];
__device__ __align__(256) __nv_bfloat16 g_Bt1h[3 * 128 * 256];
__device__ __align__(256) __nv_bfloat16 g_Bt1l[3 * 128 * 256];
__device__ __align__(256) __nv_bfloat16 g_Bt2h[3 * 128 * 128];
__device__ __align__(256) __nv_bfloat16 g_Bt2l[3 * 128 * 128];
__device__ __align__(256) __nv_bfloat16 g_Bt3h[3 * 128 * 128];   // [stage][n][k]
__device__ __align__(256) __nv_bfloat16 g_Bt3l[3 * 128 * 128];

__device__ __forceinline__ float leaky(float v) { return v > 0.0f ? v : 0.01f * v; }

__device__ __forceinline__ uint32_t s2u(const void* p) {
    uint32_t a;
    asm("{ .reg .u64 t; cvta.to.shared.u64 t, %1; cvt.u32.u64 %0, t; }" : "=r"(a) : "l"(p));
    return a;
}
__device__ __forceinline__ void ldm_x4(uint32_t* r, uint32_t addr) {
    asm volatile("ldmatrix.sync.aligned.m8n8.x4.shared.b16 {%0,%1,%2,%3}, [%4];"
                 : "=r"(r[0]), "=r"(r[1]), "=r"(r[2]), "=r"(r[3]) : "r"(addr));
}
__device__ __forceinline__ void mma16816(float* c, const uint32_t* a, const uint32_t* b) {
    asm volatile(
        "mma.sync.aligned.m16n8k16.row.col.f32.bf16.bf16.f32 "
        "{%0,%1,%2,%3}, {%4,%5,%6,%7}, {%8,%9}, {%0,%1,%2,%3};"
        : "+f"(c[0]), "+f"(c[1]), "+f"(c[2]), "+f"(c[3])
        : "r"(a[0]), "r"(a[1]), "r"(a[2]), "r"(a[3]), "r"(b[0]), "r"(b[1]));
}

// ---------------------------------------------------------------------------
// Warp-MMA GEMM, 128x128 tile per CTA, BK=32, 8 warps (64x32 each), 3-pass hi/lo.
//  MODE 1: rel-batched (grid.y=r): C=h1[r]  = leaky(x @ W1[r]^T + b1[r])
//  MODE 2: rel-batched: T0[r] = leaky(h1[r] @ W2[r]^T + b2[r]) -> fp32+bf16
//  MODE 3: single: out = leaky( sum_{r,s} T[r][s] @ W3eff[s]^T + b3 )
// ---------------------------------------------------------------------------
#define SPAD 40

template <int MODE>
__global__ void __launch_bounds__(256, 1)
mma_gemm(const float* __restrict__ bias0, const float* __restrict__ bias1,
         const float* __restrict__ bias2, float* __restrict__ out) {
    __shared__ __nv_bfloat16 sAh[128][SPAD], sAl[128][SPAD];
    __shared__ __nv_bfloat16 sBh[128][SPAD], sBl[128][SPAD];

    const int tid = threadIdx.x;
    const int wid = tid >> 5;
    const int lane = tid & 31;
    const int row0 = blockIdx.x * 128;
    const int rel = (MODE == 3) ? 0 : blockIdx.y;
    const int wm0 = (wid & 1) * 64;
    const int wn0 = (wid >> 1) * 32;

    const float* bias = (MODE == 3) ? bias0 : (rel == 0 ? bias0 : (rel == 1 ? bias1 : bias2));

    const uint32_t uAh = s2u(sAh), uAl = s2u(sAl), uBh = s2u(sBh), uBl = s2u(sBl);

    float acc[4][4][4] = {};

    const int a_row = (lane & 7) + ((lane >> 3) & 1) * 8;
    const int a_kof = ((lane >> 4) & 1) * 8;
    const int b_nof = ((lane >> 4) & 1) * 8;
    const int b_kof = ((lane >> 3) & 1) * 8;
    const int b_row = lane & 7;

    constexpr int KTOT = (MODE == 1) ? 256 : (MODE == 2) ? 128 : 1152;

    for (int k0 = 0; k0 < KTOT; k0 += 32) {
        // Resolve chunk pointers
        const __nv_bfloat16 *pAh, *pAl, *pBh, *pBl;
        int ars, ako, bko;
        if (MODE == 1) {
            pAh = g_xh; pAl = g_xl; ars = 256; ako = k0;
            pBh = g_Bt1h + rel * 128 * 256; pBl = g_Bt1l + rel * 128 * 256; bko = k0;
        } else if (MODE == 2) {
            pAh = g_h1h + (size_t)rel * MH; pAl = g_h1l + (size_t)rel * MH; ars = 128; ako = k0;
            pBh = g_Bt2h + rel * 128 * 128; pBl = g_Bt2l + rel * 128 * 128; bko = k0;
        } else {
            int c = k0 >> 7;           // 0..8 == r*3+s
            int s = c % 3;
            pAh = g_Th + (size_t)c * MH; pAl = g_Tl + (size_t)c * MH;
            ars = 128; ako = k0 & 127;
            pBh = g_Bt3h + s * 128 * 128; pBl = g_Bt3l + s * 128 * 128; bko = k0 & 127;
        }
        constexpr int BSTRIDE = (MODE == 1) ? 256 : 128;

        __syncthreads();
#pragma unroll
        for (int it = 0; it < 2; it++) {
            int i = it * 256 + tid;
            int r = i >> 2, q = (i & 3) * 8;
            uint4 z = make_uint4(0, 0, 0, 0);
            uint4 vh = z, vl = z;
            int gr = row0 + r;
            if (gr < M_NODES) {
                vh = *(const uint4*)(pAh + (size_t)gr * ars + ako + q);
                vl = *(const uint4*)(pAl + (size_t)gr * ars + ako + q);
            }
            *(uint4*)&sAh[r][q] = vh;
            *(uint4*)&sAl[r][q] = vl;
            *(uint4*)&sBh[r][q] = *(const uint4*)(pBh + (size_t)r * BSTRIDE + bko + q);
            *(uint4*)&sBl[r][q] = *(const uint4*)(pBl + (size_t)r * BSTRIDE + bko + q);
        }
        __syncthreads();

#pragma unroll
        for (int ks = 0; ks < 32; ks += 16) {
            uint32_t ah[4][4], al[4][4], bh[4][2], bl[4][2];
#pragma unroll
            for (int mf = 0; mf < 4; mf++) {
                uint32_t off = ((wm0 + mf * 16 + a_row) * SPAD + ks + a_kof) * 2;
                ldm_x4(ah[mf], uAh + off);
                ldm_x4(al[mf], uAl + off);
            }
#pragma unroll
            for (int nb = 0; nb < 2; nb++) {
                uint32_t off = ((wn0 + nb * 16 + b_nof + b_row) * SPAD + ks + b_kof) * 2;
                uint32_t t[4];
                ldm_x4(t, uBh + off);
                bh[2 * nb][0] = t[0]; bh[2 * nb][1] = t[1];
                bh[2 * nb + 1][0] = t[2]; bh[2 * nb + 1][1] = t[3];
                ldm_x4(t, uBl + off);
                bl[2 * nb][0] = t[0]; bl[2 * nb][1] = t[1];
                bl[2 * nb + 1][0] = t[2]; bl[2 * nb + 1][1] = t[3];
            }
#pragma unroll
            for (int mf = 0; mf < 4; mf++)
#pragma unroll
                for (int nf = 0; nf < 4; nf++) {
                    mma16816(acc[mf][nf], ah[mf], bh[nf]);
                    mma16816(acc[mf][nf], ah[mf], bl[nf]);
                    mma16816(acc[mf][nf], al[mf], bh[nf]);
                }
        }
    }

    const int lr = lane >> 2;
    const int lc = (lane & 3) * 2;
#pragma unroll
    for (int mf = 0; mf < 4; mf++) {
#pragma unroll
        for (int half = 0; half < 2; half++) {
            int row = row0 + wm0 + mf * 16 + lr + half * 8;
            if (row >= M_NODES) continue;
#pragma unroll
            for (int nf = 0; nf < 4; nf++) {
                int col = wn0 + nf * 8 + lc;
                float v0 = acc[mf][nf][2 * half]     + __ldg(bias + col);
                float v1 = acc[mf][nf][2 * half + 1] + __ldg(bias + col + 1);
                v0 = leaky(v0); v1 = leaky(v1);
                size_t base = (size_t)row * H_DIM + col;
                if (MODE == 3) {
                    *(float2*)(out + base) = make_float2(v0, v1);
                } else {
                    __nv_bfloat16* Ch = (MODE == 1) ? g_h1h + (size_t)rel * MH
                                                    : g_Th + (size_t)(rel * 3) * MH;
                    __nv_bfloat16* Cl = (MODE == 1) ? g_h1l + (size_t)rel * MH
                                                    : g_Tl + (size_t)(rel * 3) * MH;
                    if (MODE == 2)
                        *(float2*)(g_T + (size_t)(rel * 2) * MH + base) = make_float2(v0, v1);
                    __nv_bfloat16 h0 = __float2bfloat16(v0);
                    __nv_bfloat16 h1 = __float2bfloat16(v1);
                    __nv_bfloat162 hh; hh.x = h0; hh.y = h1;
                    __nv_bfloat162 ll;
                    ll.x = __float2bfloat16(v0 - __bfloat162float(h0));
                    ll.y = __float2bfloat16(v1 - __bfloat162float(h1));
                    *(__nv_bfloat162*)(Ch + base) = hh;
                    *(__nv_bfloat162*)(Cl + base) = ll;
                }
            }
        }
    }
}

// ---------------------------------------------------------------------------
// Prep kernels
// ---------------------------------------------------------------------------
__global__ void w3eff_kernel(const float* __restrict__ W3) {
    int i = blockIdx.x * blockDim.x + threadIdx.x;
    if (i >= H_DIM * H_DIM) return;
    int row = i / H_DIM, col = i % H_DIM;
    float w0 = W3[(0 * H_DIM + row) * H_DIM + col];
    float w1 = W3[(1 * H_DIM + row) * H_DIM + col];
    float w2 = W3[(2 * H_DIM + row) * H_DIM + col];
    g_W3eff[0 * H_DIM * H_DIM + i] = 3.0f * w0;
    g_W3eff[1 * H_DIM * H_DIM + i] = -3.0f * w0 + 3.0f * w1;
    g_W3eff[2 * H_DIM * H_DIM + i] = 0.75f * w0 - 1.5f * w1 + 0.75f * w2;
}

// Bt3[s][n][k] = W3eff[s][k][n]
__global__ void convW3_kernel() {
    int i = blockIdx.x * blockDim.x + threadIdx.x;
    if (i >= 3 * 128 * 128) return;
    int s = i >> 14, rem = i & 16383, n = rem >> 7, k = rem & 127;
    float v = g_W3eff[(s * 128 + k) * 128 + n];
    __nv_bfloat16 h = __float2bfloat16(v);
    g_Bt3h[i] = h;
    g_Bt3l[i] = __float2bfloat16(v - __bfloat162float(h));
}

// Bt1[r][n][k] = W1_r[k][n]   (K=256)
__global__ void convW1_kernel(const float* __restrict__ Wa, const float* __restrict__ Wb,
                              const float* __restrict__ Wc) {
    int i = blockIdx.x * blockDim.x + threadIdx.x;
    if (i >= 3 * 128 * 256) return;
    int r = i / 32768, rem = i % 32768, n = rem >> 8, k = rem & 255;
    const float* W = r == 0 ? Wa : (r == 1 ? Wb : Wc);
    float v = W[k * H_DIM + n];
    __nv_bfloat16 h = __float2bfloat16(v);
    g_Bt1h[i] = h;
    g_Bt1l[i] = __float2bfloat16(v - __bfloat162float(h));
}

// Bt2[r][n][k] = W2_r[k][n]   (K=128)
__global__ void convW2_kernel(const float* __restrict__ Wa, const float* __restrict__ Wb,
                              const float* __restrict__ Wc) {
    int i = blockIdx.x * blockDim.x + threadIdx.x;
    if (i >= 3 * 128 * 128) return;
    int r = i >> 14, rem = i & 16383, n = rem >> 7, k = rem & 127;
    const float* W = r == 0 ? Wa : (r == 1 ? Wb : Wc);
    float v = W[k * H_DIM + n];
    __nv_bfloat16 h = __float2bfloat16(v);
    g_Bt2h[i] = h;
    g_Bt2l[i] = __float2bfloat16(v - __bfloat162float(h));
}

__global__ void convx_kernel(const float* __restrict__ x) {
    int i = blockIdx.x * blockDim.x + threadIdx.x;
    if (i >= M_NODES * IN_DIM / 2) return;
    float2 v = ((const float2*)x)[i];
    __nv_bfloat16 h0 = __float2bfloat16(v.x), h1 = __float2bfloat16(v.y);
    __nv_bfloat162 hh; hh.x = h0; hh.y = h1;
    __nv_bfloat162 ll;
    ll.x = __float2bfloat16(v.x - __bfloat162float(h0));
    ll.y = __float2bfloat16(v.y - __bfloat162float(h1));
    ((__nv_bfloat162*)g_xh)[i] = hh;
    ((__nv_bfloat162*)g_xl)[i] = ll;
}

// ---------------------------------------------------------------------------
// Graph-side kernels (all relation-batched)
// ---------------------------------------------------------------------------
__global__ void zero_dinv3_kernel() {
    int i = blockIdx.x * blockDim.x + threadIdx.x;
    if (i < 3 * M_NODES) g_dinv3[i] = 0.0f;
}
__global__ void deg3_kernel(const int* __restrict__ d0, const int* __restrict__ d1,
                            const int* __restrict__ d2) {
    int t = blockIdx.x * blockDim.x + threadIdx.x;
    if (t >= 3 * N_EDGES) return;
    int r = t / N_EDGES, e = t - r * N_EDGES;
    const int* d = r == 0 ? d0 : (r == 1 ? d1 : d2);
    atomicAdd(&g_dinv3[r * M_NODES + d[e]], 1.0f);
}
__global__ void dinv3_kernel() {
    int i = blockIdx.x * blockDim.x + threadIdx.x;
    if (i >= 3 * M_NODES) return;
    g_dinv3[i] = rsqrtf(fmaxf(g_dinv3[i], 1.0f));
}
__global__ void zero_agg3_kernel() {
    int i = blockIdx.x * blockDim.x + threadIdx.x;
    if (i >= (int)(3 * MH / 4)) return;
    ((float4*)g_agg3)[i] = make_float4(0.f, 0.f, 0.f, 0.f);
}

// agg[r][dst] += T[r][stage][src] * dinv[r][src], one warp per edge
template <int STAGE>
__global__ void scatter3_kernel(const int* __restrict__ s0, const int* __restrict__ s1,
                                const int* __restrict__ s2, const int* __restrict__ d0,
                                const int* __restrict__ d1, const int* __restrict__ d2) {
    int t = blockIdx.x * blockDim.x + threadIdx.x;
    int eg = t >> 5;
    if (eg >= 3 * N_EDGES) return;
    int r = eg / N_EDGES, e = eg - r * N_EDGES;
    int lane = t & 31;
    const int* sp = r == 0 ? s0 : (r == 1 ? s1 : s2);
    const int* dp = r == 0 ? d0 : (r == 1 ? d1 : d2);
    int s = __ldg(sp + e);
    int d = __ldg(dp + e);
    float ds = __ldg(&g_dinv3[r * M_NODES + s]);
    const float* f = g_T + (size_t)(r * 2 + STAGE) * MH;
    float4 v = *(const float4*)(f + (size_t)s * H_DIM + lane * 4);
    float* out = g_agg3 + (size_t)r * MH + (size_t)d * H_DIM + lane * 4;
    asm volatile("red.global.add.v4.f32 [%0], {%1,%2,%3,%4};"
                 :: "l"(out), "f"(v.x * ds), "f"(v.y * ds), "f"(v.z * ds), "f"(v.w * ds)
                 : "memory");
}

// STEP=1: T[r][1] = T[r][0] - agg*dinv (fp32 + bf16);  STEP=2: bf16 only for stage 2
template <int STEP>
__global__ void combine3_kernel() {
    int i = blockIdx.x * blockDim.x + threadIdx.x;   // float4 units over 3*MH
    if (i >= (int)(3 * MH / 4)) return;
    const int perrel = (int)(MH / 4);
    int r = i / perrel, il = i - r * perrel;
    int n = il >> 5;
    float dn = g_dinv3[r * M_NODES + n];
    const float* fin = g_T + (size_t)(r * 2 + STEP - 1) * MH;
    float4 a = ((const float4*)(g_agg3 + (size_t)r * MH))[il];
    float4 v = ((const float4*)fin)[il];
    v.x -= a.x * dn; v.y -= a.y * dn; v.z -= a.z * dn; v.w -= a.w * dn;
    if (STEP == 1)
        ((float4*)(g_T + (size_t)(r * 2 + 1) * MH))[il] = v;
    size_t base = (size_t)(r * 3 + STEP) * MH + (size_t)il * 4;
    __nv_bfloat16 h0 = __float2bfloat16(v.x), h1 = __float2bfloat16(v.y);
    __nv_bfloat16 h2 = __float2bfloat16(v.z), h3 = __float2bfloat16(v.w);
    __nv_bfloat162 p0; p0.x = h0; p0.y = h1;
    __nv_bfloat162 p1; p1.x = h2; p1.y = h3;
    *(__nv_bfloat162*)(g_Th + base)     = p0;
    *(__nv_bfloat162*)(g_Th + base + 2) = p1;
    __nv_bfloat162 q0, q1;
    q0.x = __float2bfloat16(v.x - __bfloat162float(h0));
    q0.y = __float2bfloat16(v.y - __bfloat162float(h1));
    q1.x = __float2bfloat16(v.z - __bfloat162float(h2));
    q1.y = __float2bfloat16(v.w - __bfloat162float(h3));
    *(__nv_bfloat162*)(g_Tl + base)     = q0;
    *(__nv_bfloat162*)(g_Tl + base + 2) = q1;
}

// ---------------------------------------------------------------------------
// Launch
// ---------------------------------------------------------------------------
extern "C" void kernel_launch(void* const* d_in, const int* in_sizes, int n_in,
                              void* d_out, int out_size) {
    const float* x = (const float*)d_in[0];
    const int *src[3], *dst[3];
    const float *W1[3], *b1[3], *W2[3], *b2[3];
    const float *W3, *b3;

    if (in_sizes[3] == N_EDGES) {
        for (int r = 0; r < 3; r++) {
            src[r] = (const int*)d_in[1 + 2 * r];
            dst[r] = (const int*)d_in[2 + 2 * r];
        }
        for (int r = 0; r < 3; r++) {
            W1[r] = (const float*)d_in[7 + 4 * r];
            b1[r] = (const float*)d_in[8 + 4 * r];
            W2[r] = (const float*)d_in[9 + 4 * r];
            b2[r] = (const float*)d_in[10 + 4 * r];
        }
        W3 = (const float*)d_in[19];
        b3 = (const float*)d_in[20];
    } else {
        for (int r = 0; r < 3; r++) {
            src[r] = (const int*)d_in[1 + 6 * r];
            dst[r] = (const int*)d_in[2 + 6 * r];
            W1[r]  = (const float*)d_in[3 + 6 * r];
            b1[r]  = (const float*)d_in[4 + 6 * r];
            W2[r]  = (const float*)d_in[5 + 6 * r];
            b2[r]  = (const float*)d_in[6 + 6 * r];
        }
        W3 = (const float*)d_in[19];
        b3 = (const float*)d_in[20];
    }

    const int GEMM_X = (M_NODES + 127) / 128;                    // 391
    const int EW3    = (int)((3 * MH / 4 + 255) / 256);
    const int SC3    = (int)(((size_t)3 * N_EDGES * 32 + 255) / 256);
    const int DEG3   = (3 * N_EDGES + 255) / 256;
    const int NV3    = (3 * M_NODES + 255) / 256;

    // Prep (weights, x, degrees) — independent
    w3eff_kernel<<<(H_DIM * H_DIM + 255) / 256, 256>>>(W3);
    convW3_kernel<<<(3 * 128 * 128 + 255) / 256, 256>>>();
    convx_kernel<<<(M_NODES * IN_DIM / 2 + 255) / 256, 256>>>(x);
    convW1_kernel<<<(3 * 128 * 256 + 255) / 256, 256>>>(W1[0], W1[1], W1[2]);
    convW2_kernel<<<(3 * 128 * 128 + 255) / 256, 256>>>(W2[0], W2[1], W2[2]);
    zero_dinv3_kernel<<<NV3, 256>>>();
    deg3_kernel<<<DEG3, 256>>>(dst[0], dst[1], dst[2]);
    dinv3_kernel<<<NV3, 256>>>();

    // MLP (relation-batched)
    {
        dim3 g(GEMM_X, 3);
        mma_gemm<1><<<g, 256>>>(b1[0], b1[1], b1[2], nullptr);
        mma_gemm<2><<<g, 256>>>(b2[0], b2[1], b2[2], nullptr);
    }

    // Propagation step 1
    zero_agg3_kernel<<<EW3, 256>>>();
    scatter3_kernel<0><<<SC3, 256>>>(src[0], src[1], src[2], dst[0], dst[1], dst[2]);
    combine3_kernel<1><<<EW3, 256>>>();

    // Propagation step 2
    zero_agg3_kernel<<<EW3, 256>>>();
    scatter3_kernel<1><<<SC3, 256>>>(src[0], src[1], src[2], dst[0], dst[1], dst[2]);
    combine3_kernel<2><<<EW3, 256>>>();

    // Output projection: K = 9*128, fused bias + leaky -> d_out
    mma_gemm<3><<<GEMM_X, 256>>>(b3, nullptr, nullptr, (float*)d_out);
}

// round 5
// speedup vs baseline: 2.4918x; 1.3118x over previous
#include <cuda_runtime.h>
#include <cuda_bf16.h>
#include <cstdint>

#define M_NODES 50000
#define N_EDGES 600000
#define IN_DIM  256
#define H_DIM   128
#define MH ((size_t)M_NODES * H_DIM)

// ---------------------------------------------------------------------------
// Device scratch
//  g_T   fp32 [3 rel][2 stages(0,1)][MH]
//  g_Th/l bf16 [3 rel][3 stages][MH]
// ---------------------------------------------------------------------------
__device__ __align__(256) float g_T[6 * MH];
__device__ __align__(256) float g_dinv3[3 * M_NODES];
__device__ __align__(256) int   g_cnt[3 * M_NODES];
__device__ __align__(256) int   g_cur[3 * M_NODES];
__device__ __align__(256) int   g_sorted[(size_t)3 * N_EDGES];

__device__ __align__(256) __nv_bfloat16 g_xh[(size_t)M_NODES * IN_DIM];
__device__ __align__(256) __nv_bfloat16 g_xl[(size_t)M_NODES * IN_DIM];
__device__ __align__(256) __nv_bfloat16 g_h1h[3 * MH];
__device__ __align__(256) __nv_bfloat16 g_h1l[3 * MH];
__device__ __align__(256) __nv_bfloat16 g_Th[9 * MH];
__device__ __align__(256) __nv_bfloat16 g_Tl[9 * MH];
__device__ __align__(256) __nv_bfloat16 g_Bt1h[3 * 128 * 256];
__device__ __align__(256) __nv_bfloat16 g_Bt1l[3 * 128 * 256];
__device__ __align__(256) __nv_bfloat16 g_Bt2h[3 * 128 * 128];
__device__ __align__(256) __nv_bfloat16 g_Bt2l[3 * 128 * 128];
__device__ __align__(256) __nv_bfloat16 g_Bt3h[3 * 128 * 128];
__device__ __align__(256) __nv_bfloat16 g_Bt3l[3 * 128 * 128];

__device__ __forceinline__ float leaky(float v) { return v > 0.0f ? v : 0.01f * v; }

__device__ __forceinline__ uint32_t s2u(const void* p) {
    uint32_t a;
    asm("{ .reg .u64 t; cvta.to.shared.u64 t, %1; cvt.u32.u64 %0, t; }" : "=r"(a) : "l"(p));
    return a;
}
__device__ __forceinline__ void ldm_x4(uint32_t* r, uint32_t addr) {
    asm volatile("ldmatrix.sync.aligned.m8n8.x4.shared.b16 {%0,%1,%2,%3}, [%4];"
                 : "=r"(r[0]), "=r"(r[1]), "=r"(r[2]), "=r"(r[3]) : "r"(addr));
}
__device__ __forceinline__ void mma16816(float* c, const uint32_t* a, const uint32_t* b) {
    asm volatile(
        "mma.sync.aligned.m16n8k16.row.col.f32.bf16.bf16.f32 "
        "{%0,%1,%2,%3}, {%4,%5,%6,%7}, {%8,%9}, {%0,%1,%2,%3};"
        : "+f"(c[0]), "+f"(c[1]), "+f"(c[2]), "+f"(c[3])
        : "r"(a[0]), "r"(a[1]), "r"(a[2]), "r"(a[3]), "r"(b[0]), "r"(b[1]));
}

// ---------------------------------------------------------------------------
// Warp-MMA GEMM (identical to R4): 128x128 tile, BK=32, 8 warps, 3-pass hi/lo
// ---------------------------------------------------------------------------
#define SPAD 40

template <int MODE>
__global__ void __launch_bounds__(256, 1)
mma_gemm(const float* __restrict__ bias0, const float* __restrict__ bias1,
         const float* __restrict__ bias2, float* __restrict__ out) {
    __shared__ __nv_bfloat16 sAh[128][SPAD], sAl[128][SPAD];
    __shared__ __nv_bfloat16 sBh[128][SPAD], sBl[128][SPAD];

    const int tid = threadIdx.x;
    const int wid = tid >> 5;
    const int lane = tid & 31;
    const int row0 = blockIdx.x * 128;
    const int rel = (MODE == 3) ? 0 : blockIdx.y;
    const int wm0 = (wid & 1) * 64;
    const int wn0 = (wid >> 1) * 32;

    const float* bias = (MODE == 3) ? bias0 : (rel == 0 ? bias0 : (rel == 1 ? bias1 : bias2));

    const uint32_t uAh = s2u(sAh), uAl = s2u(sAl), uBh = s2u(sBh), uBl = s2u(sBl);

    float acc[4][4][4] = {};

    const int a_row = (lane & 7) + ((lane >> 3) & 1) * 8;
    const int a_kof = ((lane >> 4) & 1) * 8;
    const int b_nof = ((lane >> 4) & 1) * 8;
    const int b_kof = ((lane >> 3) & 1) * 8;
    const int b_row = lane & 7;

    constexpr int KTOT = (MODE == 1) ? 256 : (MODE == 2) ? 128 : 1152;

    for (int k0 = 0; k0 < KTOT; k0 += 32) {
        const __nv_bfloat16 *pAh, *pAl, *pBh, *pBl;
        int ars, ako, bko;
        if (MODE == 1) {
            pAh = g_xh; pAl = g_xl; ars = 256; ako = k0;
            pBh = g_Bt1h + rel * 128 * 256; pBl = g_Bt1l + rel * 128 * 256; bko = k0;
        } else if (MODE == 2) {
            pAh = g_h1h + (size_t)rel * MH; pAl = g_h1l + (size_t)rel * MH; ars = 128; ako = k0;
            pBh = g_Bt2h + rel * 128 * 128; pBl = g_Bt2l + rel * 128 * 128; bko = k0;
        } else {
            int c = k0 >> 7;
            int s = c % 3;
            pAh = g_Th + (size_t)c * MH; pAl = g_Tl + (size_t)c * MH;
            ars = 128; ako = k0 & 127;
            pBh = g_Bt3h + s * 128 * 128; pBl = g_Bt3l + s * 128 * 128; bko = k0 & 127;
        }
        constexpr int BSTRIDE = (MODE == 1) ? 256 : 128;

        __syncthreads();
#pragma unroll
        for (int it = 0; it < 2; it++) {
            int i = it * 256 + tid;
            int r = i >> 2, q = (i & 3) * 8;
            uint4 z = make_uint4(0, 0, 0, 0);
            uint4 vh = z, vl = z;
            int gr = row0 + r;
            if (gr < M_NODES) {
                vh = *(const uint4*)(pAh + (size_t)gr * ars + ako + q);
                vl = *(const uint4*)(pAl + (size_t)gr * ars + ako + q);
            }
            *(uint4*)&sAh[r][q] = vh;
            *(uint4*)&sAl[r][q] = vl;
            *(uint4*)&sBh[r][q] = *(const uint4*)(pBh + (size_t)r * BSTRIDE + bko + q);
            *(uint4*)&sBl[r][q] = *(const uint4*)(pBl + (size_t)r * BSTRIDE + bko + q);
        }
        __syncthreads();

#pragma unroll
        for (int ks = 0; ks < 32; ks += 16) {
            uint32_t ah[4][4], al[4][4], bh[4][2], bl[4][2];
#pragma unroll
            for (int mf = 0; mf < 4; mf++) {
                uint32_t off = ((wm0 + mf * 16 + a_row) * SPAD + ks + a_kof) * 2;
                ldm_x4(ah[mf], uAh + off);
                ldm_x4(al[mf], uAl + off);
            }
#pragma unroll
            for (int nb = 0; nb < 2; nb++) {
                uint32_t off = ((wn0 + nb * 16 + b_nof + b_row) * SPAD + ks + b_kof) * 2;
                uint32_t t[4];
                ldm_x4(t, uBh + off);
                bh[2 * nb][0] = t[0]; bh[2 * nb][1] = t[1];
                bh[2 * nb + 1][0] = t[2]; bh[2 * nb + 1][1] = t[3];
                ldm_x4(t, uBl + off);
                bl[2 * nb][0] = t[0]; bl[2 * nb][1] = t[1];
                bl[2 * nb + 1][0] = t[2]; bl[2 * nb + 1][1] = t[3];
            }
#pragma unroll
            for (int mf = 0; mf < 4; mf++)
#pragma unroll
                for (int nf = 0; nf < 4; nf++) {
                    mma16816(acc[mf][nf], ah[mf], bh[nf]);
                    mma16816(acc[mf][nf], ah[mf], bl[nf]);
                    mma16816(acc[mf][nf], al[mf], bh[nf]);
                }
        }
    }

    const int lr = lane >> 2;
    const int lc = (lane & 3) * 2;
#pragma unroll
    for (int mf = 0; mf < 4; mf++) {
#pragma unroll
        for (int half = 0; half < 2; half++) {
            int row = row0 + wm0 + mf * 16 + lr + half * 8;
            if (row >= M_NODES) continue;
#pragma unroll
            for (int nf = 0; nf < 4; nf++) {
                int col = wn0 + nf * 8 + lc;
                float v0 = acc[mf][nf][2 * half]     + __ldg(bias + col);
                float v1 = acc[mf][nf][2 * half + 1] + __ldg(bias + col + 1);
                v0 = leaky(v0); v1 = leaky(v1);
                size_t base = (size_t)row * H_DIM + col;
                if (MODE == 3) {
                    *(float2*)(out + base) = make_float2(v0, v1);
                } else {
                    __nv_bfloat16* Ch = (MODE == 1) ? g_h1h + (size_t)rel * MH
                                                    : g_Th + (size_t)(rel * 3) * MH;
                    __nv_bfloat16* Cl = (MODE == 1) ? g_h1l + (size_t)rel * MH
                                                    : g_Tl + (size_t)(rel * 3) * MH;
                    if (MODE == 2)
                        *(float2*)(g_T + (size_t)(rel * 2) * MH + base) = make_float2(v0, v1);
                    __nv_bfloat16 h0 = __float2bfloat16(v0);
                    __nv_bfloat16 h1 = __float2bfloat16(v1);
                    __nv_bfloat162 hh; hh.x = h0; hh.y = h1;
                    __nv_bfloat162 ll;
                    ll.x = __float2bfloat16(v0 - __bfloat162float(h0));
                    ll.y = __float2bfloat16(v1 - __bfloat162float(h1));
                    *(__nv_bfloat162*)(Ch + base) = hh;
                    *(__nv_bfloat162*)(Cl + base) = ll;
                }
            }
        }
    }
}

// ---------------------------------------------------------------------------
// Prep kernels
// ---------------------------------------------------------------------------
// Bt3[s][n][k] = W3eff[s][k][n], THETAS folded: one thread per (k,n), 3 outputs
__global__ void convW3_kernel(const float* __restrict__ W3) {
    int i = blockIdx.x * blockDim.x + threadIdx.x;
    if (i >= 128 * 128) return;
    int n = i >> 7, k = i & 127;
    float w0 = W3[(0 * 128 + k) * 128 + n];
    float w1 = W3[(1 * 128 + k) * 128 + n];
    float w2 = W3[(2 * 128 + k) * 128 + n];
    float e[3];
    e[0] = 3.0f * w0;
    e[1] = -3.0f * w0 + 3.0f * w1;
    e[2] = 0.75f * w0 - 1.5f * w1 + 0.75f * w2;
#pragma unroll
    for (int s = 0; s < 3; s++) {
        __nv_bfloat16 h = __float2bfloat16(e[s]);
        g_Bt3h[s * 128 * 128 + n * 128 + k] = h;
        g_Bt3l[s * 128 * 128 + n * 128 + k] = __float2bfloat16(e[s] - __bfloat162float(h));
    }
}

__global__ void convW1_kernel(const float* __restrict__ Wa, const float* __restrict__ Wb,
                              const float* __restrict__ Wc) {
    int i = blockIdx.x * blockDim.x + threadIdx.x;
    if (i >= 3 * 128 * 256) return;
    int r = i / 32768, rem = i % 32768, n = rem >> 8, k = rem & 255;
    const float* W = r == 0 ? Wa : (r == 1 ? Wb : Wc);
    float v = W[k * H_DIM + n];
    __nv_bfloat16 h = __float2bfloat16(v);
    g_Bt1h[i] = h;
    g_Bt1l[i] = __float2bfloat16(v - __bfloat162float(h));
}

__global__ void convW2_kernel(const float* __restrict__ Wa, const float* __restrict__ Wb,
                              const float* __restrict__ Wc) {
    int i = blockIdx.x * blockDim.x + threadIdx.x;
    if (i >= 3 * 128 * 128) return;
    int r = i >> 14, rem = i & 16383, n = rem >> 7, k = rem & 127;
    const float* W = r == 0 ? Wa : (r == 1 ? Wb : Wc);
    float v = W[k * H_DIM + n];
    __nv_bfloat16 h = __float2bfloat16(v);
    g_Bt2h[i] = h;
    g_Bt2l[i] = __float2bfloat16(v - __bfloat162float(h));
}

__global__ void convx_kernel(const float* __restrict__ x) {
    int i = blockIdx.x * blockDim.x + threadIdx.x;
    if (i >= M_NODES * IN_DIM / 2) return;
    float2 v = ((const float2*)x)[i];
    __nv_bfloat16 h0 = __float2bfloat16(v.x), h1 = __float2bfloat16(v.y);
    __nv_bfloat162 hh; hh.x = h0; hh.y = h1;
    __nv_bfloat162 ll;
    ll.x = __float2bfloat16(v.x - __bfloat162float(h0));
    ll.y = __float2bfloat16(v.y - __bfloat162float(h1));
    ((__nv_bfloat162*)g_xh)[i] = hh;
    ((__nv_bfloat162*)g_xl)[i] = ll;
}

// ---------------------------------------------------------------------------
// Graph preprocessing: histogram -> dinv, exclusive scan, counting-sort fill
// ---------------------------------------------------------------------------
__global__ void zero_cnt_kernel() {
    int i = blockIdx.x * blockDim.x + threadIdx.x;
    if (i < 3 * M_NODES) g_cnt[i] = 0;
}
__global__ void deg3_kernel(const int* __restrict__ d0, const int* __restrict__ d1,
                            const int* __restrict__ d2) {
    int t = blockIdx.x * blockDim.x + threadIdx.x;
    if (t >= 3 * N_EDGES) return;
    int r = t / N_EDGES, e = t - r * N_EDGES;
    const int* d = r == 0 ? d0 : (r == 1 ? d1 : d2);
    atomicAdd(&g_cnt[r * M_NODES + __ldg(d + e)], 1);
}
__global__ void dinv3_kernel() {
    int i = blockIdx.x * blockDim.x + threadIdx.x;
    if (i >= 3 * M_NODES) return;
    g_dinv3[i] = rsqrtf(fmaxf((float)g_cnt[i], 1.0f));
}

// Exclusive scan of g_cnt per relation -> g_cur.  One block per relation.
__global__ void scan_kernel() {
    __shared__ int sh[1024];
    __shared__ int sc_carry;
    const int r = blockIdx.x;
    const int tid = threadIdx.x;
    if (tid == 0) sc_carry = 0;
    __syncthreads();
    for (int base = 0; base < M_NODES; base += 1024) {
        int i = base + tid;
        int v = (i < M_NODES) ? g_cnt[r * M_NODES + i] : 0;
        sh[tid] = v;
        __syncthreads();
        int carry = sc_carry;
        for (int off = 1; off < 1024; off <<= 1) {
            int t = (tid >= off) ? sh[tid - off] : 0;
            __syncthreads();
            sh[tid] += t;
            __syncthreads();
        }
        if (i < M_NODES) g_cur[r * M_NODES + i] = carry + sh[tid] - v;   // exclusive
        __syncthreads();
        if (tid == 1023) sc_carry = carry + sh[1023];
        __syncthreads();
    }
}

// Counting-sort fill: sorted[r][off[dst]++] = src
__global__ void fill_kernel(const int* __restrict__ s0, const int* __restrict__ s1,
                            const int* __restrict__ s2, const int* __restrict__ d0,
                            const int* __restrict__ d1, const int* __restrict__ d2) {
    int t = blockIdx.x * blockDim.x + threadIdx.x;
    if (t >= 3 * N_EDGES) return;
    int r = t / N_EDGES, e = t - r * N_EDGES;
    const int* sp = r == 0 ? s0 : (r == 1 ? s1 : s2);
    const int* dp = r == 0 ? d0 : (r == 1 ? d1 : d2);
    int s = __ldg(sp + e);
    int d = __ldg(dp + e);
    int p = atomicAdd(&g_cur[r * M_NODES + d], 1);
    g_sorted[(size_t)r * N_EDGES + p] = s;
}

// ---------------------------------------------------------------------------
// Fused segmented-sum + combine: one warp per (rel, node)
//   T[STEP] = T[STEP-1] - (sum_{src in seg} T[STEP-1][src]*dinv[src]) * dinv[n]
//   writes fp32 (STEP==1 only) + bf16 hi/lo at stage STEP
// ---------------------------------------------------------------------------
template <int STEP>
__global__ void __launch_bounds__(256) segsum_kernel() {
    int t = blockIdx.x * blockDim.x + threadIdx.x;
    int w = t >> 5;
    if (w >= 3 * M_NODES) return;
    const int lane = t & 31;
    const int r = w / M_NODES, n = w - r * M_NODES;
    const int rn = r * M_NODES + n;
    const int end = __ldg(&g_cur[rn]);
    const int cnt = __ldg(&g_cnt[rn]);
    int j = end - cnt;
    const int* ss = g_sorted + (size_t)r * N_EDGES;
    const float* f = g_T + (size_t)(r * 2 + STEP - 1) * MH;
    const float* dv = g_dinv3 + r * M_NODES;

    float4 a0 = make_float4(0.f, 0.f, 0.f, 0.f);
    float4 a1 = make_float4(0.f, 0.f, 0.f, 0.f);
    for (; j + 2 <= end; j += 2) {
        int s0 = __ldg(ss + j);
        int s1 = __ldg(ss + j + 1);
        float e0 = __ldg(dv + s0);
        float e1 = __ldg(dv + s1);
        float4 v0 = *(const float4*)(f + (size_t)s0 * H_DIM + lane * 4);
        float4 v1 = *(const float4*)(f + (size_t)s1 * H_DIM + lane * 4);
        a0.x += v0.x * e0; a0.y += v0.y * e0; a0.z += v0.z * e0; a0.w += v0.w * e0;
        a1.x += v1.x * e1; a1.y += v1.y * e1; a1.z += v1.z * e1; a1.w += v1.w * e1;
    }
    if (j < end) {
        int s0 = __ldg(ss + j);
        float e0 = __ldg(dv + s0);
        float4 v0 = *(const float4*)(f + (size_t)s0 * H_DIM + lane * 4);
        a0.x += v0.x * e0; a0.y += v0.y * e0; a0.z += v0.z * e0; a0.w += v0.w * e0;
    }
    float dn = __ldg(dv + n);
    float4 t0 = *(const float4*)(f + (size_t)n * H_DIM + lane * 4);
    float4 o;
    o.x = t0.x - (a0.x + a1.x) * dn;
    o.y = t0.y - (a0.y + a1.y) * dn;
    o.z = t0.z - (a0.z + a1.z) * dn;
    o.w = t0.w - (a0.w + a1.w) * dn;

    if (STEP == 1)
        *(float4*)(g_T + (size_t)(r * 2 + 1) * MH + (size_t)n * H_DIM + lane * 4) = o;

    size_t base = (size_t)(r * 3 + STEP) * MH + (size_t)n * H_DIM + lane * 4;
    __nv_bfloat16 h0 = __float2bfloat16(o.x), h1 = __float2bfloat16(o.y);
    __nv_bfloat16 h2 = __float2bfloat16(o.z), h3 = __float2bfloat16(o.w);
    __nv_bfloat162 p0; p0.x = h0; p0.y = h1;
    __nv_bfloat162 p1; p1.x = h2; p1.y = h3;
    *(__nv_bfloat162*)(g_Th + base)     = p0;
    *(__nv_bfloat162*)(g_Th + base + 2) = p1;
    __nv_bfloat162 q0, q1;
    q0.x = __float2bfloat16(o.x - __bfloat162float(h0));
    q0.y = __float2bfloat16(o.y - __bfloat162float(h1));
    q1.x = __float2bfloat16(o.z - __bfloat162float(h2));
    q1.y = __float2bfloat16(o.w - __bfloat162float(h3));
    *(__nv_bfloat162*)(g_Tl + base)     = q0;
    *(__nv_bfloat162*)(g_Tl + base + 2) = q1;
}

// ---------------------------------------------------------------------------
// Launch
// ---------------------------------------------------------------------------
extern "C" void kernel_launch(void* const* d_in, const int* in_sizes, int n_in,
                              void* d_out, int out_size) {
    const float* x = (const float*)d_in[0];
    const int *src[3], *dst[3];
    const float *W1[3], *b1[3], *W2[3], *b2[3];
    const float *W3, *b3;

    if (in_sizes[3] == N_EDGES) {
        for (int r = 0; r < 3; r++) {
            src[r] = (const int*)d_in[1 + 2 * r];
            dst[r] = (const int*)d_in[2 + 2 * r];
        }
        for (int r = 0; r < 3; r++) {
            W1[r] = (const float*)d_in[7 + 4 * r];
            b1[r] = (const float*)d_in[8 + 4 * r];
            W2[r] = (const float*)d_in[9 + 4 * r];
            b2[r] = (const float*)d_in[10 + 4 * r];
        }
        W3 = (const float*)d_in[19];
        b3 = (const float*)d_in[20];
    } else {
        for (int r = 0; r < 3; r++) {
            src[r] = (const int*)d_in[1 + 6 * r];
            dst[r] = (const int*)d_in[2 + 6 * r];
            W1[r]  = (const float*)d_in[3 + 6 * r];
            b1[r]  = (const float*)d_in[4 + 6 * r];
            W2[r]  = (const float*)d_in[5 + 6 * r];
            b2[r]  = (const float*)d_in[6 + 6 * r];
        }
        W3 = (const float*)d_in[19];
        b3 = (const float*)d_in[20];
    }

    const int GEMM_X = (M_NODES + 127) / 128;                    // 391
    const int E3     = (3 * N_EDGES + 255) / 256;
    const int NV3    = (3 * M_NODES + 255) / 256;
    const int SEG3   = (int)(((size_t)3 * M_NODES * 32 + 255) / 256);

    // Prep
    convW3_kernel<<<(128 * 128 + 255) / 256, 256>>>(W3);
    convx_kernel<<<(M_NODES * IN_DIM / 2 + 255) / 256, 256>>>(x);
    convW1_kernel<<<(3 * 128 * 256 + 255) / 256, 256>>>(W1[0], W1[1], W1[2]);
    convW2_kernel<<<(3 * 128 * 128 + 255) / 256, 256>>>(W2[0], W2[1], W2[2]);

    // Graph preprocessing
    zero_cnt_kernel<<<NV3, 256>>>();
    deg3_kernel<<<E3, 256>>>(dst[0], dst[1], dst[2]);
    dinv3_kernel<<<NV3, 256>>>();
    scan_kernel<<<3, 1024>>>();
    fill_kernel<<<E3, 256>>>(src[0], src[1], src[2], dst[0], dst[1], dst[2]);

    // MLP (relation-batched)
    {
        dim3 g(GEMM_X, 3);
        mma_gemm<1><<<g, 256>>>(b1[0], b1[1], b1[2], nullptr);
        mma_gemm<2><<<g, 256>>>(b2[0], b2[1], b2[2], nullptr);
    }

    // Propagation (fused gather + combine)
    segsum_kernel<1><<<SEG3, 256>>>();
    segsum_kernel<2><<<SEG3, 256>>>();

    // Output projection: K = 9*128, fused bias + leaky -> d_out
    mma_gemm<3><<<GEMM_X, 256>>>(b3, nullptr, nullptr, (float*)d_out);
}

// round 6
// speedup vs baseline: 2.6392x; 1.0591x over previous
#include <cuda_runtime.h>
#include <cuda_bf16.h>
#include <cstdint>

#define M_NODES 50000
#define N_EDGES 600000
#define IN_DIM  256
#define H_DIM   128
#define MH ((size_t)M_NODES * H_DIM)

// ---------------------------------------------------------------------------
// Device scratch — all activations fp32; hi/lo split happens in-register
// g_T layout: [3 rel][3 stage][MH]
// ---------------------------------------------------------------------------
__device__ __align__(256) float g_T[9 * MH];
__device__ __align__(256) float g_h1[3 * MH];
__device__ __align__(256) float g_dinv3[3 * M_NODES];
__device__ __align__(256) int   g_cnt[3 * M_NODES];
__device__ __align__(256) int   g_cur[3 * M_NODES];
__device__ __align__(256) int   g_sorted[(size_t)3 * N_EDGES];

__device__ __align__(256) __nv_bfloat16 g_Bt1h[3 * 128 * 256];
__device__ __align__(256) __nv_bfloat16 g_Bt1l[3 * 128 * 256];
__device__ __align__(256) __nv_bfloat16 g_Bt2h[3 * 128 * 128];
__device__ __align__(256) __nv_bfloat16 g_Bt2l[3 * 128 * 128];
__device__ __align__(256) __nv_bfloat16 g_Bt3h[3 * 128 * 128];
__device__ __align__(256) __nv_bfloat16 g_Bt3l[3 * 128 * 128];

__device__ __forceinline__ float leaky(float v) { return v > 0.0f ? v : 0.01f * v; }

__device__ __forceinline__ uint32_t s2u(const void* p) {
    uint32_t a;
    asm("{ .reg .u64 t; cvta.to.shared.u64 t, %1; cvt.u32.u64 %0, t; }" : "=r"(a) : "l"(p));
    return a;
}
__device__ __forceinline__ void ldm_x4(uint32_t* r, uint32_t addr) {
    asm volatile("ldmatrix.sync.aligned.m8n8.x4.shared.b16 {%0,%1,%2,%3}, [%4];"
                 : "=r"(r[0]), "=r"(r[1]), "=r"(r[2]), "=r"(r[3]) : "r"(addr));
}
__device__ __forceinline__ void mma16816(float* c, const uint32_t* a, const uint32_t* b) {
    asm volatile(
        "mma.sync.aligned.m16n8k16.row.col.f32.bf16.bf16.f32 "
        "{%0,%1,%2,%3}, {%4,%5,%6,%7}, {%8,%9}, {%0,%1,%2,%3};"
        : "+f"(c[0]), "+f"(c[1]), "+f"(c[2]), "+f"(c[3])
        : "r"(a[0]), "r"(a[1]), "r"(a[2]), "r"(a[3]), "r"(b[0]), "r"(b[1]));
}

// Split 2 floats into packed bf16 hi and lo (residual) pairs
__device__ __forceinline__ void split2(float x, float y, uint32_t& hi, uint32_t& lo) {
    __nv_bfloat162 h;
    h.x = __float2bfloat16(x);
    h.y = __float2bfloat16(y);
    __nv_bfloat162 l;
    l.x = __float2bfloat16(x - __bfloat162float(h.x));
    l.y = __float2bfloat16(y - __bfloat162float(h.y));
    hi = *(uint32_t*)&h;
    lo = *(uint32_t*)&l;
}

// ---------------------------------------------------------------------------
// Warp-MMA GEMM, 128x128 tile, BK=32, 8 warps (64x32), 3-pass hi/lo.
// A is fp32 in global, split to hi/lo bf16 during smem fill.
//  MODE 1 (grid.y=rel): g_h1[r]      = leaky(x @ W1[r]^T + b1[r])        [fp32]
//  MODE 2 (grid.y=rel): g_T[r][0]    = leaky(h1[r] @ W2[r]^T + b2[r])    [fp32]
//  MODE 3: out = leaky( sum_{r,s} T[r][s] @ W3eff[s]^T + b3 )
// ---------------------------------------------------------------------------
#define SPAD 40

template <int MODE>
__global__ void __launch_bounds__(256, 1)
mma_gemm(const float* __restrict__ bias0, const float* __restrict__ bias1,
         const float* __restrict__ bias2, const float* __restrict__ Ax,
         float* __restrict__ out) {
    __shared__ __nv_bfloat16 sAh[128][SPAD], sAl[128][SPAD];
    __shared__ __nv_bfloat16 sBh[128][SPAD], sBl[128][SPAD];

    const int tid = threadIdx.x;
    const int wid = tid >> 5;
    const int lane = tid & 31;
    const int row0 = blockIdx.x * 128;
    const int rel = (MODE == 3) ? 0 : blockIdx.y;
    const int wm0 = (wid & 1) * 64;
    const int wn0 = (wid >> 1) * 32;

    const float* bias = (MODE == 3) ? bias0 : (rel == 0 ? bias0 : (rel == 1 ? bias1 : bias2));

    const uint32_t uAh = s2u(sAh), uAl = s2u(sAl), uBh = s2u(sBh), uBl = s2u(sBl);

    float acc[4][4][4] = {};

    const int a_row = (lane & 7) + ((lane >> 3) & 1) * 8;
    const int a_kof = ((lane >> 4) & 1) * 8;
    const int b_nof = ((lane >> 4) & 1) * 8;
    const int b_kof = ((lane >> 3) & 1) * 8;
    const int b_row = lane & 7;

    constexpr int KTOT = (MODE == 1) ? 256 : (MODE == 2) ? 128 : 1152;

    for (int k0 = 0; k0 < KTOT; k0 += 32) {
        const float* pA;
        const __nv_bfloat16 *pBh, *pBl;
        int ars, ako, bko;
        if (MODE == 1) {
            pA = Ax; ars = 256; ako = k0;
            pBh = g_Bt1h + rel * 128 * 256; pBl = g_Bt1l + rel * 128 * 256; bko = k0;
        } else if (MODE == 2) {
            pA = g_h1 + (size_t)rel * MH; ars = 128; ako = k0;
            pBh = g_Bt2h + rel * 128 * 128; pBl = g_Bt2l + rel * 128 * 128; bko = k0;
        } else {
            int c = k0 >> 7;           // 0..8 == r*3+s
            int s = c % 3;
            pA = g_T + (size_t)c * MH; ars = 128; ako = k0 & 127;
            pBh = g_Bt3h + s * 128 * 128; pBl = g_Bt3l + s * 128 * 128; bko = k0 & 127;
        }
        constexpr int BSTRIDE = (MODE == 1) ? 256 : 128;

        __syncthreads();
#pragma unroll
        for (int it = 0; it < 2; it++) {
            int i = it * 256 + tid;
            int r = i >> 2, q = (i & 3) * 8;
            int gr = row0 + r;
            float4 f0 = make_float4(0.f, 0.f, 0.f, 0.f);
            float4 f1 = make_float4(0.f, 0.f, 0.f, 0.f);
            if (gr < M_NODES) {
                const float* ap = pA + (size_t)gr * ars + ako + q;
                f0 = *(const float4*)ap;
                f1 = *(const float4*)(ap + 4);
            }
            uint4 H, L;
            split2(f0.x, f0.y, H.x, L.x);
            split2(f0.z, f0.w, H.y, L.y);
            split2(f1.x, f1.y, H.z, L.z);
            split2(f1.z, f1.w, H.w, L.w);
            *(uint4*)&sAh[r][q] = H;
            *(uint4*)&sAl[r][q] = L;
            *(uint4*)&sBh[r][q] = *(const uint4*)(pBh + (size_t)r * BSTRIDE + bko + q);
            *(uint4*)&sBl[r][q] = *(const uint4*)(pBl + (size_t)r * BSTRIDE + bko + q);
        }
        __syncthreads();

#pragma unroll
        for (int ks = 0; ks < 32; ks += 16) {
            uint32_t ah[4][4], al[4][4], bh[4][2], bl[4][2];
#pragma unroll
            for (int mf = 0; mf < 4; mf++) {
                uint32_t off = ((wm0 + mf * 16 + a_row) * SPAD + ks + a_kof) * 2;
                ldm_x4(ah[mf], uAh + off);
                ldm_x4(al[mf], uAl + off);
            }
#pragma unroll
            for (int nb = 0; nb < 2; nb++) {
                uint32_t off = ((wn0 + nb * 16 + b_nof + b_row) * SPAD + ks + b_kof) * 2;
                uint32_t t[4];
                ldm_x4(t, uBh + off);
                bh[2 * nb][0] = t[0]; bh[2 * nb][1] = t[1];
                bh[2 * nb + 1][0] = t[2]; bh[2 * nb + 1][1] = t[3];
                ldm_x4(t, uBl + off);
                bl[2 * nb][0] = t[0]; bl[2 * nb][1] = t[1];
                bl[2 * nb + 1][0] = t[2]; bl[2 * nb + 1][1] = t[3];
            }
#pragma unroll
            for (int mf = 0; mf < 4; mf++)
#pragma unroll
                for (int nf = 0; nf < 4; nf++) {
                    mma16816(acc[mf][nf], ah[mf], bh[nf]);
                    mma16816(acc[mf][nf], ah[mf], bl[nf]);
                    mma16816(acc[mf][nf], al[mf], bh[nf]);
                }
        }
    }

    const int lr = lane >> 2;
    const int lc = (lane & 3) * 2;
#pragma unroll
    for (int mf = 0; mf < 4; mf++) {
#pragma unroll
        for (int half = 0; half < 2; half++) {
            int row = row0 + wm0 + mf * 16 + lr + half * 8;
            if (row >= M_NODES) continue;
#pragma unroll
            for (int nf = 0; nf < 4; nf++) {
                int col = wn0 + nf * 8 + lc;
                float v0 = acc[mf][nf][2 * half]     + __ldg(bias + col);
                float v1 = acc[mf][nf][2 * half + 1] + __ldg(bias + col + 1);
                v0 = leaky(v0); v1 = leaky(v1);
                size_t base = (size_t)row * H_DIM + col;
                float* dstp;
                if (MODE == 3)      dstp = out;
                else if (MODE == 1) dstp = g_h1 + (size_t)rel * MH;
                else                dstp = g_T + (size_t)(rel * 3) * MH;
                *(float2*)(dstp + base) = make_float2(v0, v1);
            }
        }
    }
}

// ---------------------------------------------------------------------------
// Weight prep (bf16 hi/lo, transposed to [n][k])
// ---------------------------------------------------------------------------
__global__ void convW3_kernel(const float* __restrict__ W3) {
    int i = blockIdx.x * blockDim.x + threadIdx.x;
    if (i >= 128 * 128) return;
    int n = i >> 7, k = i & 127;
    float w0 = W3[(0 * 128 + k) * 128 + n];
    float w1 = W3[(1 * 128 + k) * 128 + n];
    float w2 = W3[(2 * 128 + k) * 128 + n];
    float e[3];
    e[0] = 3.0f * w0;
    e[1] = -3.0f * w0 + 3.0f * w1;
    e[2] = 0.75f * w0 - 1.5f * w1 + 0.75f * w2;
#pragma unroll
    for (int s = 0; s < 3; s++) {
        __nv_bfloat16 h = __float2bfloat16(e[s]);
        g_Bt3h[s * 128 * 128 + n * 128 + k] = h;
        g_Bt3l[s * 128 * 128 + n * 128 + k] = __float2bfloat16(e[s] - __bfloat162float(h));
    }
}

__global__ void convW1_kernel(const float* __restrict__ Wa, const float* __restrict__ Wb,
                              const float* __restrict__ Wc) {
    int i = blockIdx.x * blockDim.x + threadIdx.x;
    if (i >= 3 * 128 * 256) return;
    int r = i / 32768, rem = i % 32768, n = rem >> 8, k = rem & 255;
    const float* W = r == 0 ? Wa : (r == 1 ? Wb : Wc);
    float v = W[k * H_DIM + n];
    __nv_bfloat16 h = __float2bfloat16(v);
    g_Bt1h[i] = h;
    g_Bt1l[i] = __float2bfloat16(v - __bfloat162float(h));
}

__global__ void convW2_kernel(const float* __restrict__ Wa, const float* __restrict__ Wb,
                              const float* __restrict__ Wc) {
    int i = blockIdx.x * blockDim.x + threadIdx.x;
    if (i >= 3 * 128 * 128) return;
    int r = i >> 14, rem = i & 16383, n = rem >> 7, k = rem & 127;
    const float* W = r == 0 ? Wa : (r == 1 ? Wb : Wc);
    float v = W[k * H_DIM + n];
    __nv_bfloat16 h = __float2bfloat16(v);
    g_Bt2h[i] = h;
    g_Bt2l[i] = __float2bfloat16(v - __bfloat162float(h));
}

// ---------------------------------------------------------------------------
// Graph preprocessing: histogram -> dinv, exclusive scan, counting-sort fill
// ---------------------------------------------------------------------------
__global__ void zero_cnt_kernel() {
    int i = blockIdx.x * blockDim.x + threadIdx.x;
    if (i < 3 * M_NODES) g_cnt[i] = 0;
}
__global__ void deg3_kernel(const int* __restrict__ d0, const int* __restrict__ d1,
                            const int* __restrict__ d2) {
    int t = blockIdx.x * blockDim.x + threadIdx.x;
    if (t >= 3 * N_EDGES) return;
    int r = t / N_EDGES, e = t - r * N_EDGES;
    const int* d = r == 0 ? d0 : (r == 1 ? d1 : d2);
    atomicAdd(&g_cnt[r * M_NODES + __ldg(d + e)], 1);
}
__global__ void dinv3_kernel() {
    int i = blockIdx.x * blockDim.x + threadIdx.x;
    if (i >= 3 * M_NODES) return;
    g_dinv3[i] = rsqrtf(fmaxf((float)g_cnt[i], 1.0f));
}

__global__ void scan_kernel() {
    __shared__ int sh[1024];
    __shared__ int sc_carry;
    const int r = blockIdx.x;
    const int tid = threadIdx.x;
    if (tid == 0) sc_carry = 0;
    __syncthreads();
    for (int base = 0; base < M_NODES; base += 1024) {
        int i = base + tid;
        int v = (i < M_NODES) ? g_cnt[r * M_NODES + i] : 0;
        sh[tid] = v;
        __syncthreads();
        int carry = sc_carry;
        for (int off = 1; off < 1024; off <<= 1) {
            int t = (tid >= off) ? sh[tid - off] : 0;
            __syncthreads();
            sh[tid] += t;
            __syncthreads();
        }
        if (i < M_NODES) g_cur[r * M_NODES + i] = carry + sh[tid] - v;
        __syncthreads();
        if (tid == 1023) sc_carry = carry + sh[1023];
        __syncthreads();
    }
}

__global__ void fill_kernel(const int* __restrict__ s0, const int* __restrict__ s1,
                            const int* __restrict__ s2, const int* __restrict__ d0,
                            const int* __restrict__ d1, const int* __restrict__ d2) {
    int t = blockIdx.x * blockDim.x + threadIdx.x;
    if (t >= 3 * N_EDGES) return;
    int r = t / N_EDGES, e = t - r * N_EDGES;
    const int* sp = r == 0 ? s0 : (r == 1 ? s1 : s2);
    const int* dp = r == 0 ? d0 : (r == 1 ? d1 : d2);
    int s = __ldg(sp + e);
    int d = __ldg(dp + e);
    int p = atomicAdd(&g_cur[r * M_NODES + d], 1);
    g_sorted[(size_t)r * N_EDGES + p] = s;
}

// ---------------------------------------------------------------------------
// Fused segmented-sum + combine: one warp per (rel, node), fp32 only
//   g_T[r][STEP] = g_T[r][STEP-1] - (sum_seg T[src]*dinv[src]) * dinv[n]
// ---------------------------------------------------------------------------
template <int STEP>
__global__ void __launch_bounds__(256) segsum_kernel() {
    int t = blockIdx.x * blockDim.x + threadIdx.x;
    int w = t >> 5;
    if (w >= 3 * M_NODES) return;
    const int lane = t & 31;
    const int r = w / M_NODES, n = w - r * M_NODES;
    const int rn = r * M_NODES + n;
    const int end = __ldg(&g_cur[rn]);
    const int cnt = __ldg(&g_cnt[rn]);
    int j = end - cnt;
    const int* ss = g_sorted + (size_t)r * N_EDGES;
    const float* f = g_T + (size_t)(r * 3 + STEP - 1) * MH;
    const float* dv = g_dinv3 + r * M_NODES;

    float4 a0 = make_float4(0.f, 0.f, 0.f, 0.f);
    float4 a1 = make_float4(0.f, 0.f, 0.f, 0.f);
    for (; j + 2 <= end; j += 2) {
        int s0 = __ldg(ss + j);
        int s1 = __ldg(ss + j + 1);
        float e0 = __ldg(dv + s0);
        float e1 = __ldg(dv + s1);
        float4 v0 = *(const float4*)(f + (size_t)s0 * H_DIM + lane * 4);
        float4 v1 = *(const float4*)(f + (size_t)s1 * H_DIM + lane * 4);
        a0.x += v0.x * e0; a0.y += v0.y * e0; a0.z += v0.z * e0; a0.w += v0.w * e0;
        a1.x += v1.x * e1; a1.y += v1.y * e1; a1.z += v1.z * e1; a1.w += v1.w * e1;
    }
    if (j < end) {
        int s0 = __ldg(ss + j);
        float e0 = __ldg(dv + s0);
        float4 v0 = *(const float4*)(f + (size_t)s0 * H_DIM + lane * 4);
        a0.x += v0.x * e0; a0.y += v0.y * e0; a0.z += v0.z * e0; a0.w += v0.w * e0;
    }
    float dn = __ldg(dv + n);
    float4 t0 = *(const float4*)(f + (size_t)n * H_DIM + lane * 4);
    float4 o;
    o.x = t0.x - (a0.x + a1.x) * dn;
    o.y = t0.y - (a0.y + a1.y) * dn;
    o.z = t0.z - (a0.z + a1.z) * dn;
    o.w = t0.w - (a0.w + a1.w) * dn;
    *(float4*)(g_T + (size_t)(r * 3 + STEP) * MH + (size_t)n * H_DIM + lane * 4) = o;
}

// ---------------------------------------------------------------------------
// Launch
// ---------------------------------------------------------------------------
extern "C" void kernel_launch(void* const* d_in, const int* in_sizes, int n_in,
                              void* d_out, int out_size) {
    const float* x = (const float*)d_in[0];
    const int *src[3], *dst[3];
    const float *W1[3], *b1[3], *W2[3], *b2[3];
    const float *W3, *b3;

    if (in_sizes[3] == N_EDGES) {
        for (int r = 0; r < 3; r++) {
            src[r] = (const int*)d_in[1 + 2 * r];
            dst[r] = (const int*)d_in[2 + 2 * r];
        }
        for (int r = 0; r < 3; r++) {
            W1[r] = (const float*)d_in[7 + 4 * r];
            b1[r] = (const float*)d_in[8 + 4 * r];
            W2[r] = (const float*)d_in[9 + 4 * r];
            b2[r] = (const float*)d_in[10 + 4 * r];
        }
        W3 = (const float*)d_in[19];
        b3 = (const float*)d_in[20];
    } else {
        for (int r = 0; r < 3; r++) {
            src[r] = (const int*)d_in[1 + 6 * r];
            dst[r] = (const int*)d_in[2 + 6 * r];
            W1[r]  = (const float*)d_in[3 + 6 * r];
            b1[r]  = (const float*)d_in[4 + 6 * r];
            W2[r]  = (const float*)d_in[5 + 6 * r];
            b2[r]  = (const float*)d_in[6 + 6 * r];
        }
        W3 = (const float*)d_in[19];
        b3 = (const float*)d_in[20];
    }

    const int GEMM_X = (M_NODES + 127) / 128;                    // 391
    const int E3     = (3 * N_EDGES + 255) / 256;
    const int NV3    = (3 * M_NODES + 255) / 256;
    const int SEG3   = (int)(((size_t)3 * M_NODES * 32 + 255) / 256);

    // Weight prep
    convW3_kernel<<<(128 * 128 + 255) / 256, 256>>>(W3);
    convW1_kernel<<<(3 * 128 * 256 + 255) / 256, 256>>>(W1[0], W1[1], W1[2]);
    convW2_kernel<<<(3 * 128 * 128 + 255) / 256, 256>>>(W2[0], W2[1], W2[2]);

    // Graph preprocessing
    zero_cnt_kernel<<<NV3, 256>>>();
    deg3_kernel<<<E3, 256>>>(dst[0], dst[1], dst[2]);
    dinv3_kernel<<<NV3, 256>>>();
    scan_kernel<<<3, 1024>>>();
    fill_kernel<<<E3, 256>>>(src[0], src[1], src[2], dst[0], dst[1], dst[2]);

    // MLP (relation-batched, A split in-register)
    {
        dim3 g(GEMM_X, 3);
        mma_gemm<1><<<g, 256>>>(b1[0], b1[1], b1[2], x, nullptr);
        mma_gemm<2><<<g, 256>>>(b2[0], b2[1], b2[2], nullptr, nullptr);
    }

    // Propagation (fused gather + combine, fp32)
    segsum_kernel<1><<<SEG3, 256>>>();
    segsum_kernel<2><<<SEG3, 256>>>();

    // Output projection: K = 9*128, fused bias + leaky -> d_out
    mma_gemm<3><<<GEMM_X, 256>>>(b3, nullptr, nullptr, nullptr, (float*)d_out);
}

// round 7
// speedup vs baseline: 2.7317x; 1.0350x over previous
#include <cuda_runtime.h>
#include <cuda_bf16.h>
#include <cstdint>

#define M_NODES 50000
#define N_EDGES 600000
#define IN_DIM  256
#define H_DIM   128
#define MH ((size_t)M_NODES * H_DIM)

// ---------------------------------------------------------------------------
// Device scratch — activations fp32; hi/lo split in-register
// g_T layout: [3 rel][3 stage][MH]
// ---------------------------------------------------------------------------
__device__ __align__(256) float g_T[9 * MH];
__device__ __align__(256) float g_dinv3[3 * M_NODES];
__device__ __align__(256) int   g_cnt[3 * M_NODES];
__device__ __align__(256) int   g_cur[3 * M_NODES];
__device__ __align__(256) int   g_sorted[(size_t)3 * N_EDGES];

__device__ __align__(256) __nv_bfloat16 g_Bt1h[3 * 128 * 256];
__device__ __align__(256) __nv_bfloat16 g_Bt1l[3 * 128 * 256];
__device__ __align__(256) __nv_bfloat16 g_Bt2h[3 * 128 * 128];
__device__ __align__(256) __nv_bfloat16 g_Bt2l[3 * 128 * 128];
__device__ __align__(256) __nv_bfloat16 g_Bt3h[3 * 128 * 128];
__device__ __align__(256) __nv_bfloat16 g_Bt3l[3 * 128 * 128];

__device__ __forceinline__ float leaky(float v) { return v > 0.0f ? v : 0.01f * v; }

__device__ __forceinline__ uint32_t s2u(const void* p) {
    uint32_t a;
    asm("{ .reg .u64 t; cvta.to.shared.u64 t, %1; cvt.u32.u64 %0, t; }" : "=r"(a) : "l"(p));
    return a;
}
__device__ __forceinline__ void ldm_x4(uint32_t* r, uint32_t addr) {
    asm volatile("ldmatrix.sync.aligned.m8n8.x4.shared.b16 {%0,%1,%2,%3}, [%4];"
                 : "=r"(r[0]), "=r"(r[1]), "=r"(r[2]), "=r"(r[3]) : "r"(addr));
}
__device__ __forceinline__ void mma16816(float* c, const uint32_t* a, const uint32_t* b) {
    asm volatile(
        "mma.sync.aligned.m16n8k16.row.col.f32.bf16.bf16.f32 "
        "{%0,%1,%2,%3}, {%4,%5,%6,%7}, {%8,%9}, {%0,%1,%2,%3};"
        : "+f"(c[0]), "+f"(c[1]), "+f"(c[2]), "+f"(c[3])
        : "r"(a[0]), "r"(a[1]), "r"(a[2]), "r"(a[3]), "r"(b[0]), "r"(b[1]));
}
__device__ __forceinline__ void split2(float x, float y, uint32_t& hi, uint32_t& lo) {
    __nv_bfloat162 h;
    h.x = __float2bfloat16(x);
    h.y = __float2bfloat16(y);
    __nv_bfloat162 l;
    l.x = __float2bfloat16(x - __bfloat162float(h.x));
    l.y = __float2bfloat16(y - __bfloat162float(h.y));
    hi = *(uint32_t*)&h;
    lo = *(uint32_t*)&l;
}

#define SPAD 40    // operand-chunk row stride (halves)
#define H1S  136   // resident h1 tile row stride (halves), conflict-free for ldmatrix

// smem layout (halves) for fused12
#define O_AH 0
#define O_AL (O_AH + 128 * SPAD)
#define O_BH (O_AL + 128 * SPAD)
#define O_BL (O_BH + 128 * SPAD)
#define O_H1H (O_BL + 128 * SPAD)
#define O_H1L (O_H1H + 128 * H1S)
#define SMEM_F12_BYTES ((O_H1L + 128 * H1S) * 2)

// ---------------------------------------------------------------------------
// Fused MLP: per (row-block, rel) CTA:
//   phase A: acc = x @ W1[rel]^T   (K=256, A fp32->hi/lo in-register)
//   phase B: h1 = leaky(acc+b1) -> smem (bf16 hi/lo, resident)
//   phase C: acc = h1 @ W2[rel]^T  (K=128, A frags from resident smem)
//   phase D: g_T[rel][0] = leaky(acc+b2)
// ---------------------------------------------------------------------------
__global__ void __launch_bounds__(256, 1)
fused12_kernel(const float* __restrict__ x,
               const float* __restrict__ b1_0, const float* __restrict__ b1_1,
               const float* __restrict__ b1_2,
               const float* __restrict__ b2_0, const float* __restrict__ b2_1,
               const float* __restrict__ b2_2) {
    extern __shared__ __nv_bfloat16 sm[];
    const int tid = threadIdx.x;
    const int wid = tid >> 5;
    const int lane = tid & 31;
    const int row0 = blockIdx.x * 128;
    const int rel = blockIdx.y;
    const int wm0 = (wid & 1) * 64;
    const int wn0 = (wid >> 1) * 32;

    const float* b1 = rel == 0 ? b1_0 : (rel == 1 ? b1_1 : b1_2);
    const float* b2 = rel == 0 ? b2_0 : (rel == 1 ? b2_1 : b2_2);

    const uint32_t base = s2u(sm);
    const uint32_t uAh = base + O_AH * 2, uAl = base + O_AL * 2;
    const uint32_t uBh = base + O_BH * 2, uBl = base + O_BL * 2;
    const uint32_t uH1h = base + O_H1H * 2, uH1l = base + O_H1L * 2;

    const int a_row = (lane & 7) + ((lane >> 3) & 1) * 8;
    const int a_kof = ((lane >> 4) & 1) * 8;
    const int b_nof = ((lane >> 4) & 1) * 8;
    const int b_kof = ((lane >> 3) & 1) * 8;
    const int b_row = lane & 7;
    const int lr = lane >> 2;
    const int lc = (lane & 3) * 2;

    float acc[4][4][4] = {};

    // ---------------- Phase A: x @ W1^T, K=256 ----------------
    const __nv_bfloat16* B1h = g_Bt1h + rel * 128 * 256;
    const __nv_bfloat16* B1l = g_Bt1l + rel * 128 * 256;
    for (int k0 = 0; k0 < 256; k0 += 32) {
        __syncthreads();
#pragma unroll
        for (int it = 0; it < 2; it++) {
            int i = it * 256 + tid;
            int r = i >> 2, q = (i & 3) * 8;
            int gr = row0 + r;
            float4 f0 = make_float4(0.f, 0.f, 0.f, 0.f);
            float4 f1 = make_float4(0.f, 0.f, 0.f, 0.f);
            if (gr < M_NODES) {
                const float* ap = x + (size_t)gr * 256 + k0 + q;
                f0 = *(const float4*)ap;
                f1 = *(const float4*)(ap + 4);
            }
            uint4 H, L;
            split2(f0.x, f0.y, H.x, L.x);
            split2(f0.z, f0.w, H.y, L.y);
            split2(f1.x, f1.y, H.z, L.z);
            split2(f1.z, f1.w, H.w, L.w);
            *(uint4*)(sm + O_AH + r * SPAD + q) = H;
            *(uint4*)(sm + O_AL + r * SPAD + q) = L;
            *(uint4*)(sm + O_BH + r * SPAD + q) = *(const uint4*)(B1h + (size_t)r * 256 + k0 + q);
            *(uint4*)(sm + O_BL + r * SPAD + q) = *(const uint4*)(B1l + (size_t)r * 256 + k0 + q);
        }
        __syncthreads();
#pragma unroll
        for (int ks = 0; ks < 32; ks += 16) {
            uint32_t ah[4][4], al[4][4], bh[4][2], bl[4][2];
#pragma unroll
            for (int mf = 0; mf < 4; mf++) {
                uint32_t off = ((wm0 + mf * 16 + a_row) * SPAD + ks + a_kof) * 2;
                ldm_x4(ah[mf], uAh + off);
                ldm_x4(al[mf], uAl + off);
            }
#pragma unroll
            for (int nb = 0; nb < 2; nb++) {
                uint32_t off = ((wn0 + nb * 16 + b_nof + b_row) * SPAD + ks + b_kof) * 2;
                uint32_t t[4];
                ldm_x4(t, uBh + off);
                bh[2 * nb][0] = t[0]; bh[2 * nb][1] = t[1];
                bh[2 * nb + 1][0] = t[2]; bh[2 * nb + 1][1] = t[3];
                ldm_x4(t, uBl + off);
                bl[2 * nb][0] = t[0]; bl[2 * nb][1] = t[1];
                bl[2 * nb + 1][0] = t[2]; bl[2 * nb + 1][1] = t[3];
            }
#pragma unroll
            for (int mf = 0; mf < 4; mf++)
#pragma unroll
                for (int nf = 0; nf < 4; nf++) {
                    mma16816(acc[mf][nf], ah[mf], bh[nf]);
                    mma16816(acc[mf][nf], ah[mf], bl[nf]);
                    mma16816(acc[mf][nf], al[mf], bh[nf]);
                }
        }
    }

    // ---------------- Phase B: h1 -> resident smem ----------------
    __syncthreads();   // all MMA reads of sA/sB done (regs hold results)
#pragma unroll
    for (int mf = 0; mf < 4; mf++)
#pragma unroll
        for (int half = 0; half < 2; half++) {
            int row = wm0 + mf * 16 + lr + half * 8;
#pragma unroll
            for (int nf = 0; nf < 4; nf++) {
                int col = wn0 + nf * 8 + lc;
                float v0 = leaky(acc[mf][nf][2 * half]     + __ldg(b1 + col));
                float v1 = leaky(acc[mf][nf][2 * half + 1] + __ldg(b1 + col + 1));
                uint32_t hi, lo;
                split2(v0, v1, hi, lo);
                *(uint32_t*)(sm + O_H1H + row * H1S + col) = hi;
                *(uint32_t*)(sm + O_H1L + row * H1S + col) = lo;
            }
        }

    // reset accumulators
#pragma unroll
    for (int mf = 0; mf < 4; mf++)
#pragma unroll
        for (int nf = 0; nf < 4; nf++)
#pragma unroll
            for (int q = 0; q < 4; q++) acc[mf][nf][q] = 0.f;

    // ---------------- Phase C: h1 @ W2^T, K=128 (A from resident smem) -------
    const __nv_bfloat16* B2h = g_Bt2h + rel * 128 * 128;
    const __nv_bfloat16* B2l = g_Bt2l + rel * 128 * 128;
    for (int k0 = 0; k0 < 128; k0 += 32) {
        __syncthreads();   // also orders phase-B writes before first reads
#pragma unroll
        for (int it = 0; it < 2; it++) {
            int i = it * 256 + tid;
            int r = i >> 2, q = (i & 3) * 8;
            *(uint4*)(sm + O_BH + r * SPAD + q) = *(const uint4*)(B2h + (size_t)r * 128 + k0 + q);
            *(uint4*)(sm + O_BL + r * SPAD + q) = *(const uint4*)(B2l + (size_t)r * 128 + k0 + q);
        }
        __syncthreads();
#pragma unroll
        for (int ks = 0; ks < 32; ks += 16) {
            uint32_t ah[4][4], al[4][4], bh[4][2], bl[4][2];
#pragma unroll
            for (int mf = 0; mf < 4; mf++) {
                uint32_t off = ((wm0 + mf * 16 + a_row) * H1S + k0 + ks + a_kof) * 2;
                ldm_x4(ah[mf], uH1h + off);
                ldm_x4(al[mf], uH1l + off);
            }
#pragma unroll
            for (int nb = 0; nb < 2; nb++) {
                uint32_t off = ((wn0 + nb * 16 + b_nof + b_row) * SPAD + ks + b_kof) * 2;
                uint32_t t[4];
                ldm_x4(t, uBh + off);
                bh[2 * nb][0] = t[0]; bh[2 * nb][1] = t[1];
                bh[2 * nb + 1][0] = t[2]; bh[2 * nb + 1][1] = t[3];
                ldm_x4(t, uBl + off);
                bl[2 * nb][0] = t[0]; bl[2 * nb][1] = t[1];
                bl[2 * nb + 1][0] = t[2]; bl[2 * nb + 1][1] = t[3];
            }
#pragma unroll
            for (int mf = 0; mf < 4; mf++)
#pragma unroll
                for (int nf = 0; nf < 4; nf++) {
                    mma16816(acc[mf][nf], ah[mf], bh[nf]);
                    mma16816(acc[mf][nf], ah[mf], bl[nf]);
                    mma16816(acc[mf][nf], al[mf], bh[nf]);
                }
        }
    }

    // ---------------- Phase D: T0 = leaky(acc + b2) -> global fp32 ----------
    float* T0 = g_T + (size_t)(rel * 3) * MH;
#pragma unroll
    for (int mf = 0; mf < 4; mf++)
#pragma unroll
        for (int half = 0; half < 2; half++) {
            int row = row0 + wm0 + mf * 16 + lr + half * 8;
            if (row >= M_NODES) continue;
#pragma unroll
            for (int nf = 0; nf < 4; nf++) {
                int col = wn0 + nf * 8 + lc;
                float v0 = leaky(acc[mf][nf][2 * half]     + __ldg(b2 + col));
                float v1 = leaky(acc[mf][nf][2 * half + 1] + __ldg(b2 + col + 1));
                *(float2*)(T0 + (size_t)row * H_DIM + col) = make_float2(v0, v1);
            }
        }
}

// ---------------------------------------------------------------------------
// Output GEMM (MODE3 of R6): out = leaky( sum_{r,s} T[r][s] @ W3eff[s]^T + b3 )
// ---------------------------------------------------------------------------
__global__ void __launch_bounds__(256, 1)
mma_gemm3(const float* __restrict__ bias, float* __restrict__ out) {
    __shared__ __nv_bfloat16 sAh[128][SPAD], sAl[128][SPAD];
    __shared__ __nv_bfloat16 sBh[128][SPAD], sBl[128][SPAD];

    const int tid = threadIdx.x;
    const int wid = tid >> 5;
    const int lane = tid & 31;
    const int row0 = blockIdx.x * 128;
    const int wm0 = (wid & 1) * 64;
    const int wn0 = (wid >> 1) * 32;

    const uint32_t uAh = s2u(sAh), uAl = s2u(sAl), uBh = s2u(sBh), uBl = s2u(sBl);

    float acc[4][4][4] = {};

    const int a_row = (lane & 7) + ((lane >> 3) & 1) * 8;
    const int a_kof = ((lane >> 4) & 1) * 8;
    const int b_nof = ((lane >> 4) & 1) * 8;
    const int b_kof = ((lane >> 3) & 1) * 8;
    const int b_row = lane & 7;

    for (int k0 = 0; k0 < 1152; k0 += 32) {
        int c = k0 >> 7;
        int s = c % 3;
        const float* pA = g_T + (size_t)c * MH;
        int ako = k0 & 127;
        const __nv_bfloat16* pBh = g_Bt3h + s * 128 * 128;
        const __nv_bfloat16* pBl = g_Bt3l + s * 128 * 128;
        int bko = k0 & 127;

        __syncthreads();
#pragma unroll
        for (int it = 0; it < 2; it++) {
            int i = it * 256 + tid;
            int r = i >> 2, q = (i & 3) * 8;
            int gr = row0 + r;
            float4 f0 = make_float4(0.f, 0.f, 0.f, 0.f);
            float4 f1 = make_float4(0.f, 0.f, 0.f, 0.f);
            if (gr < M_NODES) {
                const float* ap = pA + (size_t)gr * 128 + ako + q;
                f0 = *(const float4*)ap;
                f1 = *(const float4*)(ap + 4);
            }
            uint4 H, L;
            split2(f0.x, f0.y, H.x, L.x);
            split2(f0.z, f0.w, H.y, L.y);
            split2(f1.x, f1.y, H.z, L.z);
            split2(f1.z, f1.w, H.w, L.w);
            *(uint4*)&sAh[r][q] = H;
            *(uint4*)&sAl[r][q] = L;
            *(uint4*)&sBh[r][q] = *(const uint4*)(pBh + (size_t)r * 128 + bko + q);
            *(uint4*)&sBl[r][q] = *(const uint4*)(pBl + (size_t)r * 128 + bko + q);
        }
        __syncthreads();

#pragma unroll
        for (int ks = 0; ks < 32; ks += 16) {
            uint32_t ah[4][4], al[4][4], bh[4][2], bl[4][2];
#pragma unroll
            for (int mf = 0; mf < 4; mf++) {
                uint32_t off = ((wm0 + mf * 16 + a_row) * SPAD + ks + a_kof) * 2;
                ldm_x4(ah[mf], uAh + off);
                ldm_x4(al[mf], uAl + off);
            }
#pragma unroll
            for (int nb = 0; nb < 2; nb++) {
                uint32_t off = ((wn0 + nb * 16 + b_nof + b_row) * SPAD + ks + b_kof) * 2;
                uint32_t t[4];
                ldm_x4(t, uBh + off);
                bh[2 * nb][0] = t[0]; bh[2 * nb][1] = t[1];
                bh[2 * nb + 1][0] = t[2]; bh[2 * nb + 1][1] = t[3];
                ldm_x4(t, uBl + off);
                bl[2 * nb][0] = t[0]; bl[2 * nb][1] = t[1];
                bl[2 * nb + 1][0] = t[2]; bl[2 * nb + 1][1] = t[3];
            }
#pragma unroll
            for (int mf = 0; mf < 4; mf++)
#pragma unroll
                for (int nf = 0; nf < 4; nf++) {
                    mma16816(acc[mf][nf], ah[mf], bh[nf]);
                    mma16816(acc[mf][nf], ah[mf], bl[nf]);
                    mma16816(acc[mf][nf], al[mf], bh[nf]);
                }
        }
    }

    const int lr = lane >> 2;
    const int lc = (lane & 3) * 2;
#pragma unroll
    for (int mf = 0; mf < 4; mf++)
#pragma unroll
        for (int half = 0; half < 2; half++) {
            int row = row0 + wm0 + mf * 16 + lr + half * 8;
            if (row >= M_NODES) continue;
#pragma unroll
            for (int nf = 0; nf < 4; nf++) {
                int col = wn0 + nf * 8 + lc;
                float v0 = leaky(acc[mf][nf][2 * half]     + __ldg(bias + col));
                float v1 = leaky(acc[mf][nf][2 * half + 1] + __ldg(bias + col + 1));
                *(float2*)(out + (size_t)row * H_DIM + col) = make_float2(v0, v1);
            }
        }
}

// ---------------------------------------------------------------------------
// Merged weight prep: W1 (3x128x256) | W2 (3x128x128) | W3eff (128x128 -> 3)
// ---------------------------------------------------------------------------
#define W1_TOT (3 * 128 * 256)
#define W2_TOT (3 * 128 * 128)
#define W3_TOT (128 * 128)

__global__ void convW_all(const float* __restrict__ W1a, const float* __restrict__ W1b,
                          const float* __restrict__ W1c, const float* __restrict__ W2a,
                          const float* __restrict__ W2b, const float* __restrict__ W2c,
                          const float* __restrict__ W3) {
    int i = blockIdx.x * blockDim.x + threadIdx.x;
    if (i < W1_TOT) {
        int r = i / 32768, rem = i % 32768, n = rem >> 8, k = rem & 255;
        const float* W = r == 0 ? W1a : (r == 1 ? W1b : W1c);
        float v = W[k * H_DIM + n];
        __nv_bfloat16 h = __float2bfloat16(v);
        g_Bt1h[i] = h;
        g_Bt1l[i] = __float2bfloat16(v - __bfloat162float(h));
        return;
    }
    i -= W1_TOT;
    if (i < W2_TOT) {
        int r = i >> 14, rem = i & 16383, n = rem >> 7, k = rem & 127;
        const float* W = r == 0 ? W2a : (r == 1 ? W2b : W2c);
        float v = W[k * H_DIM + n];
        __nv_bfloat16 h = __float2bfloat16(v);
        g_Bt2h[i] = h;
        g_Bt2l[i] = __float2bfloat16(v - __bfloat162float(h));
        return;
    }
    i -= W2_TOT;
    if (i < W3_TOT) {
        int n = i >> 7, k = i & 127;
        float w0 = W3[(0 * 128 + k) * 128 + n];
        float w1 = W3[(1 * 128 + k) * 128 + n];
        float w2 = W3[(2 * 128 + k) * 128 + n];
        float e[3];
        e[0] = 3.0f * w0;
        e[1] = -3.0f * w0 + 3.0f * w1;
        e[2] = 0.75f * w0 - 1.5f * w1 + 0.75f * w2;
#pragma unroll
        for (int s = 0; s < 3; s++) {
            __nv_bfloat16 h = __float2bfloat16(e[s]);
            g_Bt3h[s * 128 * 128 + n * 128 + k] = h;
            g_Bt3l[s * 128 * 128 + n * 128 + k] = __float2bfloat16(e[s] - __bfloat162float(h));
        }
    }
}

// ---------------------------------------------------------------------------
// Graph preprocessing
// ---------------------------------------------------------------------------
__global__ void zero_cnt_kernel() {
    int i = blockIdx.x * blockDim.x + threadIdx.x;
    if (i < 3 * M_NODES) g_cnt[i] = 0;
}
__global__ void deg3_kernel(const int* __restrict__ d0, const int* __restrict__ d1,
                            const int* __restrict__ d2) {
    int t = blockIdx.x * blockDim.x + threadIdx.x;
    if (t >= 3 * N_EDGES) return;
    int r = t / N_EDGES, e = t - r * N_EDGES;
    const int* d = r == 0 ? d0 : (r == 1 ? d1 : d2);
    atomicAdd(&g_cnt[r * M_NODES + __ldg(d + e)], 1);
}

// exclusive scan + dinv in one pass; one block per relation
__global__ void scan_kernel() {
    __shared__ int sh[1024];
    __shared__ int sc_carry;
    const int r = blockIdx.x;
    const int tid = threadIdx.x;
    if (tid == 0) sc_carry = 0;
    __syncthreads();
    for (int base = 0; base < M_NODES; base += 1024) {
        int i = base + tid;
        int v = (i < M_NODES) ? g_cnt[r * M_NODES + i] : 0;
        if (i < M_NODES) g_dinv3[r * M_NODES + i] = rsqrtf(fmaxf((float)v, 1.0f));
        sh[tid] = v;
        __syncthreads();
        int carry = sc_carry;
        for (int off = 1; off < 1024; off <<= 1) {
            int t = (tid >= off) ? sh[tid - off] : 0;
            __syncthreads();
            sh[tid] += t;
            __syncthreads();
        }
        if (i < M_NODES) g_cur[r * M_NODES + i] = carry + sh[tid] - v;
        __syncthreads();
        if (tid == 1023) sc_carry = carry + sh[1023];
        __syncthreads();
    }
}

__global__ void fill_kernel(const int* __restrict__ s0, const int* __restrict__ s1,
                            const int* __restrict__ s2, const int* __restrict__ d0,
                            const int* __restrict__ d1, const int* __restrict__ d2) {
    int t = blockIdx.x * blockDim.x + threadIdx.x;
    if (t >= 3 * N_EDGES) return;
    int r = t / N_EDGES, e = t - r * N_EDGES;
    const int* sp = r == 0 ? s0 : (r == 1 ? s1 : s2);
    const int* dp = r == 0 ? d0 : (r == 1 ? d1 : d2);
    int s = __ldg(sp + e);
    int d = __ldg(dp + e);
    int p = atomicAdd(&g_cur[r * M_NODES + d], 1);
    g_sorted[(size_t)r * N_EDGES + p] = s;
}

// ---------------------------------------------------------------------------
// Fused segmented-sum + combine: one warp per (rel, node), fp32
// ---------------------------------------------------------------------------
template <int STEP>
__global__ void __launch_bounds__(256) segsum_kernel() {
    int t = blockIdx.x * blockDim.x + threadIdx.x;
    int w = t >> 5;
    if (w >= 3 * M_NODES) return;
    const int lane = t & 31;
    const int r = w / M_NODES, n = w - r * M_NODES;
    const int rn = r * M_NODES + n;
    const int end = __ldg(&g_cur[rn]);
    const int cnt = __ldg(&g_cnt[rn]);
    int j = end - cnt;
    const int* ss = g_sorted + (size_t)r * N_EDGES;
    const float* f = g_T + (size_t)(r * 3 + STEP - 1) * MH;
    const float* dv = g_dinv3 + r * M_NODES;

    float4 a0 = make_float4(0.f, 0.f, 0.f, 0.f);
    float4 a1 = make_float4(0.f, 0.f, 0.f, 0.f);
    for (; j + 2 <= end; j += 2) {
        int s0 = __ldg(ss + j);
        int s1 = __ldg(ss + j + 1);
        float e0 = __ldg(dv + s0);
        float e1 = __ldg(dv + s1);
        float4 v0 = *(const float4*)(f + (size_t)s0 * H_DIM + lane * 4);
        float4 v1 = *(const float4*)(f + (size_t)s1 * H_DIM + lane * 4);
        a0.x += v0.x * e0; a0.y += v0.y * e0; a0.z += v0.z * e0; a0.w += v0.w * e0;
        a1.x += v1.x * e1; a1.y += v1.y * e1; a1.z += v1.z * e1; a1.w += v1.w * e1;
    }
    if (j < end) {
        int s0 = __ldg(ss + j);
        float e0 = __ldg(dv + s0);
        float4 v0 = *(const float4*)(f + (size_t)s0 * H_DIM + lane * 4);
        a0.x += v0.x * e0; a0.y += v0.y * e0; a0.z += v0.z * e0; a0.w += v0.w * e0;
    }
    float dn = __ldg(dv + n);
    float4 t0 = *(const float4*)(f + (size_t)n * H_DIM + lane * 4);
    float4 o;
    o.x = t0.x - (a0.x + a1.x) * dn;
    o.y = t0.y - (a0.y + a1.y) * dn;
    o.z = t0.z - (a0.z + a1.z) * dn;
    o.w = t0.w - (a0.w + a1.w) * dn;
    *(float4*)(g_T + (size_t)(r * 3 + STEP) * MH + (size_t)n * H_DIM + lane * 4) = o;
}

// ---------------------------------------------------------------------------
// Launch
// ---------------------------------------------------------------------------
extern "C" void kernel_launch(void* const* d_in, const int* in_sizes, int n_in,
                              void* d_out, int out_size) {
    const float* x = (const float*)d_in[0];
    const int *src[3], *dst[3];
    const float *W1[3], *b1[3], *W2[3], *b2[3];
    const float *W3, *b3;

    if (in_sizes[3] == N_EDGES) {
        for (int r = 0; r < 3; r++) {
            src[r] = (const int*)d_in[1 + 2 * r];
            dst[r] = (const int*)d_in[2 + 2 * r];
        }
        for (int r = 0; r < 3; r++) {
            W1[r] = (const float*)d_in[7 + 4 * r];
            b1[r] = (const float*)d_in[8 + 4 * r];
            W2[r] = (const float*)d_in[9 + 4 * r];
            b2[r] = (const float*)d_in[10 + 4 * r];
        }
        W3 = (const float*)d_in[19];
        b3 = (const float*)d_in[20];
    } else {
        for (int r = 0; r < 3; r++) {
            src[r] = (const int*)d_in[1 + 6 * r];
            dst[r] = (const int*)d_in[2 + 6 * r];
            W1[r]  = (const float*)d_in[3 + 6 * r];
            b1[r]  = (const float*)d_in[4 + 6 * r];
            W2[r]  = (const float*)d_in[5 + 6 * r];
            b2[r]  = (const float*)d_in[6 + 6 * r];
        }
        W3 = (const float*)d_in[19];
        b3 = (const float*)d_in[20];
    }

    cudaFuncSetAttribute(fused12_kernel, cudaFuncAttributeMaxDynamicSharedMemorySize,
                         SMEM_F12_BYTES);

    const int GEMM_X = (M_NODES + 127) / 128;                    // 391
    const int E3     = (3 * N_EDGES + 255) / 256;
    const int NV3    = (3 * M_NODES + 255) / 256;
    const int SEG3   = (int)(((size_t)3 * M_NODES * 32 + 255) / 256);
    const int CW     = (W1_TOT + W2_TOT + W3_TOT + 255) / 256;

    // Prep
    convW_all<<<CW, 256>>>(W1[0], W1[1], W1[2], W2[0], W2[1], W2[2], W3);
    zero_cnt_kernel<<<NV3, 256>>>();
    deg3_kernel<<<E3, 256>>>(dst[0], dst[1], dst[2]);
    scan_kernel<<<3, 1024>>>();
    fill_kernel<<<E3, 256>>>(src[0], src[1], src[2], dst[0], dst[1], dst[2]);

    // Fused 2-layer MLP (relation-batched)
    {
        dim3 g(GEMM_X, 3);
        fused12_kernel<<<g, 256, SMEM_F12_BYTES>>>(x, b1[0], b1[1], b1[2], b2[0], b2[1], b2[2]);
    }

    // Propagation
    segsum_kernel<1><<<SEG3, 256>>>();
    segsum_kernel<2><<<SEG3, 256>>>();

    // Output projection
    mma_gemm3<<<GEMM_X, 256>>>(b3, (float*)d_out);
}

// round 8
// speedup vs baseline: 2.7612x; 1.0108x over previous
#include <cuda_runtime.h>
#include <cuda_bf16.h>
#include <cstdint>

#define M_NODES 50000
#define N_EDGES 600000
#define IN_DIM  256
#define H_DIM   128
#define MH ((size_t)M_NODES * H_DIM)

// ---------------------------------------------------------------------------
// Device scratch — activations fp32; hi/lo split in-register
// g_T layout: [3 rel][3 stage][MH]
// ---------------------------------------------------------------------------
__device__ __align__(256) float g_T[9 * MH];
__device__ __align__(256) float g_dinv3[3 * M_NODES];
__device__ __align__(256) int   g_cnt[3 * M_NODES];
__device__ __align__(256) int   g_cur[3 * M_NODES];
__device__ __align__(256) int   g_sorted[(size_t)3 * N_EDGES];

__device__ __align__(256) __nv_bfloat16 g_Bt1h[3 * 128 * 256];
__device__ __align__(256) __nv_bfloat16 g_Bt1l[3 * 128 * 256];
__device__ __align__(256) __nv_bfloat16 g_Bt2h[3 * 128 * 128];
__device__ __align__(256) __nv_bfloat16 g_Bt2l[3 * 128 * 128];
__device__ __align__(256) __nv_bfloat16 g_Bt3h[3 * 128 * 128];
__device__ __align__(256) __nv_bfloat16 g_Bt3l[3 * 128 * 128];

__device__ __forceinline__ float leaky(float v) { return v > 0.0f ? v : 0.01f * v; }

__device__ __forceinline__ uint32_t s2u(const void* p) {
    uint32_t a;
    asm("{ .reg .u64 t; cvta.to.shared.u64 t, %1; cvt.u32.u64 %0, t; }" : "=r"(a) : "l"(p));
    return a;
}
__device__ __forceinline__ void ldm_x4(uint32_t* r, uint32_t addr) {
    asm volatile("ldmatrix.sync.aligned.m8n8.x4.shared.b16 {%0,%1,%2,%3}, [%4];"
                 : "=r"(r[0]), "=r"(r[1]), "=r"(r[2]), "=r"(r[3]) : "r"(addr));
}
__device__ __forceinline__ void mma16816(float* c, const uint32_t* a, const uint32_t* b) {
    asm volatile(
        "mma.sync.aligned.m16n8k16.row.col.f32.bf16.bf16.f32 "
        "{%0,%1,%2,%3}, {%4,%5,%6,%7}, {%8,%9}, {%0,%1,%2,%3};"
        : "+f"(c[0]), "+f"(c[1]), "+f"(c[2]), "+f"(c[3])
        : "r"(a[0]), "r"(a[1]), "r"(a[2]), "r"(a[3]), "r"(b[0]), "r"(b[1]));
}
__device__ __forceinline__ void split2(float x, float y, uint32_t& hi, uint32_t& lo) {
    __nv_bfloat162 h;
    h.x = __float2bfloat16(x);
    h.y = __float2bfloat16(y);
    __nv_bfloat162 l;
    l.x = __float2bfloat16(x - __bfloat162float(h.x));
    l.y = __float2bfloat16(y - __bfloat162float(h.y));
    hi = *(uint32_t*)&h;
    lo = *(uint32_t*)&l;
}

#define SPAD 40    // operand-chunk row stride (halves)
#define H1S  136   // resident h1 tile row stride (halves)

// smem layout (halves) for fused12
#define O_AH 0
#define O_AL (O_AH + 128 * SPAD)
#define O_BH (O_AL + 128 * SPAD)
#define O_BL (O_BH + 128 * SPAD)
#define O_H1H (O_BL + 128 * SPAD)
#define O_H1L (O_H1H + 128 * H1S)
#define SMEM_F12_BYTES ((O_H1L + 128 * H1S) * 2)

// ---------------------------------------------------------------------------
// Fused MLP: per (row-block, rel) CTA:
//   A: acc = x @ W1[rel]^T (K=256) -> B: h1=leaky(acc+b1) resident in smem
//   C: acc = h1 @ W2[rel]^T (K=128) -> D: g_T[rel][0] = leaky(acc+b2)
// ---------------------------------------------------------------------------
__global__ void __launch_bounds__(256, 1)
fused12_kernel(const float* __restrict__ x,
               const float* __restrict__ b1_0, const float* __restrict__ b1_1,
               const float* __restrict__ b1_2,
               const float* __restrict__ b2_0, const float* __restrict__ b2_1,
               const float* __restrict__ b2_2) {
    extern __shared__ __nv_bfloat16 sm[];
    const int tid = threadIdx.x;
    const int wid = tid >> 5;
    const int lane = tid & 31;
    const int row0 = blockIdx.x * 128;
    const int rel = blockIdx.y;
    const int wm0 = (wid & 1) * 64;
    const int wn0 = (wid >> 1) * 32;

    const float* b1 = rel == 0 ? b1_0 : (rel == 1 ? b1_1 : b1_2);
    const float* b2 = rel == 0 ? b2_0 : (rel == 1 ? b2_1 : b2_2);

    const uint32_t base = s2u(sm);
    const uint32_t uAh = base + O_AH * 2, uAl = base + O_AL * 2;
    const uint32_t uBh = base + O_BH * 2, uBl = base + O_BL * 2;
    const uint32_t uH1h = base + O_H1H * 2, uH1l = base + O_H1L * 2;

    const int a_row = (lane & 7) + ((lane >> 3) & 1) * 8;
    const int a_kof = ((lane >> 4) & 1) * 8;
    const int b_nof = ((lane >> 4) & 1) * 8;
    const int b_kof = ((lane >> 3) & 1) * 8;
    const int b_row = lane & 7;
    const int lr = lane >> 2;
    const int lc = (lane & 3) * 2;

    float acc[4][4][4] = {};

    // Phase A
    const __nv_bfloat16* B1h = g_Bt1h + rel * 128 * 256;
    const __nv_bfloat16* B1l = g_Bt1l + rel * 128 * 256;
    for (int k0 = 0; k0 < 256; k0 += 32) {
        __syncthreads();
#pragma unroll
        for (int it = 0; it < 2; it++) {
            int i = it * 256 + tid;
            int r = i >> 2, q = (i & 3) * 8;
            int gr = row0 + r;
            float4 f0 = make_float4(0.f, 0.f, 0.f, 0.f);
            float4 f1 = make_float4(0.f, 0.f, 0.f, 0.f);
            if (gr < M_NODES) {
                const float* ap = x + (size_t)gr * 256 + k0 + q;
                f0 = *(const float4*)ap;
                f1 = *(const float4*)(ap + 4);
            }
            uint4 H, L;
            split2(f0.x, f0.y, H.x, L.x);
            split2(f0.z, f0.w, H.y, L.y);
            split2(f1.x, f1.y, H.z, L.z);
            split2(f1.z, f1.w, H.w, L.w);
            *(uint4*)(sm + O_AH + r * SPAD + q) = H;
            *(uint4*)(sm + O_AL + r * SPAD + q) = L;
            *(uint4*)(sm + O_BH + r * SPAD + q) = *(const uint4*)(B1h + (size_t)r * 256 + k0 + q);
            *(uint4*)(sm + O_BL + r * SPAD + q) = *(const uint4*)(B1l + (size_t)r * 256 + k0 + q);
        }
        __syncthreads();
#pragma unroll
        for (int ks = 0; ks < 32; ks += 16) {
            uint32_t ah[4][4], al[4][4], bh[4][2], bl[4][2];
#pragma unroll
            for (int mf = 0; mf < 4; mf++) {
                uint32_t off = ((wm0 + mf * 16 + a_row) * SPAD + ks + a_kof) * 2;
                ldm_x4(ah[mf], uAh + off);
                ldm_x4(al[mf], uAl + off);
            }
#pragma unroll
            for (int nb = 0; nb < 2; nb++) {
                uint32_t off = ((wn0 + nb * 16 + b_nof + b_row) * SPAD + ks + b_kof) * 2;
                uint32_t t[4];
                ldm_x4(t, uBh + off);
                bh[2 * nb][0] = t[0]; bh[2 * nb][1] = t[1];
                bh[2 * nb + 1][0] = t[2]; bh[2 * nb + 1][1] = t[3];
                ldm_x4(t, uBl + off);
                bl[2 * nb][0] = t[0]; bl[2 * nb][1] = t[1];
                bl[2 * nb + 1][0] = t[2]; bl[2 * nb + 1][1] = t[3];
            }
#pragma unroll
            for (int mf = 0; mf < 4; mf++)
#pragma unroll
                for (int nf = 0; nf < 4; nf++) {
                    mma16816(acc[mf][nf], ah[mf], bh[nf]);
                    mma16816(acc[mf][nf], ah[mf], bl[nf]);
                    mma16816(acc[mf][nf], al[mf], bh[nf]);
                }
        }
    }

    // Phase B
    __syncthreads();
#pragma unroll
    for (int mf = 0; mf < 4; mf++)
#pragma unroll
        for (int half = 0; half < 2; half++) {
            int row = wm0 + mf * 16 + lr + half * 8;
#pragma unroll
            for (int nf = 0; nf < 4; nf++) {
                int col = wn0 + nf * 8 + lc;
                float v0 = leaky(acc[mf][nf][2 * half]     + __ldg(b1 + col));
                float v1 = leaky(acc[mf][nf][2 * half + 1] + __ldg(b1 + col + 1));
                uint32_t hi, lo;
                split2(v0, v1, hi, lo);
                *(uint32_t*)(sm + O_H1H + row * H1S + col) = hi;
                *(uint32_t*)(sm + O_H1L + row * H1S + col) = lo;
            }
        }

#pragma unroll
    for (int mf = 0; mf < 4; mf++)
#pragma unroll
        for (int nf = 0; nf < 4; nf++)
#pragma unroll
            for (int q = 0; q < 4; q++) acc[mf][nf][q] = 0.f;

    // Phase C
    const __nv_bfloat16* B2h = g_Bt2h + rel * 128 * 128;
    const __nv_bfloat16* B2l = g_Bt2l + rel * 128 * 128;
    for (int k0 = 0; k0 < 128; k0 += 32) {
        __syncthreads();
#pragma unroll
        for (int it = 0; it < 2; it++) {
            int i = it * 256 + tid;
            int r = i >> 2, q = (i & 3) * 8;
            *(uint4*)(sm + O_BH + r * SPAD + q) = *(const uint4*)(B2h + (size_t)r * 128 + k0 + q);
            *(uint4*)(sm + O_BL + r * SPAD + q) = *(const uint4*)(B2l + (size_t)r * 128 + k0 + q);
        }
        __syncthreads();
#pragma unroll
        for (int ks = 0; ks < 32; ks += 16) {
            uint32_t ah[4][4], al[4][4], bh[4][2], bl[4][2];
#pragma unroll
            for (int mf = 0; mf < 4; mf++) {
                uint32_t off = ((wm0 + mf * 16 + a_row) * H1S + k0 + ks + a_kof) * 2;
                ldm_x4(ah[mf], uH1h + off);
                ldm_x4(al[mf], uH1l + off);
            }
#pragma unroll
            for (int nb = 0; nb < 2; nb++) {
                uint32_t off = ((wn0 + nb * 16 + b_nof + b_row) * SPAD + ks + b_kof) * 2;
                uint32_t t[4];
                ldm_x4(t, uBh + off);
                bh[2 * nb][0] = t[0]; bh[2 * nb][1] = t[1];
                bh[2 * nb + 1][0] = t[2]; bh[2 * nb + 1][1] = t[3];
                ldm_x4(t, uBl + off);
                bl[2 * nb][0] = t[0]; bl[2 * nb][1] = t[1];
                bl[2 * nb + 1][0] = t[2]; bl[2 * nb + 1][1] = t[3];
            }
#pragma unroll
            for (int mf = 0; mf < 4; mf++)
#pragma unroll
                for (int nf = 0; nf < 4; nf++) {
                    mma16816(acc[mf][nf], ah[mf], bh[nf]);
                    mma16816(acc[mf][nf], ah[mf], bl[nf]);
                    mma16816(acc[mf][nf], al[mf], bh[nf]);
                }
        }
    }

    // Phase D
    float* T0 = g_T + (size_t)(rel * 3) * MH;
#pragma unroll
    for (int mf = 0; mf < 4; mf++)
#pragma unroll
        for (int half = 0; half < 2; half++) {
            int row = row0 + wm0 + mf * 16 + lr + half * 8;
            if (row >= M_NODES) continue;
#pragma unroll
            for (int nf = 0; nf < 4; nf++) {
                int col = wn0 + nf * 8 + lc;
                float v0 = leaky(acc[mf][nf][2 * half]     + __ldg(b2 + col));
                float v1 = leaky(acc[mf][nf][2 * half + 1] + __ldg(b2 + col + 1));
                *(float2*)(T0 + (size_t)row * H_DIM + col) = make_float2(v0, v1);
            }
        }
}

// ---------------------------------------------------------------------------
// Output GEMM: out = leaky( sum_{r,s} T[r][s] @ W3eff[s]^T + b3 )
// ---------------------------------------------------------------------------
__global__ void __launch_bounds__(256, 1)
mma_gemm3(const float* __restrict__ bias, float* __restrict__ out) {
    __shared__ __nv_bfloat16 sAh[128][SPAD], sAl[128][SPAD];
    __shared__ __nv_bfloat16 sBh[128][SPAD], sBl[128][SPAD];

    const int tid = threadIdx.x;
    const int wid = tid >> 5;
    const int lane = tid & 31;
    const int row0 = blockIdx.x * 128;
    const int wm0 = (wid & 1) * 64;
    const int wn0 = (wid >> 1) * 32;

    const uint32_t uAh = s2u(sAh), uAl = s2u(sAl), uBh = s2u(sBh), uBl = s2u(sBl);

    float acc[4][4][4] = {};

    const int a_row = (lane & 7) + ((lane >> 3) & 1) * 8;
    const int a_kof = ((lane >> 4) & 1) * 8;
    const int b_nof = ((lane >> 4) & 1) * 8;
    const int b_kof = ((lane >> 3) & 1) * 8;
    const int b_row = lane & 7;

    for (int k0 = 0; k0 < 1152; k0 += 32) {
        int c = k0 >> 7;
        int s = c % 3;
        const float* pA = g_T + (size_t)c * MH;
        int ako = k0 & 127;
        const __nv_bfloat16* pBh = g_Bt3h + s * 128 * 128;
        const __nv_bfloat16* pBl = g_Bt3l + s * 128 * 128;
        int bko = k0 & 127;

        __syncthreads();
#pragma unroll
        for (int it = 0; it < 2; it++) {
            int i = it * 256 + tid;
            int r = i >> 2, q = (i & 3) * 8;
            int gr = row0 + r;
            float4 f0 = make_float4(0.f, 0.f, 0.f, 0.f);
            float4 f1 = make_float4(0.f, 0.f, 0.f, 0.f);
            if (gr < M_NODES) {
                const float* ap = pA + (size_t)gr * 128 + ako + q;
                f0 = *(const float4*)ap;
                f1 = *(const float4*)(ap + 4);
            }
            uint4 H, L;
            split2(f0.x, f0.y, H.x, L.x);
            split2(f0.z, f0.w, H.y, L.y);
            split2(f1.x, f1.y, H.z, L.z);
            split2(f1.z, f1.w, H.w, L.w);
            *(uint4*)&sAh[r][q] = H;
            *(uint4*)&sAl[r][q] = L;
            *(uint4*)&sBh[r][q] = *(const uint4*)(pBh + (size_t)r * 128 + bko + q);
            *(uint4*)&sBl[r][q] = *(const uint4*)(pBl + (size_t)r * 128 + bko + q);
        }
        __syncthreads();

#pragma unroll
        for (int ks = 0; ks < 32; ks += 16) {
            uint32_t ah[4][4], al[4][4], bh[4][2], bl[4][2];
#pragma unroll
            for (int mf = 0; mf < 4; mf++) {
                uint32_t off = ((wm0 + mf * 16 + a_row) * SPAD + ks + a_kof) * 2;
                ldm_x4(ah[mf], uAh + off);
                ldm_x4(al[mf], uAl + off);
            }
#pragma unroll
            for (int nb = 0; nb < 2; nb++) {
                uint32_t off = ((wn0 + nb * 16 + b_nof + b_row) * SPAD + ks + b_kof) * 2;
                uint32_t t[4];
                ldm_x4(t, uBh + off);
                bh[2 * nb][0] = t[0]; bh[2 * nb][1] = t[1];
                bh[2 * nb + 1][0] = t[2]; bh[2 * nb + 1][1] = t[3];
                ldm_x4(t, uBl + off);
                bl[2 * nb][0] = t[0]; bl[2 * nb][1] = t[1];
                bl[2 * nb + 1][0] = t[2]; bl[2 * nb + 1][1] = t[3];
            }
#pragma unroll
            for (int mf = 0; mf < 4; mf++)
#pragma unroll
                for (int nf = 0; nf < 4; nf++) {
                    mma16816(acc[mf][nf], ah[mf], bh[nf]);
                    mma16816(acc[mf][nf], ah[mf], bl[nf]);
                    mma16816(acc[mf][nf], al[mf], bh[nf]);
                }
        }
    }

    const int lr = lane >> 2;
    const int lc = (lane & 3) * 2;
#pragma unroll
    for (int mf = 0; mf < 4; mf++)
#pragma unroll
        for (int half = 0; half < 2; half++) {
            int row = row0 + wm0 + mf * 16 + lr + half * 8;
            if (row >= M_NODES) continue;
#pragma unroll
            for (int nf = 0; nf < 4; nf++) {
                int col = wn0 + nf * 8 + lc;
                float v0 = leaky(acc[mf][nf][2 * half]     + __ldg(bias + col));
                float v1 = leaky(acc[mf][nf][2 * half + 1] + __ldg(bias + col + 1));
                *(float2*)(out + (size_t)row * H_DIM + col) = make_float2(v0, v1);
            }
        }
}

// ---------------------------------------------------------------------------
// Merged weight prep
// ---------------------------------------------------------------------------
#define W1_TOT (3 * 128 * 256)
#define W2_TOT (3 * 128 * 128)
#define W3_TOT (128 * 128)

__global__ void convW_all(const float* __restrict__ W1a, const float* __restrict__ W1b,
                          const float* __restrict__ W1c, const float* __restrict__ W2a,
                          const float* __restrict__ W2b, const float* __restrict__ W2c,
                          const float* __restrict__ W3) {
    int i = blockIdx.x * blockDim.x + threadIdx.x;
    if (i < W1_TOT) {
        int r = i / 32768, rem = i % 32768, n = rem >> 8, k = rem & 255;
        const float* W = r == 0 ? W1a : (r == 1 ? W1b : W1c);
        float v = W[k * H_DIM + n];
        __nv_bfloat16 h = __float2bfloat16(v);
        g_Bt1h[i] = h;
        g_Bt1l[i] = __float2bfloat16(v - __bfloat162float(h));
        return;
    }
    i -= W1_TOT;
    if (i < W2_TOT) {
        int r = i >> 14, rem = i & 16383, n = rem >> 7, k = rem & 127;
        const float* W = r == 0 ? W2a : (r == 1 ? W2b : W2c);
        float v = W[k * H_DIM + n];
        __nv_bfloat16 h = __float2bfloat16(v);
        g_Bt2h[i] = h;
        g_Bt2l[i] = __float2bfloat16(v - __bfloat162float(h));
        return;
    }
    i -= W2_TOT;
    if (i < W3_TOT) {
        int n = i >> 7, k = i & 127;
        float w0 = W3[(0 * 128 + k) * 128 + n];
        float w1 = W3[(1 * 128 + k) * 128 + n];
        float w2 = W3[(2 * 128 + k) * 128 + n];
        float e[3];
        e[0] = 3.0f * w0;
        e[1] = -3.0f * w0 + 3.0f * w1;
        e[2] = 0.75f * w0 - 1.5f * w1 + 0.75f * w2;
#pragma unroll
        for (int s = 0; s < 3; s++) {
            __nv_bfloat16 h = __float2bfloat16(e[s]);
            g_Bt3h[s * 128 * 128 + n * 128 + k] = h;
            g_Bt3l[s * 128 * 128 + n * 128 + k] = __float2bfloat16(e[s] - __bfloat162float(h));
        }
    }
}

// ---------------------------------------------------------------------------
// Graph preprocessing
// ---------------------------------------------------------------------------
__global__ void zero_cnt_kernel() {
    int i = blockIdx.x * blockDim.x + threadIdx.x;
    if (i < 3 * M_NODES) g_cnt[i] = 0;
}
__global__ void deg3_kernel(const int* __restrict__ d0, const int* __restrict__ d1,
                            const int* __restrict__ d2) {
    int t = blockIdx.x * blockDim.x + threadIdx.x;
    if (t >= 3 * N_EDGES) return;
    int r = t / N_EDGES, e = t - r * N_EDGES;
    const int* d = r == 0 ? d0 : (r == 1 ? d1 : d2);
    atomicAdd(&g_cnt[r * M_NODES + __ldg(d + e)], 1);
}

// Work-efficient exclusive scan + dinv: one block per relation.
// Each thread serially scans a contiguous chunk; one block-scan over thread sums.
#define SCAN_CH ((M_NODES + 1023) / 1024)   // 49
__global__ void scan_kernel() {
    __shared__ int sh[1024];
    const int r = blockIdx.x;
    const int tid = threadIdx.x;
    const int base = tid * SCAN_CH;

    int lsum = 0;
#pragma unroll 7
    for (int k = 0; k < SCAN_CH; k++) {
        int i = base + k;
        if (i < M_NODES) {
            int v = g_cnt[r * M_NODES + i];
            g_dinv3[r * M_NODES + i] = rsqrtf(fmaxf((float)v, 1.0f));
            lsum += v;
        }
    }
    sh[tid] = lsum;
    __syncthreads();
    // Hillis-Steele inclusive scan over 1024 thread sums (10 steps)
    for (int off = 1; off < 1024; off <<= 1) {
        int t = (tid >= off) ? sh[tid - off] : 0;
        __syncthreads();
        sh[tid] += t;
        __syncthreads();
    }
    int run = sh[tid] - lsum;   // exclusive prefix of this thread's chunk
#pragma unroll 7
    for (int k = 0; k < SCAN_CH; k++) {
        int i = base + k;
        if (i < M_NODES) {
            int v = g_cnt[r * M_NODES + i];
            g_cur[r * M_NODES + i] = run;
            run += v;
        }
    }
}

__global__ void fill_kernel(const int* __restrict__ s0, const int* __restrict__ s1,
                            const int* __restrict__ s2, const int* __restrict__ d0,
                            const int* __restrict__ d1, const int* __restrict__ d2) {
    int t = blockIdx.x * blockDim.x + threadIdx.x;
    if (t >= 3 * N_EDGES) return;
    int r = t / N_EDGES, e = t - r * N_EDGES;
    const int* sp = r == 0 ? s0 : (r == 1 ? s1 : s2);
    const int* dp = r == 0 ? d0 : (r == 1 ? d1 : d2);
    int s = __ldg(sp + e);
    int d = __ldg(dp + e);
    int p = atomicAdd(&g_cur[r * M_NODES + d], 1);
    g_sorted[(size_t)r * N_EDGES + p] = s;
}

// ---------------------------------------------------------------------------
// Fused segmented-sum + combine: one warp per (rel, node), fp32
// Note: after fill, g_cur[rn] == segment END (start + cnt).
// ---------------------------------------------------------------------------
template <int STEP>
__global__ void __launch_bounds__(256) segsum_kernel() {
    int t = blockIdx.x * blockDim.x + threadIdx.x;
    int w = t >> 5;
    if (w >= 3 * M_NODES) return;
    const int lane = t & 31;
    const int r = w / M_NODES, n = w - r * M_NODES;
    const int rn = r * M_NODES + n;
    const int end = __ldg(&g_cur[rn]);
    const int cnt = __ldg(&g_cnt[rn]);
    int j = end - cnt;
    const int* ss = g_sorted + (size_t)r * N_EDGES;
    const float* f = g_T + (size_t)(r * 3 + STEP - 1) * MH;
    const float* dv = g_dinv3 + r * M_NODES;

    float4 a0 = make_float4(0.f, 0.f, 0.f, 0.f);
    float4 a1 = make_float4(0.f, 0.f, 0.f, 0.f);
    for (; j + 2 <= end; j += 2) {
        int s0 = __ldg(ss + j);
        int s1 = __ldg(ss + j + 1);
        float e0 = __ldg(dv + s0);
        float e1 = __ldg(dv + s1);
        float4 v0 = *(const float4*)(f + (size_t)s0 * H_DIM + lane * 4);
        float4 v1 = *(const float4*)(f + (size_t)s1 * H_DIM + lane * 4);
        a0.x += v0.x * e0; a0.y += v0.y * e0; a0.z += v0.z * e0; a0.w += v0.w * e0;
        a1.x += v1.x * e1; a1.y += v1.y * e1; a1.z += v1.z * e1; a1.w += v1.w * e1;
    }
    if (j < end) {
        int s0 = __ldg(ss + j);
        float e0 = __ldg(dv + s0);
        float4 v0 = *(const float4*)(f + (size_t)s0 * H_DIM + lane * 4);
        a0.x += v0.x * e0; a0.y += v0.y * e0; a0.z += v0.z * e0; a0.w += v0.w * e0;
    }
    float dn = __ldg(dv + n);
    float4 t0 = *(const float4*)(f + (size_t)n * H_DIM + lane * 4);
    float4 o;
    o.x = t0.x - (a0.x + a1.x) * dn;
    o.y = t0.y - (a0.y + a1.y) * dn;
    o.z = t0.z - (a0.z + a1.z) * dn;
    o.w = t0.w - (a0.w + a1.w) * dn;
    *(float4*)(g_T + (size_t)(r * 3 + STEP) * MH + (size_t)n * H_DIM + lane * 4) = o;
}

// ---------------------------------------------------------------------------
// Launch
// ---------------------------------------------------------------------------
extern "C" void kernel_launch(void* const* d_in, const int* in_sizes, int n_in,
                              void* d_out, int out_size) {
    const float* x = (const float*)d_in[0];
    const int *src[3], *dst[3];
    const float *W1[3], *b1[3], *W2[3], *b2[3];
    const float *W3, *b3;

    if (in_sizes[3] == N_EDGES) {
        for (int r = 0; r < 3; r++) {
            src[r] = (const int*)d_in[1 + 2 * r];
            dst[r] = (const int*)d_in[2 + 2 * r];
        }
        for (int r = 0; r < 3; r++) {
            W1[r] = (const float*)d_in[7 + 4 * r];
            b1[r] = (const float*)d_in[8 + 4 * r];
            W2[r] = (const float*)d_in[9 + 4 * r];
            b2[r] = (const float*)d_in[10 + 4 * r];
        }
        W3 = (const float*)d_in[19];
        b3 = (const float*)d_in[20];
    } else {
        for (int r = 0; r < 3; r++) {
            src[r] = (const int*)d_in[1 + 6 * r];
            dst[r] = (const int*)d_in[2 + 6 * r];
            W1[r]  = (const float*)d_in[3 + 6 * r];
            b1[r]  = (const float*)d_in[4 + 6 * r];
            W2[r]  = (const float*)d_in[5 + 6 * r];
            b2[r]  = (const float*)d_in[6 + 6 * r];
        }
        W3 = (const float*)d_in[19];
        b3 = (const float*)d_in[20];
    }

    cudaFuncSetAttribute(fused12_kernel, cudaFuncAttributeMaxDynamicSharedMemorySize,
                         SMEM_F12_BYTES);

    const int GEMM_X = (M_NODES + 127) / 128;                    // 391
    const int E3     = (3 * N_EDGES + 255) / 256;
    const int NV3    = (3 * M_NODES + 255) / 256;
    const int SEG3   = (int)(((size_t)3 * M_NODES * 32 + 255) / 256);
    const int CW     = (W1_TOT + W2_TOT + W3_TOT + 255) / 256;

    // Prep
    convW_all<<<CW, 256>>>(W1[0], W1[1], W1[2], W2[0], W2[1], W2[2], W3);
    zero_cnt_kernel<<<NV3, 256>>>();
    deg3_kernel<<<E3, 256>>>(dst[0], dst[1], dst[2]);
    scan_kernel<<<3, 1024>>>();
    fill_kernel<<<E3, 256>>>(src[0], src[1], src[2], dst[0], dst[1], dst[2]);

    // Fused 2-layer MLP (relation-batched)
    {
        dim3 g(GEMM_X, 3);
        fused12_kernel<<<g, 256, SMEM_F12_BYTES>>>(x, b1[0], b1[1], b1[2], b2[0], b2[1], b2[2]);
    }

    // Propagation
    segsum_kernel<1><<<SEG3, 256>>>();
    segsum_kernel<2><<<SEG3, 256>>>();

    // Output projection
    mma_gemm3<<<GEMM_X, 256>>>(b3, (float*)d_out);
}

// round 10
// speedup vs baseline: 2.8810x; 1.0434x over previous
#include <cuda_runtime.h>
#include <cuda_bf16.h>
#include <cstdint>

#define M_NODES 50000
#define N_EDGES 600000
#define IN_DIM  256
#define H_DIM   128
#define MH ((size_t)M_NODES * H_DIM)

// ---------------------------------------------------------------------------
// Device scratch — activations fp32; hi/lo split in-register
// g_T layout: [3 rel][3 stage][MH]
// ---------------------------------------------------------------------------
__device__ __align__(256) float g_T[9 * MH];
__device__ __align__(256) float g_dinv3[3 * M_NODES];
__device__ __align__(256) int   g_cnt[3 * M_NODES];
__device__ __align__(256) int   g_cur[3 * M_NODES];
__device__ __align__(256) int   g_sorted[(size_t)3 * N_EDGES];

__device__ __align__(256) __nv_bfloat16 g_Bt1h[3 * 128 * 256];
__device__ __align__(256) __nv_bfloat16 g_Bt1l[3 * 128 * 256];
__device__ __align__(256) __nv_bfloat16 g_Bt2h[3 * 128 * 128];
__device__ __align__(256) __nv_bfloat16 g_Bt2l[3 * 128 * 128];
__device__ __align__(256) __nv_bfloat16 g_Bt3h[3 * 128 * 128];
__device__ __align__(256) __nv_bfloat16 g_Bt3l[3 * 128 * 128];

__device__ __forceinline__ float leaky(float v) { return v > 0.0f ? v : 0.01f * v; }

__device__ __forceinline__ uint32_t s2u(const void* p) {
    uint32_t a;
    asm("{ .reg .u64 t; cvta.to.shared.u64 t, %1; cvt.u32.u64 %0, t; }" : "=r"(a) : "l"(p));
    return a;
}
__device__ __forceinline__ void ldm_x4(uint32_t* r, uint32_t addr) {
    asm volatile("ldmatrix.sync.aligned.m8n8.x4.shared.b16 {%0,%1,%2,%3}, [%4];"
                 : "=r"(r[0]), "=r"(r[1]), "=r"(r[2]), "=r"(r[3]) : "r"(addr));
}
__device__ __forceinline__ void mma16816(float* c, const uint32_t* a, const uint32_t* b) {
    asm volatile(
        "mma.sync.aligned.m16n8k16.row.col.f32.bf16.bf16.f32 "
        "{%0,%1,%2,%3}, {%4,%5,%6,%7}, {%8,%9}, {%0,%1,%2,%3};"
        : "+f"(c[0]), "+f"(c[1]), "+f"(c[2]), "+f"(c[3])
        : "r"(a[0]), "r"(a[1]), "r"(a[2]), "r"(a[3]), "r"(b[0]), "r"(b[1]));
}
__device__ __forceinline__ void split2(float x, float y, uint32_t& hi, uint32_t& lo) {
    __nv_bfloat162 h;
    h.x = __float2bfloat16(x);
    h.y = __float2bfloat16(y);
    __nv_bfloat162 l;
    l.x = __float2bfloat16(x - __bfloat162float(h.x));
    l.y = __float2bfloat16(y - __bfloat162float(h.y));
    hi = *(uint32_t*)&h;
    lo = *(uint32_t*)&l;
}

#define SPAD 40    // operand-chunk row stride (halves)
#define H1S  136   // resident h1 tile row stride (halves)

// smem layout (halves) for fused12
#define O_AH 0
#define O_AL (O_AH + 128 * SPAD)
#define O_BH (O_AL + 128 * SPAD)
#define O_BL (O_BH + 128 * SPAD)
#define O_H1H (O_BL + 128 * SPAD)
#define O_H1L (O_H1H + 128 * H1S)
#define SMEM_F12_BYTES ((O_H1L + 128 * H1S) * 2)

// ---------------------------------------------------------------------------
// Fused MLP: per (row-block, rel) CTA:
//   A: acc = x @ W1[rel]^T (K=256) -> B: h1=leaky(acc+b1) resident in smem
//   C: acc = h1 @ W2[rel]^T (K=128) -> D: g_T[rel][0] = leaky(acc+b2)
// ---------------------------------------------------------------------------
__global__ void __launch_bounds__(256, 1)
fused12_kernel(const float* __restrict__ x,
               const float* __restrict__ b1_0, const float* __restrict__ b1_1,
               const float* __restrict__ b1_2,
               const float* __restrict__ b2_0, const float* __restrict__ b2_1,
               const float* __restrict__ b2_2) {
    extern __shared__ __nv_bfloat16 sm[];
    const int tid = threadIdx.x;
    const int wid = tid >> 5;
    const int lane = tid & 31;
    const int row0 = blockIdx.x * 128;
    const int rel = blockIdx.y;
    const int wm0 = (wid & 1) * 64;
    const int wn0 = (wid >> 1) * 32;

    const float* b1 = rel == 0 ? b1_0 : (rel == 1 ? b1_1 : b1_2);
    const float* b2 = rel == 0 ? b2_0 : (rel == 1 ? b2_1 : b2_2);

    const uint32_t base = s2u(sm);
    const uint32_t uAh = base + O_AH * 2, uAl = base + O_AL * 2;
    const uint32_t uBh = base + O_BH * 2, uBl = base + O_BL * 2;
    const uint32_t uH1h = base + O_H1H * 2, uH1l = base + O_H1L * 2;

    const int a_row = (lane & 7) + ((lane >> 3) & 1) * 8;
    const int a_kof = ((lane >> 4) & 1) * 8;
    const int b_nof = ((lane >> 4) & 1) * 8;
    const int b_kof = ((lane >> 3) & 1) * 8;
    const int b_row = lane & 7;
    const int lr = lane >> 2;
    const int lc = (lane & 3) * 2;

    float acc[4][4][4] = {};

    // Phase A
    const __nv_bfloat16* B1h = g_Bt1h + rel * 128 * 256;
    const __nv_bfloat16* B1l = g_Bt1l + rel * 128 * 256;
    for (int k0 = 0; k0 < 256; k0 += 32) {
        __syncthreads();
#pragma unroll
        for (int it = 0; it < 2; it++) {
            int i = it * 256 + tid;
            int r = i >> 2, q = (i & 3) * 8;
            int gr = row0 + r;
            float4 f0 = make_float4(0.f, 0.f, 0.f, 0.f);
            float4 f1 = make_float4(0.f, 0.f, 0.f, 0.f);
            if (gr < M_NODES) {
                const float* ap = x + (size_t)gr * 256 + k0 + q;
                f0 = *(const float4*)ap;
                f1 = *(const float4*)(ap + 4);
            }
            uint4 H, L;
            split2(f0.x, f0.y, H.x, L.x);
            split2(f0.z, f0.w, H.y, L.y);
            split2(f1.x, f1.y, H.z, L.z);
            split2(f1.z, f1.w, H.w, L.w);
            *(uint4*)(sm + O_AH + r * SPAD + q) = H;
            *(uint4*)(sm + O_AL + r * SPAD + q) = L;
            *(uint4*)(sm + O_BH + r * SPAD + q) = *(const uint4*)(B1h + (size_t)r * 256 + k0 + q);
            *(uint4*)(sm + O_BL + r * SPAD + q) = *(const uint4*)(B1l + (size_t)r * 256 + k0 + q);
        }
        __syncthreads();
#pragma unroll
        for (int ks = 0; ks < 32; ks += 16) {
            uint32_t ah[4][4], al[4][4], bh[4][2], bl[4][2];
#pragma unroll
            for (int mf = 0; mf < 4; mf++) {
                uint32_t off = ((wm0 + mf * 16 + a_row) * SPAD + ks + a_kof) * 2;
                ldm_x4(ah[mf], uAh + off);
                ldm_x4(al[mf], uAl + off);
            }
#pragma unroll
            for (int nb = 0; nb < 2; nb++) {
                uint32_t off = ((wn0 + nb * 16 + b_nof + b_row) * SPAD + ks + b_kof) * 2;
                uint32_t t[4];
                ldm_x4(t, uBh + off);
                bh[2 * nb][0] = t[0]; bh[2 * nb][1] = t[1];
                bh[2 * nb + 1][0] = t[2]; bh[2 * nb + 1][1] = t[3];
                ldm_x4(t, uBl + off);
                bl[2 * nb][0] = t[0]; bl[2 * nb][1] = t[1];
                bl[2 * nb + 1][0] = t[2]; bl[2 * nb + 1][1] = t[3];
            }
#pragma unroll
            for (int mf = 0; mf < 4; mf++)
#pragma unroll
                for (int nf = 0; nf < 4; nf++) {
                    mma16816(acc[mf][nf], ah[mf], bh[nf]);
                    mma16816(acc[mf][nf], ah[mf], bl[nf]);
                    mma16816(acc[mf][nf], al[mf], bh[nf]);
                }
        }
    }

    // Phase B
    __syncthreads();
#pragma unroll
    for (int mf = 0; mf < 4; mf++)
#pragma unroll
        for (int half = 0; half < 2; half++) {
            int row = wm0 + mf * 16 + lr + half * 8;
#pragma unroll
            for (int nf = 0; nf < 4; nf++) {
                int col = wn0 + nf * 8 + lc;
                float v0 = leaky(acc[mf][nf][2 * half]     + __ldg(b1 + col));
                float v1 = leaky(acc[mf][nf][2 * half + 1] + __ldg(b1 + col + 1));
                uint32_t hi, lo;
                split2(v0, v1, hi, lo);
                *(uint32_t*)(sm + O_H1H + row * H1S + col) = hi;
                *(uint32_t*)(sm + O_H1L + row * H1S + col) = lo;
            }
        }

#pragma unroll
    for (int mf = 0; mf < 4; mf++)
#pragma unroll
        for (int nf = 0; nf < 4; nf++)
#pragma unroll
            for (int q = 0; q < 4; q++) acc[mf][nf][q] = 0.f;

    // Phase C
    const __nv_bfloat16* B2h = g_Bt2h + rel * 128 * 128;
    const __nv_bfloat16* B2l = g_Bt2l + rel * 128 * 128;
    for (int k0 = 0; k0 < 128; k0 += 32) {
        __syncthreads();
#pragma unroll
        for (int it = 0; it < 2; it++) {
            int i = it * 256 + tid;
            int r = i >> 2, q = (i & 3) * 8;
            *(uint4*)(sm + O_BH + r * SPAD + q) = *(const uint4*)(B2h + (size_t)r * 128 + k0 + q);
            *(uint4*)(sm + O_BL + r * SPAD + q) = *(const uint4*)(B2l + (size_t)r * 128 + k0 + q);
        }
        __syncthreads();
#pragma unroll
        for (int ks = 0; ks < 32; ks += 16) {
            uint32_t ah[4][4], al[4][4], bh[4][2], bl[4][2];
#pragma unroll
            for (int mf = 0; mf < 4; mf++) {
                uint32_t off = ((wm0 + mf * 16 + a_row) * H1S + k0 + ks + a_kof) * 2;
                ldm_x4(ah[mf], uH1h + off);
                ldm_x4(al[mf], uH1l + off);
            }
#pragma unroll
            for (int nb = 0; nb < 2; nb++) {
                uint32_t off = ((wn0 + nb * 16 + b_nof + b_row) * SPAD + ks + b_kof) * 2;
                uint32_t t[4];
                ldm_x4(t, uBh + off);
                bh[2 * nb][0] = t[0]; bh[2 * nb][1] = t[1];
                bh[2 * nb + 1][0] = t[2]; bh[2 * nb + 1][1] = t[3];
                ldm_x4(t, uBl + off);
                bl[2 * nb][0] = t[0]; bl[2 * nb][1] = t[1];
                bl[2 * nb + 1][0] = t[2]; bl[2 * nb + 1][1] = t[3];
            }
#pragma unroll
            for (int mf = 0; mf < 4; mf++)
#pragma unroll
                for (int nf = 0; nf < 4; nf++) {
                    mma16816(acc[mf][nf], ah[mf], bh[nf]);
                    mma16816(acc[mf][nf], ah[mf], bl[nf]);
                    mma16816(acc[mf][nf], al[mf], bh[nf]);
                }
        }
    }

    // Phase D
    float* T0 = g_T + (size_t)(rel * 3) * MH;
#pragma unroll
    for (int mf = 0; mf < 4; mf++)
#pragma unroll
        for (int half = 0; half < 2; half++) {
            int row = row0 + wm0 + mf * 16 + lr + half * 8;
            if (row >= M_NODES) continue;
#pragma unroll
            for (int nf = 0; nf < 4; nf++) {
                int col = wn0 + nf * 8 + lc;
                float v0 = leaky(acc[mf][nf][2 * half]     + __ldg(b2 + col));
                float v1 = leaky(acc[mf][nf][2 * half + 1] + __ldg(b2 + col + 1));
                *(float2*)(T0 + (size_t)row * H_DIM + col) = make_float2(v0, v1);
            }
        }
}

// ---------------------------------------------------------------------------
// Output GEMM: out = leaky( sum_{r,s} T[r][s] @ W3eff[s]^T + b3 )
// ---------------------------------------------------------------------------
__global__ void __launch_bounds__(256, 1)
mma_gemm3(const float* __restrict__ bias, float* __restrict__ out) {
    __shared__ __nv_bfloat16 sAh[128][SPAD], sAl[128][SPAD];
    __shared__ __nv_bfloat16 sBh[128][SPAD], sBl[128][SPAD];

    const int tid = threadIdx.x;
    const int wid = tid >> 5;
    const int lane = tid & 31;
    const int row0 = blockIdx.x * 128;
    const int wm0 = (wid & 1) * 64;
    const int wn0 = (wid >> 1) * 32;

    const uint32_t uAh = s2u(sAh), uAl = s2u(sAl), uBh = s2u(sBh), uBl = s2u(sBl);

    float acc[4][4][4] = {};

    const int a_row = (lane & 7) + ((lane >> 3) & 1) * 8;
    const int a_kof = ((lane >> 4) & 1) * 8;
    const int b_nof = ((lane >> 4) & 1) * 8;
    const int b_kof = ((lane >> 3) & 1) * 8;
    const int b_row = lane & 7;

    for (int k0 = 0; k0 < 1152; k0 += 32) {
        int c = k0 >> 7;
        int s = c % 3;
        const float* pA = g_T + (size_t)c * MH;
        int ako = k0 & 127;
        const __nv_bfloat16* pBh = g_Bt3h + s * 128 * 128;
        const __nv_bfloat16* pBl = g_Bt3l + s * 128 * 128;
        int bko = k0 & 127;

        __syncthreads();
#pragma unroll
        for (int it = 0; it < 2; it++) {
            int i = it * 256 + tid;
            int r = i >> 2, q = (i & 3) * 8;
            int gr = row0 + r;
            float4 f0 = make_float4(0.f, 0.f, 0.f, 0.f);
            float4 f1 = make_float4(0.f, 0.f, 0.f, 0.f);
            if (gr < M_NODES) {
                const float* ap = pA + (size_t)gr * 128 + ako + q;
                f0 = *(const float4*)ap;
                f1 = *(const float4*)(ap + 4);
            }
            uint4 H, L;
            split2(f0.x, f0.y, H.x, L.x);
            split2(f0.z, f0.w, H.y, L.y);
            split2(f1.x, f1.y, H.z, L.z);
            split2(f1.z, f1.w, H.w, L.w);
            *(uint4*)&sAh[r][q] = H;
            *(uint4*)&sAl[r][q] = L;
            *(uint4*)&sBh[r][q] = *(const uint4*)(pBh + (size_t)r * 128 + bko + q);
            *(uint4*)&sBl[r][q] = *(const uint4*)(pBl + (size_t)r * 128 + bko + q);
        }
        __syncthreads();

#pragma unroll
        for (int ks = 0; ks < 32; ks += 16) {
            uint32_t ah[4][4], al[4][4], bh[4][2], bl[4][2];
#pragma unroll
            for (int mf = 0; mf < 4; mf++) {
                uint32_t off = ((wm0 + mf * 16 + a_row) * SPAD + ks + a_kof) * 2;
                ldm_x4(ah[mf], uAh + off);
                ldm_x4(al[mf], uAl + off);
            }
#pragma unroll
            for (int nb = 0; nb < 2; nb++) {
                uint32_t off = ((wn0 + nb * 16 + b_nof + b_row) * SPAD + ks + b_kof) * 2;
                uint32_t t[4];
                ldm_x4(t, uBh + off);
                bh[2 * nb][0] = t[0]; bh[2 * nb][1] = t[1];
                bh[2 * nb + 1][0] = t[2]; bh[2 * nb + 1][1] = t[3];
                ldm_x4(t, uBl + off);
                bl[2 * nb][0] = t[0]; bl[2 * nb][1] = t[1];
                bl[2 * nb + 1][0] = t[2]; bl[2 * nb + 1][1] = t[3];
            }
#pragma unroll
            for (int mf = 0; mf < 4; mf++)
#pragma unroll
                for (int nf = 0; nf < 4; nf++) {
                    mma16816(acc[mf][nf], ah[mf], bh[nf]);
                    mma16816(acc[mf][nf], ah[mf], bl[nf]);
                    mma16816(acc[mf][nf], al[mf], bh[nf]);
                }
        }
    }

    const int lr = lane >> 2;
    const int lc = (lane & 3) * 2;
#pragma unroll
    for (int mf = 0; mf < 4; mf++)
#pragma unroll
        for (int half = 0; half < 2; half++) {
            int row = row0 + wm0 + mf * 16 + lr + half * 8;
            if (row >= M_NODES) continue;
#pragma unroll
            for (int nf = 0; nf < 4; nf++) {
                int col = wn0 + nf * 8 + lc;
                float v0 = leaky(acc[mf][nf][2 * half]     + __ldg(bias + col));
                float v1 = leaky(acc[mf][nf][2 * half + 1] + __ldg(bias + col + 1));
                *(float2*)(out + (size_t)row * H_DIM + col) = make_float2(v0, v1);
            }
        }
}

// ---------------------------------------------------------------------------
// Merged weight prep
// ---------------------------------------------------------------------------
#define W1_TOT (3 * 128 * 256)
#define W2_TOT (3 * 128 * 128)
#define W3_TOT (128 * 128)

__global__ void convW_all(const float* __restrict__ W1a, const float* __restrict__ W1b,
                          const float* __restrict__ W1c, const float* __restrict__ W2a,
                          const float* __restrict__ W2b, const float* __restrict__ W2c,
                          const float* __restrict__ W3) {
    int i = blockIdx.x * blockDim.x + threadIdx.x;
    if (i < W1_TOT) {
        int r = i / 32768, rem = i % 32768, n = rem >> 8, k = rem & 255;
        const float* W = r == 0 ? W1a : (r == 1 ? W1b : W1c);
        float v = W[k * H_DIM + n];
        __nv_bfloat16 h = __float2bfloat16(v);
        g_Bt1h[i] = h;
        g_Bt1l[i] = __float2bfloat16(v - __bfloat162float(h));
        return;
    }
    i -= W1_TOT;
    if (i < W2_TOT) {
        int r = i >> 14, rem = i & 16383, n = rem >> 7, k = rem & 127;
        const float* W = r == 0 ? W2a : (r == 1 ? W2b : W2c);
        float v = W[k * H_DIM + n];
        __nv_bfloat16 h = __float2bfloat16(v);
        g_Bt2h[i] = h;
        g_Bt2l[i] = __float2bfloat16(v - __bfloat162float(h));
        return;
    }
    i -= W2_TOT;
    if (i < W3_TOT) {
        int n = i >> 7, k = i & 127;
        float w0 = W3[(0 * 128 + k) * 128 + n];
        float w1 = W3[(1 * 128 + k) * 128 + n];
        float w2 = W3[(2 * 128 + k) * 128 + n];
        float e[3];
        e[0] = 3.0f * w0;
        e[1] = -3.0f * w0 + 3.0f * w1;
        e[2] = 0.75f * w0 - 1.5f * w1 + 0.75f * w2;
#pragma unroll
        for (int s = 0; s < 3; s++) {
            __nv_bfloat16 h = __float2bfloat16(e[s]);
            g_Bt3h[s * 128 * 128 + n * 128 + k] = h;
            g_Bt3l[s * 128 * 128 + n * 128 + k] = __float2bfloat16(e[s] - __bfloat162float(h));
        }
    }
}

// ---------------------------------------------------------------------------
// Graph preprocessing
// ---------------------------------------------------------------------------
__global__ void zero_cnt_kernel() {
    int i = blockIdx.x * blockDim.x + threadIdx.x;
    if (i < 3 * M_NODES) g_cnt[i] = 0;
}
__global__ void deg3_kernel(const int* __restrict__ d0, const int* __restrict__ d1,
                            const int* __restrict__ d2) {
    int t = blockIdx.x * blockDim.x + threadIdx.x;
    if (t >= 3 * N_EDGES) return;
    int r = t / N_EDGES, e = t - r * N_EDGES;
    const int* d = r == 0 ? d0 : (r == 1 ? d1 : d2);
    atomicAdd(&g_cnt[r * M_NODES + __ldg(d + e)], 1);
}

// Coalesced tiled scan + dinv: one block per relation.
// Per 1024-tile: coalesced load, warp shfl-scan, warp-sum scan, carry.
__global__ void scan_kernel() {
    __shared__ int warp_sums[32];
    __shared__ int s_carry;
    const int r = blockIdx.x;
    const int tid = threadIdx.x;
    const int lane = tid & 31;
    const int wid = tid >> 5;
    if (tid == 0) s_carry = 0;
    __syncthreads();

    for (int base = 0; base < M_NODES; base += 1024) {
        int i = base + tid;
        int v = (i < M_NODES) ? g_cnt[r * M_NODES + i] : 0;
        if (i < M_NODES) g_dinv3[r * M_NODES + i] = rsqrtf(fmaxf((float)v, 1.0f));

        // warp inclusive scan
        int x = v;
#pragma unroll
        for (int o = 1; o < 32; o <<= 1) {
            int y = __shfl_up_sync(0xFFFFFFFFu, x, o);
            if (lane >= o) x += y;
        }
        if (lane == 31) warp_sums[wid] = x;
        __syncthreads();
        if (wid == 0) {
            int w = warp_sums[lane];
#pragma unroll
            for (int o = 1; o < 32; o <<= 1) {
                int y = __shfl_up_sync(0xFFFFFFFFu, w, o);
                if (lane >= o) w += y;
            }
            warp_sums[lane] = w;
        }
        __syncthreads();
        int carry = s_carry;
        int woff = (wid > 0) ? warp_sums[wid - 1] : 0;
        if (i < M_NODES) g_cur[r * M_NODES + i] = carry + woff + x - v;
        int total = warp_sums[31];
        __syncthreads();
        if (tid == 0) s_carry = carry + total;
    }
}

__global__ void fill_kernel(const int* __restrict__ s0, const int* __restrict__ s1,
                            const int* __restrict__ s2, const int* __restrict__ d0,
                            const int* __restrict__ d1, const int* __restrict__ d2) {
    int t = blockIdx.x * blockDim.x + threadIdx.x;
    if (t >= 3 * N_EDGES) return;
    int r = t / N_EDGES, e = t - r * N_EDGES;
    const int* sp = r == 0 ? s0 : (r == 1 ? s1 : s2);
    const int* dp = r == 0 ? d0 : (r == 1 ? d1 : d2);
    int s = __ldg(sp + e);
    int d = __ldg(dp + e);
    int p = atomicAdd(&g_cur[r * M_NODES + d], 1);
    g_sorted[(size_t)r * N_EDGES + p] = s;
}

// ---------------------------------------------------------------------------
// Fused segmented-sum + combine: one warp per (rel, node), fp32
// After fill, g_cur[rn] == segment END (start + cnt).
// ---------------------------------------------------------------------------
template <int STEP>
__global__ void __launch_bounds__(256) segsum_kernel() {
    int t = blockIdx.x * blockDim.x + threadIdx.x;
    int w = t >> 5;
    if (w >= 3 * M_NODES) return;
    const int lane = t & 31;
    const int r = w / M_NODES, n = w - r * M_NODES;
    const int rn = r * M_NODES + n;
    const int end = __ldg(&g_cur[rn]);
    const int cnt = __ldg(&g_cnt[rn]);
    int j = end - cnt;
    const int* ss = g_sorted + (size_t)r * N_EDGES;
    const float* f = g_T + (size_t)(r * 3 + STEP - 1) * MH;
    const float* dv = g_dinv3 + r * M_NODES;

    float4 a0 = make_float4(0.f, 0.f, 0.f, 0.f);
    float4 a1 = make_float4(0.f, 0.f, 0.f, 0.f);
    for (; j + 2 <= end; j += 2) {
        int s0 = __ldg(ss + j);
        int s1 = __ldg(ss + j + 1);
        float e0 = __ldg(dv + s0);
        float e1 = __ldg(dv + s1);
        float4 v0 = *(const float4*)(f + (size_t)s0 * H_DIM + lane * 4);
        float4 v1 = *(const float4*)(f + (size_t)s1 * H_DIM + lane * 4);
        a0.x += v0.x * e0; a0.y += v0.y * e0; a0.z += v0.z * e0; a0.w += v0.w * e0;
        a1.x += v1.x * e1; a1.y += v1.y * e1; a1.z += v1.z * e1; a1.w += v1.w * e1;
    }
    if (j < end) {
        int s0 = __ldg(ss + j);
        float e0 = __ldg(dv + s0);
        float4 v0 = *(const float4*)(f + (size_t)s0 * H_DIM + lane * 4);
        a0.x += v0.x * e0; a0.y += v0.y * e0; a0.z += v0.z * e0; a0.w += v0.w * e0;
    }
    float dn = __ldg(dv + n);
    float4 t0 = *(const float4*)(f + (size_t)n * H_DIM + lane * 4);
    float4 o;
    o.x = t0.x - (a0.x + a1.x) * dn;
    o.y = t0.y - (a0.y + a1.y) * dn;
    o.z = t0.z - (a0.z + a1.z) * dn;
    o.w = t0.w - (a0.w + a1.w) * dn;
    *(float4*)(g_T + (size_t)(r * 3 + STEP) * MH + (size_t)n * H_DIM + lane * 4) = o;
}

// ---------------------------------------------------------------------------
// Launch
// ---------------------------------------------------------------------------
extern "C" void kernel_launch(void* const* d_in, const int* in_sizes, int n_in,
                              void* d_out, int out_size) {
    const float* x = (const float*)d_in[0];
    const int *src[3], *dst[3];
    const float *W1[3], *b1[3], *W2[3], *b2[3];
    const float *W3, *b3;

    if (in_sizes[3] == N_EDGES) {
        for (int r = 0; r < 3; r++) {
            src[r] = (const int*)d_in[1 + 2 * r];
            dst[r] = (const int*)d_in[2 + 2 * r];
        }
        for (int r = 0; r < 3; r++) {
            W1[r] = (const float*)d_in[7 + 4 * r];
            b1[r] = (const float*)d_in[8 + 4 * r];
            W2[r] = (const float*)d_in[9 + 4 * r];
            b2[r] = (const float*)d_in[10 + 4 * r];
        }
        W3 = (const float*)d_in[19];
        b3 = (const float*)d_in[20];
    } else {
        for (int r = 0; r < 3; r++) {
            src[r] = (const int*)d_in[1 + 6 * r];
            dst[r] = (const int*)d_in[2 + 6 * r];
            W1[r]  = (const float*)d_in[3 + 6 * r];
            b1[r]  = (const float*)d_in[4 + 6 * r];
            W2[r]  = (const float*)d_in[5 + 6 * r];
            b2[r]  = (const float*)d_in[6 + 6 * r];
        }
        W3 = (const float*)d_in[19];
        b3 = (const float*)d_in[20];
    }

    cudaFuncSetAttribute(fused12_kernel, cudaFuncAttributeMaxDynamicSharedMemorySize,
                         SMEM_F12_BYTES);

    const int GEMM_X = (M_NODES + 127) / 128;                    // 391
    const int E3     = (3 * N_EDGES + 255) / 256;
    const int NV3    = (3 * M_NODES + 255) / 256;
    const int SEG3   = (int)(((size_t)3 * M_NODES * 32 + 255) / 256);
    const int CW     = (W1_TOT + W2_TOT + W3_TOT + 255) / 256;

    // Prep
    convW_all<<<CW, 256>>>(W1[0], W1[1], W1[2], W2[0], W2[1], W2[2], W3);
    zero_cnt_kernel<<<NV3, 256>>>();
    deg3_kernel<<<E3, 256>>>(dst[0], dst[1], dst[2]);
    scan_kernel<<<3, 1024>>>();
    fill_kernel<<<E3, 256>>>(src[0], src[1], src[2], dst[0], dst[1], dst[2]);

    // Fused 2-layer MLP (relation-batched)
    {
        dim3 g(GEMM_X, 3);
        fused12_kernel<<<g, 256, SMEM_F12_BYTES>>>(x, b1[0], b1[1], b1[2], b2[0], b2[1], b2[2]);
    }

    // Propagation
    segsum_kernel<1><<<SEG3, 256>>>();
    segsum_kernel<2><<<SEG3, 256>>>();

    // Output projection
    mma_gemm3<<<GEMM_X, 256>>>(b3, (float*)d_out);
}

// round 11
// speedup vs baseline: 3.0165x; 1.0470x over previous
#include <cuda_runtime.h>
#include <cuda_bf16.h>
#include <cstdint>

#define M_NODES 50000
#define N_EDGES 600000
#define IN_DIM  256
#define H_DIM   128
#define MH ((size_t)M_NODES * H_DIM)

#define SCAN_TILE 4096
#define SCAN_NBLK ((M_NODES + SCAN_TILE - 1) / SCAN_TILE)   // 13

// ---------------------------------------------------------------------------
// Device scratch — activations fp32; hi/lo split in-register
// g_T layout: [3 rel][3 stage][MH]
// ---------------------------------------------------------------------------
__device__ __align__(256) float g_T[9 * MH];
__device__ __align__(256) float g_dinv3[3 * M_NODES];
__device__ __align__(256) int   g_cnt[3 * M_NODES];
__device__ __align__(256) int   g_cur[3 * M_NODES];
__device__ __align__(256) int   g_blk[3 * SCAN_NBLK];
__device__ __align__(256) int   g_sorted[(size_t)3 * N_EDGES];

__device__ __align__(256) __nv_bfloat16 g_Bt1h[3 * 128 * 256];
__device__ __align__(256) __nv_bfloat16 g_Bt1l[3 * 128 * 256];
__device__ __align__(256) __nv_bfloat16 g_Bt2h[3 * 128 * 128];
__device__ __align__(256) __nv_bfloat16 g_Bt2l[3 * 128 * 128];
__device__ __align__(256) __nv_bfloat16 g_Bt3h[3 * 128 * 128];
__device__ __align__(256) __nv_bfloat16 g_Bt3l[3 * 128 * 128];

__device__ __forceinline__ float leaky(float v) { return v > 0.0f ? v : 0.01f * v; }

__device__ __forceinline__ uint32_t s2u(const void* p) {
    uint32_t a;
    asm("{ .reg .u64 t; cvta.to.shared.u64 t, %1; cvt.u32.u64 %0, t; }" : "=r"(a) : "l"(p));
    return a;
}
__device__ __forceinline__ void ldm_x4(uint32_t* r, uint32_t addr) {
    asm volatile("ldmatrix.sync.aligned.m8n8.x4.shared.b16 {%0,%1,%2,%3}, [%4];"
                 : "=r"(r[0]), "=r"(r[1]), "=r"(r[2]), "=r"(r[3]) : "r"(addr));
}
__device__ __forceinline__ void mma16816(float* c, const uint32_t* a, const uint32_t* b) {
    asm volatile(
        "mma.sync.aligned.m16n8k16.row.col.f32.bf16.bf16.f32 "
        "{%0,%1,%2,%3}, {%4,%5,%6,%7}, {%8,%9}, {%0,%1,%2,%3};"
        : "+f"(c[0]), "+f"(c[1]), "+f"(c[2]), "+f"(c[3])
        : "r"(a[0]), "r"(a[1]), "r"(a[2]), "r"(a[3]), "r"(b[0]), "r"(b[1]));
}
__device__ __forceinline__ void split2(float x, float y, uint32_t& hi, uint32_t& lo) {
    __nv_bfloat162 h;
    h.x = __float2bfloat16(x);
    h.y = __float2bfloat16(y);
    __nv_bfloat162 l;
    l.x = __float2bfloat16(x - __bfloat162float(h.x));
    l.y = __float2bfloat16(y - __bfloat162float(h.y));
    hi = *(uint32_t*)&h;
    lo = *(uint32_t*)&l;
}

#define SPAD 40    // operand-chunk row stride (halves)
#define H1S  136   // resident h1 tile row stride (halves)

// smem layout (halves) for fused12
#define O_AH 0
#define O_AL (O_AH + 128 * SPAD)
#define O_BH (O_AL + 128 * SPAD)
#define O_BL (O_BH + 128 * SPAD)
#define O_H1H (O_BL + 128 * SPAD)
#define O_H1L (O_H1H + 128 * H1S)
#define SMEM_F12_BYTES ((O_H1L + 128 * H1S) * 2)

// ---------------------------------------------------------------------------
// Fused MLP: per (row-block, rel) CTA:
//   A: acc = x @ W1[rel]^T (K=256) -> B: h1=leaky(acc+b1) resident in smem
//   C: acc = h1 @ W2[rel]^T (K=128) -> D: g_T[rel][0] = leaky(acc+b2)
// ---------------------------------------------------------------------------
__global__ void __launch_bounds__(256, 1)
fused12_kernel(const float* __restrict__ x,
               const float* __restrict__ b1_0, const float* __restrict__ b1_1,
               const float* __restrict__ b1_2,
               const float* __restrict__ b2_0, const float* __restrict__ b2_1,
               const float* __restrict__ b2_2) {
    extern __shared__ __nv_bfloat16 sm[];
    const int tid = threadIdx.x;
    const int wid = tid >> 5;
    const int lane = tid & 31;
    const int row0 = blockIdx.x * 128;
    const int rel = blockIdx.y;
    const int wm0 = (wid & 1) * 64;
    const int wn0 = (wid >> 1) * 32;

    const float* b1 = rel == 0 ? b1_0 : (rel == 1 ? b1_1 : b1_2);
    const float* b2 = rel == 0 ? b2_0 : (rel == 1 ? b2_1 : b2_2);

    const uint32_t base = s2u(sm);
    const uint32_t uAh = base + O_AH * 2, uAl = base + O_AL * 2;
    const uint32_t uBh = base + O_BH * 2, uBl = base + O_BL * 2;
    const uint32_t uH1h = base + O_H1H * 2, uH1l = base + O_H1L * 2;

    const int a_row = (lane & 7) + ((lane >> 3) & 1) * 8;
    const int a_kof = ((lane >> 4) & 1) * 8;
    const int b_nof = ((lane >> 4) & 1) * 8;
    const int b_kof = ((lane >> 3) & 1) * 8;
    const int b_row = lane & 7;
    const int lr = lane >> 2;
    const int lc = (lane & 3) * 2;

    float acc[4][4][4] = {};

    // Phase A
    const __nv_bfloat16* B1h = g_Bt1h + rel * 128 * 256;
    const __nv_bfloat16* B1l = g_Bt1l + rel * 128 * 256;
    for (int k0 = 0; k0 < 256; k0 += 32) {
        __syncthreads();
#pragma unroll
        for (int it = 0; it < 2; it++) {
            int i = it * 256 + tid;
            int r = i >> 2, q = (i & 3) * 8;
            int gr = row0 + r;
            float4 f0 = make_float4(0.f, 0.f, 0.f, 0.f);
            float4 f1 = make_float4(0.f, 0.f, 0.f, 0.f);
            if (gr < M_NODES) {
                const float* ap = x + (size_t)gr * 256 + k0 + q;
                f0 = *(const float4*)ap;
                f1 = *(const float4*)(ap + 4);
            }
            uint4 H, L;
            split2(f0.x, f0.y, H.x, L.x);
            split2(f0.z, f0.w, H.y, L.y);
            split2(f1.x, f1.y, H.z, L.z);
            split2(f1.z, f1.w, H.w, L.w);
            *(uint4*)(sm + O_AH + r * SPAD + q) = H;
            *(uint4*)(sm + O_AL + r * SPAD + q) = L;
            *(uint4*)(sm + O_BH + r * SPAD + q) = *(const uint4*)(B1h + (size_t)r * 256 + k0 + q);
            *(uint4*)(sm + O_BL + r * SPAD + q) = *(const uint4*)(B1l + (size_t)r * 256 + k0 + q);
        }
        __syncthreads();
#pragma unroll
        for (int ks = 0; ks < 32; ks += 16) {
            uint32_t ah[4][4], al[4][4], bh[4][2], bl[4][2];
#pragma unroll
            for (int mf = 0; mf < 4; mf++) {
                uint32_t off = ((wm0 + mf * 16 + a_row) * SPAD + ks + a_kof) * 2;
                ldm_x4(ah[mf], uAh + off);
                ldm_x4(al[mf], uAl + off);
            }
#pragma unroll
            for (int nb = 0; nb < 2; nb++) {
                uint32_t off = ((wn0 + nb * 16 + b_nof + b_row) * SPAD + ks + b_kof) * 2;
                uint32_t t[4];
                ldm_x4(t, uBh + off);
                bh[2 * nb][0] = t[0]; bh[2 * nb][1] = t[1];
                bh[2 * nb + 1][0] = t[2]; bh[2 * nb + 1][1] = t[3];
                ldm_x4(t, uBl + off);
                bl[2 * nb][0] = t[0]; bl[2 * nb][1] = t[1];
                bl[2 * nb + 1][0] = t[2]; bl[2 * nb + 1][1] = t[3];
            }
#pragma unroll
            for (int mf = 0; mf < 4; mf++)
#pragma unroll
                for (int nf = 0; nf < 4; nf++) {
                    mma16816(acc[mf][nf], ah[mf], bh[nf]);
                    mma16816(acc[mf][nf], ah[mf], bl[nf]);
                    mma16816(acc[mf][nf], al[mf], bh[nf]);
                }
        }
    }

    // Phase B
    __syncthreads();
#pragma unroll
    for (int mf = 0; mf < 4; mf++)
#pragma unroll
        for (int half = 0; half < 2; half++) {
            int row = wm0 + mf * 16 + lr + half * 8;
#pragma unroll
            for (int nf = 0; nf < 4; nf++) {
                int col = wn0 + nf * 8 + lc;
                float v0 = leaky(acc[mf][nf][2 * half]     + __ldg(b1 + col));
                float v1 = leaky(acc[mf][nf][2 * half + 1] + __ldg(b1 + col + 1));
                uint32_t hi, lo;
                split2(v0, v1, hi, lo);
                *(uint32_t*)(sm + O_H1H + row * H1S + col) = hi;
                *(uint32_t*)(sm + O_H1L + row * H1S + col) = lo;
            }
        }

#pragma unroll
    for (int mf = 0; mf < 4; mf++)
#pragma unroll
        for (int nf = 0; nf < 4; nf++)
#pragma unroll
            for (int q = 0; q < 4; q++) acc[mf][nf][q] = 0.f;

    // Phase C
    const __nv_bfloat16* B2h = g_Bt2h + rel * 128 * 128;
    const __nv_bfloat16* B2l = g_Bt2l + rel * 128 * 128;
    for (int k0 = 0; k0 < 128; k0 += 32) {
        __syncthreads();
#pragma unroll
        for (int it = 0; it < 2; it++) {
            int i = it * 256 + tid;
            int r = i >> 2, q = (i & 3) * 8;
            *(uint4*)(sm + O_BH + r * SPAD + q) = *(const uint4*)(B2h + (size_t)r * 128 + k0 + q);
            *(uint4*)(sm + O_BL + r * SPAD + q) = *(const uint4*)(B2l + (size_t)r * 128 + k0 + q);
        }
        __syncthreads();
#pragma unroll
        for (int ks = 0; ks < 32; ks += 16) {
            uint32_t ah[4][4], al[4][4], bh[4][2], bl[4][2];
#pragma unroll
            for (int mf = 0; mf < 4; mf++) {
                uint32_t off = ((wm0 + mf * 16 + a_row) * H1S + k0 + ks + a_kof) * 2;
                ldm_x4(ah[mf], uH1h + off);
                ldm_x4(al[mf], uH1l + off);
            }
#pragma unroll
            for (int nb = 0; nb < 2; nb++) {
                uint32_t off = ((wn0 + nb * 16 + b_nof + b_row) * SPAD + ks + b_kof) * 2;
                uint32_t t[4];
                ldm_x4(t, uBh + off);
                bh[2 * nb][0] = t[0]; bh[2 * nb][1] = t[1];
                bh[2 * nb + 1][0] = t[2]; bh[2 * nb + 1][1] = t[3];
                ldm_x4(t, uBl + off);
                bl[2 * nb][0] = t[0]; bl[2 * nb][1] = t[1];
                bl[2 * nb + 1][0] = t[2]; bl[2 * nb + 1][1] = t[3];
            }
#pragma unroll
            for (int mf = 0; mf < 4; mf++)
#pragma unroll
                for (int nf = 0; nf < 4; nf++) {
                    mma16816(acc[mf][nf], ah[mf], bh[nf]);
                    mma16816(acc[mf][nf], ah[mf], bl[nf]);
                    mma16816(acc[mf][nf], al[mf], bh[nf]);
                }
        }
    }

    // Phase D
    float* T0 = g_T + (size_t)(rel * 3) * MH;
#pragma unroll
    for (int mf = 0; mf < 4; mf++)
#pragma unroll
        for (int half = 0; half < 2; half++) {
            int row = row0 + wm0 + mf * 16 + lr + half * 8;
            if (row >= M_NODES) continue;
#pragma unroll
            for (int nf = 0; nf < 4; nf++) {
                int col = wn0 + nf * 8 + lc;
                float v0 = leaky(acc[mf][nf][2 * half]     + __ldg(b2 + col));
                float v1 = leaky(acc[mf][nf][2 * half + 1] + __ldg(b2 + col + 1));
                *(float2*)(T0 + (size_t)row * H_DIM + col) = make_float2(v0, v1);
            }
        }
}

// ---------------------------------------------------------------------------
// Output GEMM: out = leaky( sum_{r,s} T[r][s] @ W3eff[s]^T + b3 )
// ---------------------------------------------------------------------------
__global__ void __launch_bounds__(256, 1)
mma_gemm3(const float* __restrict__ bias, float* __restrict__ out) {
    __shared__ __nv_bfloat16 sAh[128][SPAD], sAl[128][SPAD];
    __shared__ __nv_bfloat16 sBh[128][SPAD], sBl[128][SPAD];

    const int tid = threadIdx.x;
    const int wid = tid >> 5;
    const int lane = tid & 31;
    const int row0 = blockIdx.x * 128;
    const int wm0 = (wid & 1) * 64;
    const int wn0 = (wid >> 1) * 32;

    const uint32_t uAh = s2u(sAh), uAl = s2u(sAl), uBh = s2u(sBh), uBl = s2u(sBl);

    float acc[4][4][4] = {};

    const int a_row = (lane & 7) + ((lane >> 3) & 1) * 8;
    const int a_kof = ((lane >> 4) & 1) * 8;
    const int b_nof = ((lane >> 4) & 1) * 8;
    const int b_kof = ((lane >> 3) & 1) * 8;
    const int b_row = lane & 7;

    for (int k0 = 0; k0 < 1152; k0 += 32) {
        int c = k0 >> 7;
        int s = c % 3;
        const float* pA = g_T + (size_t)c * MH;
        int ako = k0 & 127;
        const __nv_bfloat16* pBh = g_Bt3h + s * 128 * 128;
        const __nv_bfloat16* pBl = g_Bt3l + s * 128 * 128;
        int bko = k0 & 127;

        __syncthreads();
#pragma unroll
        for (int it = 0; it < 2; it++) {
            int i = it * 256 + tid;
            int r = i >> 2, q = (i & 3) * 8;
            int gr = row0 + r;
            float4 f0 = make_float4(0.f, 0.f, 0.f, 0.f);
            float4 f1 = make_float4(0.f, 0.f, 0.f, 0.f);
            if (gr < M_NODES) {
                const float* ap = pA + (size_t)gr * 128 + ako + q;
                f0 = *(const float4*)ap;
                f1 = *(const float4*)(ap + 4);
            }
            uint4 H, L;
            split2(f0.x, f0.y, H.x, L.x);
            split2(f0.z, f0.w, H.y, L.y);
            split2(f1.x, f1.y, H.z, L.z);
            split2(f1.z, f1.w, H.w, L.w);
            *(uint4*)&sAh[r][q] = H;
            *(uint4*)&sAl[r][q] = L;
            *(uint4*)&sBh[r][q] = *(const uint4*)(pBh + (size_t)r * 128 + bko + q);
            *(uint4*)&sBl[r][q] = *(const uint4*)(pBl + (size_t)r * 128 + bko + q);
        }
        __syncthreads();

#pragma unroll
        for (int ks = 0; ks < 32; ks += 16) {
            uint32_t ah[4][4], al[4][4], bh[4][2], bl[4][2];
#pragma unroll
            for (int mf = 0; mf < 4; mf++) {
                uint32_t off = ((wm0 + mf * 16 + a_row) * SPAD + ks + a_kof) * 2;
                ldm_x4(ah[mf], uAh + off);
                ldm_x4(al[mf], uAl + off);
            }
#pragma unroll
            for (int nb = 0; nb < 2; nb++) {
                uint32_t off = ((wn0 + nb * 16 + b_nof + b_row) * SPAD + ks + b_kof) * 2;
                uint32_t t[4];
                ldm_x4(t, uBh + off);
                bh[2 * nb][0] = t[0]; bh[2 * nb][1] = t[1];
                bh[2 * nb + 1][0] = t[2]; bh[2 * nb + 1][1] = t[3];
                ldm_x4(t, uBl + off);
                bl[2 * nb][0] = t[0]; bl[2 * nb][1] = t[1];
                bl[2 * nb + 1][0] = t[2]; bl[2 * nb + 1][1] = t[3];
            }
#pragma unroll
            for (int mf = 0; mf < 4; mf++)
#pragma unroll
                for (int nf = 0; nf < 4; nf++) {
                    mma16816(acc[mf][nf], ah[mf], bh[nf]);
                    mma16816(acc[mf][nf], ah[mf], bl[nf]);
                    mma16816(acc[mf][nf], al[mf], bh[nf]);
                }
        }
    }

    const int lr = lane >> 2;
    const int lc = (lane & 3) * 2;
#pragma unroll
    for (int mf = 0; mf < 4; mf++)
#pragma unroll
        for (int half = 0; half < 2; half++) {
            int row = row0 + wm0 + mf * 16 + lr + half * 8;
            if (row >= M_NODES) continue;
#pragma unroll
            for (int nf = 0; nf < 4; nf++) {
                int col = wn0 + nf * 8 + lc;
                float v0 = leaky(acc[mf][nf][2 * half]     + __ldg(bias + col));
                float v1 = leaky(acc[mf][nf][2 * half + 1] + __ldg(bias + col + 1));
                *(float2*)(out + (size_t)row * H_DIM + col) = make_float2(v0, v1);
            }
        }
}

// ---------------------------------------------------------------------------
// Merged weight prep
// ---------------------------------------------------------------------------
#define W1_TOT (3 * 128 * 256)
#define W2_TOT (3 * 128 * 128)
#define W3_TOT (128 * 128)

__global__ void convW_all(const float* __restrict__ W1a, const float* __restrict__ W1b,
                          const float* __restrict__ W1c, const float* __restrict__ W2a,
                          const float* __restrict__ W2b, const float* __restrict__ W2c,
                          const float* __restrict__ W3) {
    int i = blockIdx.x * blockDim.x + threadIdx.x;
    if (i < W1_TOT) {
        int r = i / 32768, rem = i % 32768, n = rem >> 8, k = rem & 255;
        const float* W = r == 0 ? W1a : (r == 1 ? W1b : W1c);
        float v = W[k * H_DIM + n];
        __nv_bfloat16 h = __float2bfloat16(v);
        g_Bt1h[i] = h;
        g_Bt1l[i] = __float2bfloat16(v - __bfloat162float(h));
        return;
    }
    i -= W1_TOT;
    if (i < W2_TOT) {
        int r = i >> 14, rem = i & 16383, n = rem >> 7, k = rem & 127;
        const float* W = r == 0 ? W2a : (r == 1 ? W2b : W2c);
        float v = W[k * H_DIM + n];
        __nv_bfloat16 h = __float2bfloat16(v);
        g_Bt2h[i] = h;
        g_Bt2l[i] = __float2bfloat16(v - __bfloat162float(h));
        return;
    }
    i -= W2_TOT;
    if (i < W3_TOT) {
        int n = i >> 7, k = i & 127;
        float w0 = W3[(0 * 128 + k) * 128 + n];
        float w1 = W3[(1 * 128 + k) * 128 + n];
        float w2 = W3[(2 * 128 + k) * 128 + n];
        float e[3];
        e[0] = 3.0f * w0;
        e[1] = -3.0f * w0 + 3.0f * w1;
        e[2] = 0.75f * w0 - 1.5f * w1 + 0.75f * w2;
#pragma unroll
        for (int s = 0; s < 3; s++) {
            __nv_bfloat16 h = __float2bfloat16(e[s]);
            g_Bt3h[s * 128 * 128 + n * 128 + k] = h;
            g_Bt3l[s * 128 * 128 + n * 128 + k] = __float2bfloat16(e[s] - __bfloat162float(h));
        }
    }
}

// ---------------------------------------------------------------------------
// Graph preprocessing
// ---------------------------------------------------------------------------
__global__ void zero_cnt_kernel() {
    int i = blockIdx.x * blockDim.x + threadIdx.x;
    if (i < 3 * M_NODES) g_cnt[i] = 0;
}
__global__ void deg3_kernel(const int* __restrict__ d0, const int* __restrict__ d1,
                            const int* __restrict__ d2) {
    int t = blockIdx.x * blockDim.x + threadIdx.x;
    if (t >= 3 * N_EDGES) return;
    int r = t / N_EDGES, e = t - r * N_EDGES;
    const int* d = r == 0 ? d0 : (r == 1 ? d1 : d2);
    atomicAdd(&g_cnt[r * M_NODES + __ldg(d + e)], 1);
}

// ---- Three-phase scan: fully parallel across 13x3 blocks ----
// Phase A: per-block sums of 4096-element chunks (+ dinv emit)
__global__ void scanA_kernel() {
    __shared__ int wsum[8];
    const int r = blockIdx.y, b = blockIdx.x;
    const int tid = threadIdx.x;
    const int base = b * SCAN_TILE + tid * 16;

    int s = 0;
#pragma unroll
    for (int k = 0; k < 16; k++) {
        int i = base + k;
        if (i < M_NODES) {
            int v = g_cnt[r * M_NODES + i];
            g_dinv3[r * M_NODES + i] = rsqrtf(fmaxf((float)v, 1.0f));
            s += v;
        }
    }
#pragma unroll
    for (int o = 16; o > 0; o >>= 1) s += __shfl_down_sync(0xFFFFFFFFu, s, o);
    if ((tid & 31) == 0) wsum[tid >> 5] = s;
    __syncthreads();
    if (tid == 0) {
        int t = 0;
#pragma unroll
        for (int w = 0; w < 8; w++) t += wsum[w];
        g_blk[r * SCAN_NBLK + b] = t;
    }
}

// Phase B: exclusive scan of 13 block sums per relation (3 threads)
__global__ void scanB_kernel() {
    int r = threadIdx.x;
    if (r >= 3) return;
    int run = 0;
#pragma unroll
    for (int b = 0; b < SCAN_NBLK; b++) {
        int t = g_blk[r * SCAN_NBLK + b];
        g_blk[r * SCAN_NBLK + b] = run;
        run += t;
    }
}

// Phase C: block-internal exclusive scan + block offset -> g_cur
__global__ void scanC_kernel() {
    __shared__ int warp_sums[8];
    const int r = blockIdx.y, b = blockIdx.x;
    const int tid = threadIdx.x;
    const int lane = tid & 31;
    const int wid = tid >> 5;
    const int base = b * SCAN_TILE + tid * 16;

    int v[16];
    int tsum = 0;
#pragma unroll
    for (int k = 0; k < 16; k++) {
        int i = base + k;
        v[k] = (i < M_NODES) ? g_cnt[r * M_NODES + i] : 0;
        tsum += v[k];
    }
    // inclusive scan of thread sums
    int x = tsum;
#pragma unroll
    for (int o = 1; o < 32; o <<= 1) {
        int y = __shfl_up_sync(0xFFFFFFFFu, x, o);
        if (lane >= o) x += y;
    }
    if (lane == 31) warp_sums[wid] = x;
    __syncthreads();
    if (wid == 0 && lane < 8) {
        int w = warp_sums[lane];
#pragma unroll
        for (int o = 1; o < 8; o <<= 1) {
            int y = __shfl_up_sync(0xFFu, w, o);
            if (lane >= o) w += y;
        }
        warp_sums[lane] = w;
    }
    __syncthreads();
    int woff = (wid > 0) ? warp_sums[wid - 1] : 0;
    int run = g_blk[r * SCAN_NBLK + b] + woff + x - tsum;
#pragma unroll
    for (int k = 0; k < 16; k++) {
        int i = base + k;
        if (i < M_NODES) g_cur[r * M_NODES + i] = run;
        run += v[k];
    }
}

__global__ void fill_kernel(const int* __restrict__ s0, const int* __restrict__ s1,
                            const int* __restrict__ s2, const int* __restrict__ d0,
                            const int* __restrict__ d1, const int* __restrict__ d2) {
    int t = blockIdx.x * blockDim.x + threadIdx.x;
    if (t >= 3 * N_EDGES) return;
    int r = t / N_EDGES, e = t - r * N_EDGES;
    const int* sp = r == 0 ? s0 : (r == 1 ? s1 : s2);
    const int* dp = r == 0 ? d0 : (r == 1 ? d1 : d2);
    int s = __ldg(sp + e);
    int d = __ldg(dp + e);
    int p = atomicAdd(&g_cur[r * M_NODES + d], 1);
    g_sorted[(size_t)r * N_EDGES + p] = s;
}

// ---------------------------------------------------------------------------
// Fused segmented-sum + combine: one warp per (rel, node), fp32
// After fill, g_cur[rn] == segment END (start + cnt).
// ---------------------------------------------------------------------------
template <int STEP>
__global__ void __launch_bounds__(256) segsum_kernel() {
    int t = blockIdx.x * blockDim.x + threadIdx.x;
    int w = t >> 5;
    if (w >= 3 * M_NODES) return;
    const int lane = t & 31;
    const int r = w / M_NODES, n = w - r * M_NODES;
    const int rn = r * M_NODES + n;
    const int end = __ldg(&g_cur[rn]);
    const int cnt = __ldg(&g_cnt[rn]);
    int j = end - cnt;
    const int* ss = g_sorted + (size_t)r * N_EDGES;
    const float* f = g_T + (size_t)(r * 3 + STEP - 1) * MH;
    const float* dv = g_dinv3 + r * M_NODES;

    float4 a0 = make_float4(0.f, 0.f, 0.f, 0.f);
    float4 a1 = make_float4(0.f, 0.f, 0.f, 0.f);
    for (; j + 2 <= end; j += 2) {
        int s0 = __ldg(ss + j);
        int s1 = __ldg(ss + j + 1);
        float e0 = __ldg(dv + s0);
        float e1 = __ldg(dv + s1);
        float4 v0 = *(const float4*)(f + (size_t)s0 * H_DIM + lane * 4);
        float4 v1 = *(const float4*)(f + (size_t)s1 * H_DIM + lane * 4);
        a0.x += v0.x * e0; a0.y += v0.y * e0; a0.z += v0.z * e0; a0.w += v0.w * e0;
        a1.x += v1.x * e1; a1.y += v1.y * e1; a1.z += v1.z * e1; a1.w += v1.w * e1;
    }
    if (j < end) {
        int s0 = __ldg(ss + j);
        float e0 = __ldg(dv + s0);
        float4 v0 = *(const float4*)(f + (size_t)s0 * H_DIM + lane * 4);
        a0.x += v0.x * e0; a0.y += v0.y * e0; a0.z += v0.z * e0; a0.w += v0.w * e0;
    }
    float dn = __ldg(dv + n);
    float4 t0 = *(const float4*)(f + (size_t)n * H_DIM + lane * 4);
    float4 o;
    o.x = t0.x - (a0.x + a1.x) * dn;
    o.y = t0.y - (a0.y + a1.y) * dn;
    o.z = t0.z - (a0.z + a1.z) * dn;
    o.w = t0.w - (a0.w + a1.w) * dn;
    *(float4*)(g_T + (size_t)(r * 3 + STEP) * MH + (size_t)n * H_DIM + lane * 4) = o;
}

// ---------------------------------------------------------------------------
// Launch
// ---------------------------------------------------------------------------
extern "C" void kernel_launch(void* const* d_in, const int* in_sizes, int n_in,
                              void* d_out, int out_size) {
    const float* x = (const float*)d_in[0];
    const int *src[3], *dst[3];
    const float *W1[3], *b1[3], *W2[3], *b2[3];
    const float *W3, *b3;

    if (in_sizes[3] == N_EDGES) {
        for (int r = 0; r < 3; r++) {
            src[r] = (const int*)d_in[1 + 2 * r];
            dst[r] = (const int*)d_in[2 + 2 * r];
        }
        for (int r = 0; r < 3; r++) {
            W1[r] = (const float*)d_in[7 + 4 * r];
            b1[r] = (const float*)d_in[8 + 4 * r];
            W2[r] = (const float*)d_in[9 + 4 * r];
            b2[r] = (const float*)d_in[10 + 4 * r];
        }
        W3 = (const float*)d_in[19];
        b3 = (const float*)d_in[20];
    } else {
        for (int r = 0; r < 3; r++) {
            src[r] = (const int*)d_in[1 + 6 * r];
            dst[r] = (const int*)d_in[2 + 6 * r];
            W1[r]  = (const float*)d_in[3 + 6 * r];
            b1[r]  = (const float*)d_in[4 + 6 * r];
            W2[r]  = (const float*)d_in[5 + 6 * r];
            b2[r]  = (const float*)d_in[6 + 6 * r];
        }
        W3 = (const float*)d_in[19];
        b3 = (const float*)d_in[20];
    }

    cudaFuncSetAttribute(fused12_kernel, cudaFuncAttributeMaxDynamicSharedMemorySize,
                         SMEM_F12_BYTES);

    const int GEMM_X = (M_NODES + 127) / 128;                    // 391
    const int E3     = (3 * N_EDGES + 255) / 256;
    const int NV3    = (3 * M_NODES + 255) / 256;
    const int SEG3   = (int)(((size_t)3 * M_NODES * 32 + 255) / 256);
    const int CW     = (W1_TOT + W2_TOT + W3_TOT + 255) / 256;

    // Prep
    convW_all<<<CW, 256>>>(W1[0], W1[1], W1[2], W2[0], W2[1], W2[2], W3);
    zero_cnt_kernel<<<NV3, 256>>>();
    deg3_kernel<<<E3, 256>>>(dst[0], dst[1], dst[2]);
    {
        dim3 sg(SCAN_NBLK, 3);
        scanA_kernel<<<sg, 256>>>();
        scanB_kernel<<<1, 32>>>();
        scanC_kernel<<<sg, 256>>>();
    }
    fill_kernel<<<E3, 256>>>(src[0], src[1], src[2], dst[0], dst[1], dst[2]);

    // Fused 2-layer MLP (relation-batched)
    {
        dim3 g(GEMM_X, 3);
        fused12_kernel<<<g, 256, SMEM_F12_BYTES>>>(x, b1[0], b1[1], b1[2], b2[0], b2[1], b2[2]);
    }

    // Propagation
    segsum_kernel<1><<<SEG3, 256>>>();
    segsum_kernel<2><<<SEG3, 256>>>();

    // Output projection
    mma_gemm3<<<GEMM_X, 256>>>(b3, (float*)d_out);
}

// round 12
// speedup vs baseline: 3.1267x; 1.0365x over previous
#include <cuda_runtime.h>
#include <cuda_bf16.h>
#include <cstdint>

#define M_NODES 50000
#define N_EDGES 600000
#define IN_DIM  256
#define H_DIM   128
#define MH ((size_t)M_NODES * H_DIM)

#define SCAN_TILE 4096
#define SCAN_NBLK ((M_NODES + SCAN_TILE - 1) / SCAN_TILE)   // 13

// ---------------------------------------------------------------------------
// Device scratch — activations fp32; hi/lo split in-register
// g_T layout: [3 rel][3 stage][MH]
// ---------------------------------------------------------------------------
__device__ __align__(256) float g_T[9 * MH];
__device__ __align__(256) float g_dinv3[3 * M_NODES];
__device__ __align__(256) int   g_cnt[3 * M_NODES];
__device__ __align__(256) int   g_cur[3 * M_NODES];
__device__ __align__(256) int   g_blk[3 * SCAN_NBLK];
__device__ __align__(256) int   g_sorted[(size_t)3 * N_EDGES];

__device__ __align__(256) __nv_bfloat16 g_Bt1h[3 * 128 * 256];
__device__ __align__(256) __nv_bfloat16 g_Bt1l[3 * 128 * 256];
__device__ __align__(256) __nv_bfloat16 g_Bt2h[3 * 128 * 128];
__device__ __align__(256) __nv_bfloat16 g_Bt2l[3 * 128 * 128];
__device__ __align__(256) __nv_bfloat16 g_Bt3h[3 * 128 * 128];
__device__ __align__(256) __nv_bfloat16 g_Bt3l[3 * 128 * 128];

__device__ __forceinline__ float leaky(float v) { return v > 0.0f ? v : 0.01f * v; }

__device__ __forceinline__ uint32_t s2u(const void* p) {
    uint32_t a;
    asm("{ .reg .u64 t; cvta.to.shared.u64 t, %1; cvt.u32.u64 %0, t; }" : "=r"(a) : "l"(p));
    return a;
}
__device__ __forceinline__ void ldm_x4(uint32_t* r, uint32_t addr) {
    asm volatile("ldmatrix.sync.aligned.m8n8.x4.shared.b16 {%0,%1,%2,%3}, [%4];"
                 : "=r"(r[0]), "=r"(r[1]), "=r"(r[2]), "=r"(r[3]) : "r"(addr));
}
__device__ __forceinline__ void mma16816(float* c, const uint32_t* a, const uint32_t* b) {
    asm volatile(
        "mma.sync.aligned.m16n8k16.row.col.f32.bf16.bf16.f32 "
        "{%0,%1,%2,%3}, {%4,%5,%6,%7}, {%8,%9}, {%0,%1,%2,%3};"
        : "+f"(c[0]), "+f"(c[1]), "+f"(c[2]), "+f"(c[3])
        : "r"(a[0]), "r"(a[1]), "r"(a[2]), "r"(a[3]), "r"(b[0]), "r"(b[1]));
}
__device__ __forceinline__ void split2(float x, float y, uint32_t& hi, uint32_t& lo) {
    __nv_bfloat162 h;
    h.x = __float2bfloat16(x);
    h.y = __float2bfloat16(y);
    __nv_bfloat162 l;
    l.x = __float2bfloat16(x - __bfloat162float(h.x));
    l.y = __float2bfloat16(y - __bfloat162float(h.y));
    hi = *(uint32_t*)&h;
    lo = *(uint32_t*)&l;
}

#define SPAD 40    // operand-chunk row stride (halves)
#define H1S  136   // resident h1 tile row stride (halves)

// smem layout (halves) for fused12
#define O_AH 0
#define O_AL (O_AH + 128 * SPAD)
#define O_BH (O_AL + 128 * SPAD)
#define O_BL (O_BH + 128 * SPAD)
#define O_H1H (O_BL + 128 * SPAD)
#define O_H1L (O_H1H + 128 * H1S)
#define SMEM_F12_BYTES ((O_H1L + 128 * H1S) * 2)

// ---------------------------------------------------------------------------
// Fused MLP: per (row-block, rel) CTA:
//   A: acc = x @ W1[rel]^T (K=256) -> B: h1=leaky(acc+b1) resident in smem
//   C: acc = h1 @ W2[rel]^T (K=128) -> D: g_T[rel][0] = leaky(acc+b2)
// ---------------------------------------------------------------------------
__global__ void __launch_bounds__(256, 1)
fused12_kernel(const float* __restrict__ x,
               const float* __restrict__ b1_0, const float* __restrict__ b1_1,
               const float* __restrict__ b1_2,
               const float* __restrict__ b2_0, const float* __restrict__ b2_1,
               const float* __restrict__ b2_2) {
    extern __shared__ __nv_bfloat16 sm[];
    const int tid = threadIdx.x;
    const int wid = tid >> 5;
    const int lane = tid & 31;
    const int row0 = blockIdx.x * 128;
    const int rel = blockIdx.y;
    const int wm0 = (wid & 1) * 64;
    const int wn0 = (wid >> 1) * 32;

    const float* b1 = rel == 0 ? b1_0 : (rel == 1 ? b1_1 : b1_2);
    const float* b2 = rel == 0 ? b2_0 : (rel == 1 ? b2_1 : b2_2);

    const uint32_t base = s2u(sm);
    const uint32_t uAh = base + O_AH * 2, uAl = base + O_AL * 2;
    const uint32_t uBh = base + O_BH * 2, uBl = base + O_BL * 2;
    const uint32_t uH1h = base + O_H1H * 2, uH1l = base + O_H1L * 2;

    const int a_row = (lane & 7) + ((lane >> 3) & 1) * 8;
    const int a_kof = ((lane >> 4) & 1) * 8;
    const int b_nof = ((lane >> 4) & 1) * 8;
    const int b_kof = ((lane >> 3) & 1) * 8;
    const int b_row = lane & 7;
    const int lr = lane >> 2;
    const int lc = (lane & 3) * 2;

    float acc[4][4][4] = {};

    // Phase A
    const __nv_bfloat16* B1h = g_Bt1h + rel * 128 * 256;
    const __nv_bfloat16* B1l = g_Bt1l + rel * 128 * 256;
    for (int k0 = 0; k0 < 256; k0 += 32) {
        __syncthreads();
#pragma unroll
        for (int it = 0; it < 2; it++) {
            int i = it * 256 + tid;
            int r = i >> 2, q = (i & 3) * 8;
            int gr = row0 + r;
            float4 f0 = make_float4(0.f, 0.f, 0.f, 0.f);
            float4 f1 = make_float4(0.f, 0.f, 0.f, 0.f);
            if (gr < M_NODES) {
                const float* ap = x + (size_t)gr * 256 + k0 + q;
                f0 = *(const float4*)ap;
                f1 = *(const float4*)(ap + 4);
            }
            uint4 H, L;
            split2(f0.x, f0.y, H.x, L.x);
            split2(f0.z, f0.w, H.y, L.y);
            split2(f1.x, f1.y, H.z, L.z);
            split2(f1.z, f1.w, H.w, L.w);
            *(uint4*)(sm + O_AH + r * SPAD + q) = H;
            *(uint4*)(sm + O_AL + r * SPAD + q) = L;
            *(uint4*)(sm + O_BH + r * SPAD + q) = *(const uint4*)(B1h + (size_t)r * 256 + k0 + q);
            *(uint4*)(sm + O_BL + r * SPAD + q) = *(const uint4*)(B1l + (size_t)r * 256 + k0 + q);
        }
        __syncthreads();
#pragma unroll
        for (int ks = 0; ks < 32; ks += 16) {
            uint32_t ah[4][4], al[4][4], bh[4][2], bl[4][2];
#pragma unroll
            for (int mf = 0; mf < 4; mf++) {
                uint32_t off = ((wm0 + mf * 16 + a_row) * SPAD + ks + a_kof) * 2;
                ldm_x4(ah[mf], uAh + off);
                ldm_x4(al[mf], uAl + off);
            }
#pragma unroll
            for (int nb = 0; nb < 2; nb++) {
                uint32_t off = ((wn0 + nb * 16 + b_nof + b_row) * SPAD + ks + b_kof) * 2;
                uint32_t t[4];
                ldm_x4(t, uBh + off);
                bh[2 * nb][0] = t[0]; bh[2 * nb][1] = t[1];
                bh[2 * nb + 1][0] = t[2]; bh[2 * nb + 1][1] = t[3];
                ldm_x4(t, uBl + off);
                bl[2 * nb][0] = t[0]; bl[2 * nb][1] = t[1];
                bl[2 * nb + 1][0] = t[2]; bl[2 * nb + 1][1] = t[3];
            }
#pragma unroll
            for (int mf = 0; mf < 4; mf++)
#pragma unroll
                for (int nf = 0; nf < 4; nf++) {
                    mma16816(acc[mf][nf], ah[mf], bh[nf]);
                    mma16816(acc[mf][nf], ah[mf], bl[nf]);
                    mma16816(acc[mf][nf], al[mf], bh[nf]);
                }
        }
    }

    // Phase B
    __syncthreads();
#pragma unroll
    for (int mf = 0; mf < 4; mf++)
#pragma unroll
        for (int half = 0; half < 2; half++) {
            int row = wm0 + mf * 16 + lr + half * 8;
#pragma unroll
            for (int nf = 0; nf < 4; nf++) {
                int col = wn0 + nf * 8 + lc;
                float v0 = leaky(acc[mf][nf][2 * half]     + __ldg(b1 + col));
                float v1 = leaky(acc[mf][nf][2 * half + 1] + __ldg(b1 + col + 1));
                uint32_t hi, lo;
                split2(v0, v1, hi, lo);
                *(uint32_t*)(sm + O_H1H + row * H1S + col) = hi;
                *(uint32_t*)(sm + O_H1L + row * H1S + col) = lo;
            }
        }

#pragma unroll
    for (int mf = 0; mf < 4; mf++)
#pragma unroll
        for (int nf = 0; nf < 4; nf++)
#pragma unroll
            for (int q = 0; q < 4; q++) acc[mf][nf][q] = 0.f;

    // Phase C
    const __nv_bfloat16* B2h = g_Bt2h + rel * 128 * 128;
    const __nv_bfloat16* B2l = g_Bt2l + rel * 128 * 128;
    for (int k0 = 0; k0 < 128; k0 += 32) {
        __syncthreads();
#pragma unroll
        for (int it = 0; it < 2; it++) {
            int i = it * 256 + tid;
            int r = i >> 2, q = (i & 3) * 8;
            *(uint4*)(sm + O_BH + r * SPAD + q) = *(const uint4*)(B2h + (size_t)r * 128 + k0 + q);
            *(uint4*)(sm + O_BL + r * SPAD + q) = *(const uint4*)(B2l + (size_t)r * 128 + k0 + q);
        }
        __syncthreads();
#pragma unroll
        for (int ks = 0; ks < 32; ks += 16) {
            uint32_t ah[4][4], al[4][4], bh[4][2], bl[4][2];
#pragma unroll
            for (int mf = 0; mf < 4; mf++) {
                uint32_t off = ((wm0 + mf * 16 + a_row) * H1S + k0 + ks + a_kof) * 2;
                ldm_x4(ah[mf], uH1h + off);
                ldm_x4(al[mf], uH1l + off);
            }
#pragma unroll
            for (int nb = 0; nb < 2; nb++) {
                uint32_t off = ((wn0 + nb * 16 + b_nof + b_row) * SPAD + ks + b_kof) * 2;
                uint32_t t[4];
                ldm_x4(t, uBh + off);
                bh[2 * nb][0] = t[0]; bh[2 * nb][1] = t[1];
                bh[2 * nb + 1][0] = t[2]; bh[2 * nb + 1][1] = t[3];
                ldm_x4(t, uBl + off);
                bl[2 * nb][0] = t[0]; bl[2 * nb][1] = t[1];
                bl[2 * nb + 1][0] = t[2]; bl[2 * nb + 1][1] = t[3];
            }
#pragma unroll
            for (int mf = 0; mf < 4; mf++)
#pragma unroll
                for (int nf = 0; nf < 4; nf++) {
                    mma16816(acc[mf][nf], ah[mf], bh[nf]);
                    mma16816(acc[mf][nf], ah[mf], bl[nf]);
                    mma16816(acc[mf][nf], al[mf], bh[nf]);
                }
        }
    }

    // Phase D
    float* T0 = g_T + (size_t)(rel * 3) * MH;
#pragma unroll
    for (int mf = 0; mf < 4; mf++)
#pragma unroll
        for (int half = 0; half < 2; half++) {
            int row = row0 + wm0 + mf * 16 + lr + half * 8;
            if (row >= M_NODES) continue;
#pragma unroll
            for (int nf = 0; nf < 4; nf++) {
                int col = wn0 + nf * 8 + lc;
                float v0 = leaky(acc[mf][nf][2 * half]     + __ldg(b2 + col));
                float v1 = leaky(acc[mf][nf][2 * half + 1] + __ldg(b2 + col + 1));
                *(float2*)(T0 + (size_t)row * H_DIM + col) = make_float2(v0, v1);
            }
        }
}

// ---------------------------------------------------------------------------
// Output GEMM: out = leaky( sum_{r,s} T[r][s] @ W3eff[s]^T + b3 )
// ---------------------------------------------------------------------------
__global__ void __launch_bounds__(256, 1)
mma_gemm3(const float* __restrict__ bias, float* __restrict__ out) {
    __shared__ __nv_bfloat16 sAh[128][SPAD], sAl[128][SPAD];
    __shared__ __nv_bfloat16 sBh[128][SPAD], sBl[128][SPAD];

    const int tid = threadIdx.x;
    const int wid = tid >> 5;
    const int lane = tid & 31;
    const int row0 = blockIdx.x * 128;
    const int wm0 = (wid & 1) * 64;
    const int wn0 = (wid >> 1) * 32;

    const uint32_t uAh = s2u(sAh), uAl = s2u(sAl), uBh = s2u(sBh), uBl = s2u(sBl);

    float acc[4][4][4] = {};

    const int a_row = (lane & 7) + ((lane >> 3) & 1) * 8;
    const int a_kof = ((lane >> 4) & 1) * 8;
    const int b_nof = ((lane >> 4) & 1) * 8;
    const int b_kof = ((lane >> 3) & 1) * 8;
    const int b_row = lane & 7;

    for (int k0 = 0; k0 < 1152; k0 += 32) {
        int c = k0 >> 7;
        int s = c % 3;
        const float* pA = g_T + (size_t)c * MH;
        int ako = k0 & 127;
        const __nv_bfloat16* pBh = g_Bt3h + s * 128 * 128;
        const __nv_bfloat16* pBl = g_Bt3l + s * 128 * 128;
        int bko = k0 & 127;

        __syncthreads();
#pragma unroll
        for (int it = 0; it < 2; it++) {
            int i = it * 256 + tid;
            int r = i >> 2, q = (i & 3) * 8;
            int gr = row0 + r;
            float4 f0 = make_float4(0.f, 0.f, 0.f, 0.f);
            float4 f1 = make_float4(0.f, 0.f, 0.f, 0.f);
            if (gr < M_NODES) {
                const float* ap = pA + (size_t)gr * 128 + ako + q;
                f0 = *(const float4*)ap;
                f1 = *(const float4*)(ap + 4);
            }
            uint4 H, L;
            split2(f0.x, f0.y, H.x, L.x);
            split2(f0.z, f0.w, H.y, L.y);
            split2(f1.x, f1.y, H.z, L.z);
            split2(f1.z, f1.w, H.w, L.w);
            *(uint4*)&sAh[r][q] = H;
            *(uint4*)&sAl[r][q] = L;
            *(uint4*)&sBh[r][q] = *(const uint4*)(pBh + (size_t)r * 128 + bko + q);
            *(uint4*)&sBl[r][q] = *(const uint4*)(pBl + (size_t)r * 128 + bko + q);
        }
        __syncthreads();

#pragma unroll
        for (int ks = 0; ks < 32; ks += 16) {
            uint32_t ah[4][4], al[4][4], bh[4][2], bl[4][2];
#pragma unroll
            for (int mf = 0; mf < 4; mf++) {
                uint32_t off = ((wm0 + mf * 16 + a_row) * SPAD + ks + a_kof) * 2;
                ldm_x4(ah[mf], uAh + off);
                ldm_x4(al[mf], uAl + off);
            }
#pragma unroll
            for (int nb = 0; nb < 2; nb++) {
                uint32_t off = ((wn0 + nb * 16 + b_nof + b_row) * SPAD + ks + b_kof) * 2;
                uint32_t t[4];
                ldm_x4(t, uBh + off);
                bh[2 * nb][0] = t[0]; bh[2 * nb][1] = t[1];
                bh[2 * nb + 1][0] = t[2]; bh[2 * nb + 1][1] = t[3];
                ldm_x4(t, uBl + off);
                bl[2 * nb][0] = t[0]; bl[2 * nb][1] = t[1];
                bl[2 * nb + 1][0] = t[2]; bl[2 * nb + 1][1] = t[3];
            }
#pragma unroll
            for (int mf = 0; mf < 4; mf++)
#pragma unroll
                for (int nf = 0; nf < 4; nf++) {
                    mma16816(acc[mf][nf], ah[mf], bh[nf]);
                    mma16816(acc[mf][nf], ah[mf], bl[nf]);
                    mma16816(acc[mf][nf], al[mf], bh[nf]);
                }
        }
    }

    const int lr = lane >> 2;
    const int lc = (lane & 3) * 2;
#pragma unroll
    for (int mf = 0; mf < 4; mf++)
#pragma unroll
        for (int half = 0; half < 2; half++) {
            int row = row0 + wm0 + mf * 16 + lr + half * 8;
            if (row >= M_NODES) continue;
#pragma unroll
            for (int nf = 0; nf < 4; nf++) {
                int col = wn0 + nf * 8 + lc;
                float v0 = leaky(acc[mf][nf][2 * half]     + __ldg(bias + col));
                float v1 = leaky(acc[mf][nf][2 * half + 1] + __ldg(bias + col + 1));
                *(float2*)(out + (size_t)row * H_DIM + col) = make_float2(v0, v1);
            }
        }
}

// ---------------------------------------------------------------------------
// Merged weight prep
// ---------------------------------------------------------------------------
#define W1_TOT (3 * 128 * 256)
#define W2_TOT (3 * 128 * 128)
#define W3_TOT (128 * 128)

__global__ void convW_all(const float* __restrict__ W1a, const float* __restrict__ W1b,
                          const float* __restrict__ W1c, const float* __restrict__ W2a,
                          const float* __restrict__ W2b, const float* __restrict__ W2c,
                          const float* __restrict__ W3) {
    int i = blockIdx.x * blockDim.x + threadIdx.x;
    if (i < W1_TOT) {
        int r = i / 32768, rem = i % 32768, n = rem >> 8, k = rem & 255;
        const float* W = r == 0 ? W1a : (r == 1 ? W1b : W1c);
        float v = W[k * H_DIM + n];
        __nv_bfloat16 h = __float2bfloat16(v);
        g_Bt1h[i] = h;
        g_Bt1l[i] = __float2bfloat16(v - __bfloat162float(h));
        return;
    }
    i -= W1_TOT;
    if (i < W2_TOT) {
        int r = i >> 14, rem = i & 16383, n = rem >> 7, k = rem & 127;
        const float* W = r == 0 ? W2a : (r == 1 ? W2b : W2c);
        float v = W[k * H_DIM + n];
        __nv_bfloat16 h = __float2bfloat16(v);
        g_Bt2h[i] = h;
        g_Bt2l[i] = __float2bfloat16(v - __bfloat162float(h));
        return;
    }
    i -= W2_TOT;
    if (i < W3_TOT) {
        int n = i >> 7, k = i & 127;
        float w0 = W3[(0 * 128 + k) * 128 + n];
        float w1 = W3[(1 * 128 + k) * 128 + n];
        float w2 = W3[(2 * 128 + k) * 128 + n];
        float e[3];
        e[0] = 3.0f * w0;
        e[1] = -3.0f * w0 + 3.0f * w1;
        e[2] = 0.75f * w0 - 1.5f * w1 + 0.75f * w2;
#pragma unroll
        for (int s = 0; s < 3; s++) {
            __nv_bfloat16 h = __float2bfloat16(e[s]);
            g_Bt3h[s * 128 * 128 + n * 128 + k] = h;
            g_Bt3l[s * 128 * 128 + n * 128 + k] = __float2bfloat16(e[s] - __bfloat162float(h));
        }
    }
}

// ---------------------------------------------------------------------------
// Graph preprocessing
// ---------------------------------------------------------------------------
__global__ void zero_cnt_kernel() {
    int i = blockIdx.x * blockDim.x + threadIdx.x;
    if (i < 3 * M_NODES) g_cnt[i] = 0;
}
__global__ void deg3_kernel(const int* __restrict__ d0, const int* __restrict__ d1,
                            const int* __restrict__ d2) {
    int t = blockIdx.x * blockDim.x + threadIdx.x;
    if (t >= 3 * N_EDGES) return;
    int r = t / N_EDGES, e = t - r * N_EDGES;
    const int* d = r == 0 ? d0 : (r == 1 ? d1 : d2);
    atomicAdd(&g_cnt[r * M_NODES + __ldg(d + e)], 1);
}

// ---- Three-phase scan: fully parallel across 13x3 blocks ----
__global__ void scanA_kernel() {
    __shared__ int wsum[8];
    const int r = blockIdx.y, b = blockIdx.x;
    const int tid = threadIdx.x;
    const int base = b * SCAN_TILE + tid * 16;

    int s = 0;
#pragma unroll
    for (int k = 0; k < 16; k++) {
        int i = base + k;
        if (i < M_NODES) {
            int v = g_cnt[r * M_NODES + i];
            g_dinv3[r * M_NODES + i] = rsqrtf(fmaxf((float)v, 1.0f));
            s += v;
        }
    }
#pragma unroll
    for (int o = 16; o > 0; o >>= 1) s += __shfl_down_sync(0xFFFFFFFFu, s, o);
    if ((tid & 31) == 0) wsum[tid >> 5] = s;
    __syncthreads();
    if (tid == 0) {
        int t = 0;
#pragma unroll
        for (int w = 0; w < 8; w++) t += wsum[w];
        g_blk[r * SCAN_NBLK + b] = t;
    }
}

__global__ void scanB_kernel() {
    int r = threadIdx.x;
    if (r >= 3) return;
    int run = 0;
#pragma unroll
    for (int b = 0; b < SCAN_NBLK; b++) {
        int t = g_blk[r * SCAN_NBLK + b];
        g_blk[r * SCAN_NBLK + b] = run;
        run += t;
    }
}

__global__ void scanC_kernel() {
    __shared__ int warp_sums[8];
    const int r = blockIdx.y, b = blockIdx.x;
    const int tid = threadIdx.x;
    const int lane = tid & 31;
    const int wid = tid >> 5;
    const int base = b * SCAN_TILE + tid * 16;

    int v[16];
    int tsum = 0;
#pragma unroll
    for (int k = 0; k < 16; k++) {
        int i = base + k;
        v[k] = (i < M_NODES) ? g_cnt[r * M_NODES + i] : 0;
        tsum += v[k];
    }
    int x = tsum;
#pragma unroll
    for (int o = 1; o < 32; o <<= 1) {
        int y = __shfl_up_sync(0xFFFFFFFFu, x, o);
        if (lane >= o) x += y;
    }
    if (lane == 31) warp_sums[wid] = x;
    __syncthreads();
    if (wid == 0 && lane < 8) {
        int w = warp_sums[lane];
#pragma unroll
        for (int o = 1; o < 8; o <<= 1) {
            int y = __shfl_up_sync(0xFFu, w, o);
            if (lane >= o) w += y;
        }
        warp_sums[lane] = w;
    }
    __syncthreads();
    int woff = (wid > 0) ? warp_sums[wid - 1] : 0;
    int run = g_blk[r * SCAN_NBLK + b] + woff + x - tsum;
#pragma unroll
    for (int k = 0; k < 16; k++) {
        int i = base + k;
        if (i < M_NODES) g_cur[r * M_NODES + i] = run;
        run += v[k];
    }
}

__global__ void fill_kernel(const int* __restrict__ s0, const int* __restrict__ s1,
                            const int* __restrict__ s2, const int* __restrict__ d0,
                            const int* __restrict__ d1, const int* __restrict__ d2) {
    int t = blockIdx.x * blockDim.x + threadIdx.x;
    if (t >= 3 * N_EDGES) return;
    int r = t / N_EDGES, e = t - r * N_EDGES;
    const int* sp = r == 0 ? s0 : (r == 1 ? s1 : s2);
    const int* dp = r == 0 ? d0 : (r == 1 ? d1 : d2);
    int s = __ldg(sp + e);
    int d = __ldg(dp + e);
    int p = atomicAdd(&g_cur[r * M_NODES + d], 1);
    g_sorted[(size_t)r * N_EDGES + p] = s;
}

// ---------------------------------------------------------------------------
// Fused segmented-sum + combine: one warp per (rel, node), fp32
// After fill, g_cur[rn] == segment END (start + cnt).
// ---------------------------------------------------------------------------
template <int STEP>
__global__ void __launch_bounds__(256) segsum_kernel() {
    int t = blockIdx.x * blockDim.x + threadIdx.x;
    int w = t >> 5;
    if (w >= 3 * M_NODES) return;
    const int lane = t & 31;
    const int r = w / M_NODES, n = w - r * M_NODES;
    const int rn = r * M_NODES + n;
    const int end = __ldg(&g_cur[rn]);
    const int cnt = __ldg(&g_cnt[rn]);
    int j = end - cnt;
    const int* ss = g_sorted + (size_t)r * N_EDGES;
    const float* f = g_T + (size_t)(r * 3 + STEP - 1) * MH;
    const float* dv = g_dinv3 + r * M_NODES;

    float4 a0 = make_float4(0.f, 0.f, 0.f, 0.f);
    float4 a1 = make_float4(0.f, 0.f, 0.f, 0.f);
    for (; j + 2 <= end; j += 2) {
        int s0 = __ldg(ss + j);
        int s1 = __ldg(ss + j + 1);
        float e0 = __ldg(dv + s0);
        float e1 = __ldg(dv + s1);
        float4 v0 = *(const float4*)(f + (size_t)s0 * H_DIM + lane * 4);
        float4 v1 = *(const float4*)(f + (size_t)s1 * H_DIM + lane * 4);
        a0.x += v0.x * e0; a0.y += v0.y * e0; a0.z += v0.z * e0; a0.w += v0.w * e0;
        a1.x += v1.x * e1; a1.y += v1.y * e1; a1.z += v1.z * e1; a1.w += v1.w * e1;
    }
    if (j < end) {
        int s0 = __ldg(ss + j);
        float e0 = __ldg(dv + s0);
        float4 v0 = *(const float4*)(f + (size_t)s0 * H_DIM + lane * 4);
        a0.x += v0.x * e0; a0.y += v0.y * e0; a0.z += v0.z * e0; a0.w += v0.w * e0;
    }
    float dn = __ldg(dv + n);
    float4 t0 = *(const float4*)(f + (size_t)n * H_DIM + lane * 4);
    float4 o;
    o.x = t0.x - (a0.x + a1.x) * dn;
    o.y = t0.y - (a0.y + a1.y) * dn;
    o.z = t0.z - (a0.z + a1.z) * dn;
    o.w = t0.w - (a0.w + a1.w) * dn;
    *(float4*)(g_T + (size_t)(r * 3 + STEP) * MH + (size_t)n * H_DIM + lane * 4) = o;
}

// ---------------------------------------------------------------------------
// Launch — fork/join so the graph-prep chain overlaps the MLP GEMMs
// ---------------------------------------------------------------------------
extern "C" void kernel_launch(void* const* d_in, const int* in_sizes, int n_in,
                              void* d_out, int out_size) {
    const float* x = (const float*)d_in[0];
    const int *src[3], *dst[3];
    const float *W1[3], *b1[3], *W2[3], *b2[3];
    const float *W3, *b3;

    if (in_sizes[3] == N_EDGES) {
        for (int r = 0; r < 3; r++) {
            src[r] = (const int*)d_in[1 + 2 * r];
            dst[r] = (const int*)d_in[2 + 2 * r];
        }
        for (int r = 0; r < 3; r++) {
            W1[r] = (const float*)d_in[7 + 4 * r];
            b1[r] = (const float*)d_in[8 + 4 * r];
            W2[r] = (const float*)d_in[9 + 4 * r];
            b2[r] = (const float*)d_in[10 + 4 * r];
        }
        W3 = (const float*)d_in[19];
        b3 = (const float*)d_in[20];
    } else {
        for (int r = 0; r < 3; r++) {
            src[r] = (const int*)d_in[1 + 6 * r];
            dst[r] = (const int*)d_in[2 + 6 * r];
            W1[r]  = (const float*)d_in[3 + 6 * r];
            b1[r]  = (const float*)d_in[4 + 6 * r];
            W2[r]  = (const float*)d_in[5 + 6 * r];
            b2[r]  = (const float*)d_in[6 + 6 * r];
        }
        W3 = (const float*)d_in[19];
        b3 = (const float*)d_in[20];
    }

    cudaFuncSetAttribute(fused12_kernel, cudaFuncAttributeMaxDynamicSharedMemorySize,
                         SMEM_F12_BYTES);

    const int GEMM_X = (M_NODES + 127) / 128;                    // 391
    const int E3     = (3 * N_EDGES + 255) / 256;
    const int NV3    = (3 * M_NODES + 255) / 256;
    const int SEG3   = (int)(((size_t)3 * M_NODES * 32 + 255) / 256);
    const int CW     = (W1_TOT + W2_TOT + W3_TOT + 255) / 256;

    // Fork a side stream off the capture stream for the graph-prep chain.
    cudaStream_t sSide;
    cudaEvent_t evFork, evJoin;
    cudaStreamCreateWithFlags(&sSide, cudaStreamNonBlocking);
    cudaEventCreateWithFlags(&evFork, cudaEventDisableTiming);
    cudaEventCreateWithFlags(&evJoin, cudaEventDisableTiming);

    cudaEventRecord(evFork, 0);
    cudaStreamWaitEvent(sSide, evFork, 0);

    // Side chain: graph preprocessing (independent of MLP)
    zero_cnt_kernel<<<NV3, 256, 0, sSide>>>();
    deg3_kernel<<<E3, 256, 0, sSide>>>(dst[0], dst[1], dst[2]);
    {
        dim3 sg(SCAN_NBLK, 3);
        scanA_kernel<<<sg, 256, 0, sSide>>>();
        scanB_kernel<<<1, 32, 0, sSide>>>();
        scanC_kernel<<<sg, 256, 0, sSide>>>();
    }
    fill_kernel<<<E3, 256, 0, sSide>>>(src[0], src[1], src[2], dst[0], dst[1], dst[2]);
    cudaEventRecord(evJoin, sSide);

    // Main chain: weight conversion + fused 2-layer MLP (relation-batched)
    convW_all<<<CW, 256>>>(W1[0], W1[1], W1[2], W2[0], W2[1], W2[2], W3);
    {
        dim3 g(GEMM_X, 3);
        fused12_kernel<<<g, 256, SMEM_F12_BYTES>>>(x, b1[0], b1[1], b1[2], b2[0], b2[1], b2[2]);
    }

    // Join: propagation needs both chains complete
    cudaStreamWaitEvent(0, evJoin, 0);

    segsum_kernel<1><<<SEG3, 256>>>();
    segsum_kernel<2><<<SEG3, 256>>>();

    // Output projection
    mma_gemm3<<<GEMM_X, 256>>>(b3, (float*)d_out);
}